// round 13
// baseline (speedup 1.0000x reference)
#include <cuda_runtime.h>
#include <cuda_bf16.h>
#include <math.h>
#include <stdint.h>

// Problem constants
constexpr int kB  = 8;
constexpr int kS  = 384;
constexpr int kD  = 768;
constexpr int kE  = 768;
constexpr int kH  = 12;
constexpr int kHD = 64;
constexpr int kR  = 2 * kS - 1;   // 767 distinct relative positions actually used
constexpr int kK3 = 3 * kD;       // 2304: bf16-split concatenated K
constexpr int kKS = 192;          // 3*64: split head-dim for logits MMA

// ---------------------------------------------------------------------------
// Scratch (device globals; no runtime allocation allowed)
// ---------------------------------------------------------------------------
__device__ float g_v[kB * kH * kS * kHD];               // [B,H,S,HD] fp32
__device__ float g_logits[(size_t)kB * kH * kS * kS];   // [B,H,S,S]

// bf16-split operand buffers for projections (duplicated-hi layout)
__device__ unsigned short g_ab[3072 * kK3];      // A-split: x, then AV output
__device__ unsigned short g_wqkv[2304 * kK3];    // [Wq|Wk|Wv] split
__device__ unsigned short g_apos[768 * kK3];     // rel rows split (padded to 768)
__device__ unsigned short g_wpos[1536 * kK3];    // [Wpk|Wpq] split; reused for Wo

// bf16-split logits operands (written by tgemm epilogues)
__device__ unsigned short g_qs[96 * kS * kKS];   // [bh][s][192] pattern A (hi,hi,lo)
__device__ unsigned short g_ks[96 * kS * kKS];   // [bh][s][192] pattern B (hi,lo,hi)
__device__ unsigned short g_pks[kH * 768 * kKS]; // [h][r][192]  pattern B
__device__ unsigned short g_pqs[kH * 768 * kKS]; // [h][r][192]  pattern A

// attention probabilities, hi/lo bf16 split: [bh][i][384] each
__device__ unsigned short g_ps [(size_t)96 * kS * kS];
__device__ unsigned short g_psl[(size_t)96 * kS * kS];
// transposed split V for tensor AV: [bh][jt][d][192] pattern B (hi|lo|hi)
__device__ unsigned short g_vt[96 * 6 * 64 * 192];

// ---------------------------------------------------------------------------
// PTX helpers (target-independent: cp.async, ldmatrix, mma.sync — sm_80+)
// ---------------------------------------------------------------------------
__device__ __forceinline__ uint32_t smem_to_u32(const void* p) {
    uint32_t a;
    asm("{ .reg .u64 t; cvta.to.shared.u64 t, %1; cvt.u32.u64 %0, t; }"
        : "=r"(a) : "l"(p));
    return a;
}

__device__ __forceinline__ void cp_async16(uint32_t saddr, const void* gptr) {
    asm volatile("cp.async.cg.shared.global [%0], [%1], 16;\n"
                 :: "r"(saddr), "l"(gptr));
}
#define CP_COMMIT()  asm volatile("cp.async.commit_group;\n" ::: "memory")
#define CP_WAIT(n)   asm volatile("cp.async.wait_group %0;\n" :: "n"(n) : "memory")

__device__ __forceinline__ void ldmatrix_x4(uint32_t* r, uint32_t addr) {
    asm volatile("ldmatrix.sync.aligned.m8n8.x4.shared.b16 {%0,%1,%2,%3}, [%4];"
                 : "=r"(r[0]), "=r"(r[1]), "=r"(r[2]), "=r"(r[3]) : "r"(addr));
}
__device__ __forceinline__ void ldmatrix_x2(uint32_t* r, uint32_t addr) {
    asm volatile("ldmatrix.sync.aligned.m8n8.x2.shared.b16 {%0,%1}, [%2];"
                 : "=r"(r[0]), "=r"(r[1]) : "r"(addr));
}

__device__ __forceinline__ void mma_bf16(float* d, const uint32_t* a, const uint32_t* b) {
    asm volatile(
        "mma.sync.aligned.m16n8k16.row.col.f32.bf16.bf16.f32 "
        "{%0,%1,%2,%3}, {%4,%5,%6,%7}, {%8,%9}, {%0,%1,%2,%3};"
        : "+f"(d[0]), "+f"(d[1]), "+f"(d[2]), "+f"(d[3])
        : "r"(a[0]), "r"(a[1]), "r"(a[2]), "r"(a[3]),
          "r"(b[0]), "r"(b[1]));
}

// ---------------------------------------------------------------------------
// fp32 -> bf16 hi/lo split conversion kernels (duplicated-hi layouts)
// A pattern:  out[m, 0:K]=hi, [K:2K]=hi, [2K:3K]=lo
// W pattern:  out[n, 0:K]=hi, [K:2K]=lo, [2K:3K]=hi
// ---------------------------------------------------------------------------
union BF4 { __nv_bfloat16 h[4]; uint2 u; };

__device__ __forceinline__ void split4(float4 a, uint2& hi, uint2& lo)
{
    float v[4] = {a.x, a.y, a.z, a.w};
    BF4 H, L;
#pragma unroll
    for (int i = 0; i < 4; i++) {
        __nv_bfloat16 h1 = __float2bfloat16_rn(v[i]);
        float res = v[i] - __bfloat162float(h1);
        H.h[i] = h1;
        L.h[i] = __float2bfloat16_rn(res);
    }
    hi = H.u; lo = L.u;
}

__device__ __forceinline__ void split2_pack(float v0, float v1,
                                            uint32_t& hp, uint32_t& lp)
{
    __nv_bfloat16 h0 = __float2bfloat16_rn(v0), h1 = __float2bfloat16_rn(v1);
    float r0 = v0 - __bfloat162float(h0), r1 = v1 - __bfloat162float(h1);
    __nv_bfloat16 l0 = __float2bfloat16_rn(r0), l1 = __float2bfloat16_rn(r1);
    hp = (uint32_t)*(unsigned short*)&h0 | ((uint32_t)*(unsigned short*)&h1 << 16);
    lp = (uint32_t)*(unsigned short*)&l0 | ((uint32_t)*(unsigned short*)&l1 << 16);
}

__global__ __launch_bounds__(256) void split_a_kernel(
    const float* __restrict__ A, unsigned short* __restrict__ out,
    int Msrc, int Mpad, int K)
{
    int idx = blockIdx.x * 256 + threadIdx.x;
    int kq = K >> 2;
    if (idx >= Mpad * kq) return;
    int m = idx / kq;
    int c4 = (idx - m * kq) << 2;
    float4 a = (m < Msrc) ? *(const float4*)(A + (size_t)m * K + c4)
                          : make_float4(0.f, 0.f, 0.f, 0.f);
    uint2 hi, lo; split4(a, hi, lo);
    size_t base = (size_t)m * 3 * K + c4;
    *(uint2*)(out + base)         = hi;
    *(uint2*)(out + base + K)     = hi;
    *(uint2*)(out + base + 2 * K) = lo;
}

__global__ __launch_bounds__(256) void split_w_kernel(
    const float* __restrict__ W0, const float* __restrict__ W1,
    const float* __restrict__ W2, unsigned short* __restrict__ out,
    int nsrc, int K)
{
    int idx = blockIdx.x * 256 + threadIdx.x;
    int kq = K >> 2;
    int rows = nsrc * 768;
    if (idx >= rows * kq) return;
    int rr = idx / kq;
    int c4 = (idx - rr * kq) << 2;
    int s = rr / 768, r = rr - s * 768;
    const float* W = (s == 0) ? W0 : (s == 1) ? W1 : W2;
    float4 a = *(const float4*)(W + (size_t)r * K + c4);
    uint2 hi, lo; split4(a, hi, lo);
    size_t base = (size_t)rr * 3 * K + c4;
    *(uint2*)(out + base)         = hi;
    *(uint2*)(out + base + K)     = lo;
    *(uint2*)(out + base + 2 * K) = hi;
}

// ---------------------------------------------------------------------------
// bf16 HMMA GEMM body (projections). 128x256 CTA tile, BK=64, 256 threads,
// 8 warps (2 M x 4 N), warp tile 64x64 — per k16 step 8 LDSM.x4 feed 32 MMAs.
// mode 0: QKV   n<768 -> q split(A-pat), n<1536 -> k split(B-pat), else v fp32
// mode 1: POS   n<768 -> pk split(B-pat), else pq split(A-pat)
// mode 2: plain fp32 C[m*768+n]
// ---------------------------------------------------------------------------
constexpr int BK   = 64;
constexpr int LDT  = 72;                       // smem stride in halves (pad 8)
constexpr int ABUF = 128 * LDT * 2;            // 18432 B (A tile)
constexpr int BBUF = 256 * LDT * 2;            // 36864 B (B tile)
constexpr int STAGE = ABUF + BBUF;             // 55296 B per stage
constexpr int TGEMM_SMEM = 2 * STAGE;          // 110592 B

__device__ __forceinline__ void store_split_pair(
    unsigned short* base, float v0, float v1, bool patA)
{
    uint32_t hp, lp;
    split2_pack(v0, v1, hp, lp);
    *(uint32_t*)(base)       = hp;
    *(uint32_t*)(base + 64)  = patA ? hp : lp;
    *(uint32_t*)(base + 128) = patA ? lp : hp;
}

__device__ __forceinline__ void store_pair(
    int mode, int Msrc, int mrow, int n, float v0, float v1,
    const float* __restrict__ b0, const float* __restrict__ b1,
    const float* __restrict__ b2,
    float* __restrict__ o0,
    unsigned short* __restrict__ s0, unsigned short* __restrict__ s1)
{
    if (mrow >= Msrc) return;
    if (mode == 2) {
        float2 w = make_float2(v0 + b0[n], v1 + b0[n + 1]);
        *(float2*)&o0[(size_t)mrow * 768 + n] = w;
        return;
    }
    int which = n / 768;
    int e = n - which * 768;
    int h = e >> 6, hd = e & 63;
    const float* bp = (which == 0) ? b0 : (which == 1) ? b1 : b2;
    float w0 = v0 + bp[e], w1 = v1 + bp[e + 1];
    if (mode == 0) {
        int bi = mrow / kS, s = mrow - bi * kS;
        if (which == 2) {
            *(float2*)&o0[((((size_t)bi * kH) + h) * kS + s) * (size_t)kHD + hd]
                = make_float2(w0, w1);
        } else {
            unsigned short* base = ((which == 0) ? s0 : s1)
                + (((size_t)(bi * kH + h) * kS) + s) * kKS + hd;
            store_split_pair(base, w0, w1, which == 0);  // q: A-pat, k: B-pat
        }
    } else {  // mode 1: pk (B-pat), pq (A-pat)
        unsigned short* base = ((which == 0) ? s0 : s1)
            + (((size_t)h * 768) + mrow) * kKS + hd;
        store_split_pair(base, w0, w1, which == 1);
    }
}

__device__ __forceinline__ void tgemm_body(
    const __nv_bfloat16* __restrict__ A, const __nv_bfloat16* __restrict__ B,
    int Msrc,
    const float* __restrict__ bias0, const float* __restrict__ bias1,
    const float* __restrict__ bias2,
    float* __restrict__ out0,
    unsigned short* __restrict__ s0, unsigned short* __restrict__ s1,
    int mode, int m0, int n0, char* smem)
{
    const uint32_t sbase = smem_to_u32(smem);

    const int t = threadIdx.x, lane = t & 31, wid = t >> 5;
    const int warp_m = wid & 1, warp_n = wid >> 1;   // 2 x 4, warp tile 64x64

    const __nv_bfloat16* Ag = A + (size_t)m0 * kK3;
    const __nv_bfloat16* Bg = B + (size_t)n0 * kK3;
    const int NC = kK3 / BK;

    auto issue = [&](int c) {
        const int buf = c & 1;
        const uint32_t dA = sbase + buf * STAGE;
        const uint32_t dB = dA + ABUF;
        const __nv_bfloat16* Ak = Ag + (size_t)c * BK;
        const __nv_bfloat16* Bk = Bg + (size_t)c * BK;
#pragma unroll
        for (int it = 0; it < 4; it++) {          // A: 128 rows x 8 chunks
            int idx = it * 256 + t;
            int r = idx >> 3, c8 = (idx & 7) * 8;
            cp_async16(dA + (uint32_t)(r * LDT + c8) * 2,
                       Ak + (size_t)r * kK3 + c8);
        }
#pragma unroll
        for (int it = 0; it < 8; it++) {          // B: 256 rows x 8 chunks
            int idx = it * 256 + t;
            int r = idx >> 3, c8 = (idx & 7) * 8;
            cp_async16(dB + (uint32_t)(r * LDT + c8) * 2,
                       Bk + (size_t)r * kK3 + c8);
        }
        CP_COMMIT();
    };

    float d[4][8][4];
#pragma unroll
    for (int i = 0; i < 4; i++)
#pragma unroll
        for (int j = 0; j < 8; j++)
#pragma unroll
            for (int e = 0; e < 4; e++) d[i][j][e] = 0.f;

    // A ldmatrix.x4 lane address: rows lane&15, k-half (lane>>4)*8
    const int a_row = warp_m * 64 + (lane & 15);
    const int a_col = (lane >> 4) * 8;
    // B ldmatrix.x4 lane address: j-frag pair — lanes 0-15 j, 16-31 j+1;
    // within each, lanes 0-7 k-lo, 8-15 k-hi.
    const int b_row = warp_n * 64 + (lane & 7) + ((lane >> 4) & 1) * 8;
    const int b_col = ((lane >> 3) & 1) * 8;

    issue(0);

    for (int c = 0; c < NC; c++) {
        if (c + 1 < NC) { issue(c + 1); CP_WAIT(1); }
        else           { CP_WAIT(0); }
        __syncthreads();

        const int buf = c & 1;
        const uint32_t sA = sbase + buf * STAGE;
        const uint32_t sB = sA + ABUF;

#pragma unroll
        for (int ks = 0; ks < BK; ks += 16) {
            uint32_t a[4][4], bb[4][4];
#pragma unroll
            for (int i = 0; i < 4; i++)
                ldmatrix_x4(a[i], sA + (uint32_t)((a_row + i * 16) * LDT + a_col + ks) * 2);
#pragma unroll
            for (int jp = 0; jp < 4; jp++)
                ldmatrix_x4(bb[jp], sB + (uint32_t)((b_row + jp * 16) * LDT + b_col + ks) * 2);
#pragma unroll
            for (int i = 0; i < 4; i++)
#pragma unroll
                for (int jp = 0; jp < 4; jp++) {
                    mma_bf16(d[i][2 * jp],     a[i], &bb[jp][0]);
                    mma_bf16(d[i][2 * jp + 1], a[i], &bb[jp][2]);
                }
        }
        __syncthreads();
    }

    const int mbase = m0 + warp_m * 64 + (lane >> 2);
    const int nbase = n0 + warp_n * 64 + (lane & 3) * 2;
#pragma unroll
    for (int i = 0; i < 4; i++) {
#pragma unroll
        for (int j = 0; j < 8; j++) {
            int mm = mbase + i * 16;
            int nn = nbase + j * 8;
            store_pair(mode, Msrc, mm,     nn, d[i][j][0], d[i][j][1],
                       bias0, bias1, bias2, out0, s0, s1);
            store_pair(mode, Msrc, mm + 8, nn, d[i][j][2], d[i][j][3],
                       bias0, bias1, bias2, out0, s0, s1);
        }
    }
}

// Plain entry (used for the output projection, mode 2)
__global__ __launch_bounds__(256) void tgemm_kernel(
    const __nv_bfloat16* __restrict__ A, const __nv_bfloat16* __restrict__ B,
    int Msrc,
    const float* __restrict__ bias0,
    float* __restrict__ out0)
{
    extern __shared__ __align__(16) char smem[];
    tgemm_body(A, B, Msrc, bias0, nullptr, nullptr, out0, nullptr, nullptr,
               2, blockIdx.y * 128, blockIdx.x * 256, smem);
}

// Merged QKV + POS entry: flat grid of 216 + 36 = 252 blocks.
__global__ __launch_bounds__(256) void tgemm_dual_kernel(
    const __nv_bfloat16* __restrict__ Aq, const __nv_bfloat16* __restrict__ Bq,
    const float* __restrict__ bq, const float* __restrict__ bk,
    const float* __restrict__ bv,
    float* __restrict__ v_out,
    unsigned short* __restrict__ qs, unsigned short* __restrict__ ks,
    const __nv_bfloat16* __restrict__ Ap, const __nv_bfloat16* __restrict__ Bp,
    const float* __restrict__ bpk, const float* __restrict__ bpq,
    unsigned short* __restrict__ pks, unsigned short* __restrict__ pqs)
{
    extern __shared__ __align__(16) char smem[];
    const int bx = blockIdx.x;
    if (bx < 216) {                                   // QKV: 24 m x 9 n
        int m0 = (bx / 9) * 128, n0 = (bx % 9) * 256;
        tgemm_body(Aq, Bq, 3072, bq, bk, bv, v_out, qs, ks, 0, m0, n0, smem);
    } else {                                          // POS: 6 m x 6 n
        int i = bx - 216;
        int m0 = (i / 6) * 128, n0 = (i % 6) * 256;
        tgemm_body(Ap, Bp, kR, bpk, bpq, nullptr, nullptr, pks, pqs, 1, m0, n0, smem);
    }
}

// ---------------------------------------------------------------------------
// V transpose + split: g_v [bh][s][64] fp32 -> g_vt [bh][jt][d][192] (hi|lo|hi)
// ---------------------------------------------------------------------------
__global__ __launch_bounds__(256) void vtrans_kernel(
    const float* __restrict__ v, unsigned short* __restrict__ vt)
{
    __shared__ float tile[64][65];
    const int bh = blockIdx.y, jt = blockIdx.x;
    const int t = threadIdx.x;
    const float* src = v + ((size_t)bh * kS + jt * 64) * kHD;

#pragma unroll
    for (int i = 0; i < 16; i++) {
        int idx = i * 256 + t;
        tile[idx >> 6][idx & 63] = src[idx];
    }
    __syncthreads();

    unsigned short* dst = vt + (((size_t)bh * 6 + jt) * 64) * 192;
#pragma unroll
    for (int i = 0; i < 8; i++) {
        int idx = i * 256 + t;            // 0..2047
        int dd  = idx >> 5;               // d row
        int jp  = (idx & 31) * 2;         // j pair
        uint32_t hp, lp;
        split2_pack(tile[jp][dd], tile[jp + 1][dd], hp, lp);
        unsigned short* base = dst + (size_t)dd * 192 + jp;
        *(uint32_t*)(base)       = hp;    // pattern B: hi, lo, hi
        *(uint32_t*)(base + 64)  = lp;
        *(uint32_t*)(base + 128) = hp;
    }
}

// ---------------------------------------------------------------------------
// Fused banded-MMA logits kernel (round-6/10 winner, unchanged).
// ---------------------------------------------------------------------------
constexpr int LDS = 200;  // smem stride in halves for all operand tiles
constexpr int LOGMMA_SMEM = (2 * 64 * LDS + 2 * 128 * LDS) * 2;  // 153600 B
constexpr int QW_STRIDE = 132;

__global__ __launch_bounds__(256) void logits_mma_kernel(
    const unsigned short* __restrict__ qs, const unsigned short* __restrict__ ks,
    const unsigned short* __restrict__ pks, const unsigned short* __restrict__ pqs,
    const int* __restrict__ mask, const int* __restrict__ seg,
    const float* __restrict__ sep,
    const float* __restrict__ same_bias, const float* __restrict__ cross_bias,
    const float* __restrict__ sep_scale, const float* __restrict__ sep_decay,
    float* __restrict__ logits)
{
    extern __shared__ __align__(16) char smem[];
    const uint32_t sb = smem_to_u32(smem);

    __shared__ int   s_segi[64], s_segj[64], s_maskj[64];
    __shared__ float s_sepi[64], s_sepj[64];

    const int t = threadIdx.x, lane = t & 31, wid = t >> 5;
    const int wm = wid >> 2, wn = wid & 3;          // 2 x 4 warps
    const int bh = blockIdx.z, b = bh / kH, h = bh % kH;
    const int i0 = blockIdx.y * 64, j0 = blockIdx.x * 64;
    const int rb = i0 - j0 + 320;                   // window base: r = rb + u

    const uint32_t sQ  = sb;
    const uint32_t sK  = sQ + 64 * LDS * 2;
    const uint32_t sPK = sK + 64 * LDS * 2;
    const uint32_t sPQ = sPK + 128 * LDS * 2;

    if (t < 64) {
        s_segi[t] = seg[b * kS + i0 + t];
        s_sepi[t] = fabsf(sep[b * kS + i0 + t]);
    } else if (t < 128) {
        int u = t - 64;
        s_segj[u]  = seg[b * kS + j0 + u];
        s_sepj[u]  = fabsf(sep[b * kS + j0 + u]);
        s_maskj[u] = mask[b * kS + j0 + u];
    }

    {
        const unsigned short* gq  = qs  + ((size_t)bh * kS + i0) * kKS;
        const unsigned short* gk  = ks  + ((size_t)bh * kS + j0) * kKS;
        const unsigned short* gpk = pks + ((size_t)h * 768 + rb) * kKS;
        const unsigned short* gpq = pqs + ((size_t)h * 768 + rb) * kKS;
        const int r0 = t >> 3;
        const int c0 = (t & 7);
#pragma unroll
        for (int rh = 0; rh < 2; rh++) {
#pragma unroll
            for (int cc = 0; cc < 3; cc++) {
                int row = r0 + rh * 32, ch = c0 + cc * 8;
                uint32_t so = (uint32_t)(row * LDS + ch * 8) * 2;
                cp_async16(sQ + so, gq + (size_t)row * kKS + ch * 8);
                cp_async16(sK + so, gk + (size_t)row * kKS + ch * 8);
            }
        }
#pragma unroll
        for (int rh = 0; rh < 4; rh++) {
#pragma unroll
            for (int cc = 0; cc < 3; cc++) {
                int row = r0 + rh * 32, ch = c0 + cc * 8;
                uint32_t so = (uint32_t)(row * LDS + ch * 8) * 2;
                cp_async16(sPK + so, gpk + (size_t)row * kKS + ch * 8);
                cp_async16(sPQ + so, gpq + (size_t)row * kKS + ch * 8);
            }
        }
        CP_COMMIT();
        CP_WAIT(0);
    }
    __syncthreads();

    float c2c[2][2][4], qw[2][4][4], kw[2][4][4];
#pragma unroll
    for (int i = 0; i < 2; i++) {
#pragma unroll
        for (int j = 0; j < 2; j++)
#pragma unroll
            for (int e = 0; e < 4; e++) c2c[i][j][e] = 0.f;
#pragma unroll
        for (int j = 0; j < 4; j++)
#pragma unroll
            for (int e = 0; e < 4; e++) { qw[i][j][e] = 0.f; kw[i][j][e] = 0.f; }
    }

    const int aRow = (lane & 15);
    const int aCol = (lane >> 4) * 8;
    const int bRow = (lane & 7);
    const int bCol = ((lane >> 3) & 1) * 8;

#pragma unroll
    for (int ksp = 0; ksp < kKS; ksp += 16) {
        uint32_t aQ[2][4], aK[2][4];
#pragma unroll
        for (int fi = 0; fi < 2; fi++) {
            int r = wm * 32 + fi * 16 + aRow;
            ldmatrix_x4(aQ[fi], sQ + (uint32_t)(r * LDS + aCol + ksp) * 2);
            ldmatrix_x4(aK[fi], sK + (uint32_t)(r * LDS + aCol + ksp) * 2);
        }
        uint32_t bC[2][2];
#pragma unroll
        for (int fj = 0; fj < 2; fj++) {
            int r = wn * 16 + fj * 8 + bRow;
            ldmatrix_x2(bC[fj], sK + (uint32_t)(r * LDS + bCol + ksp) * 2);
        }
        uint32_t bPK[4][2], bPQ[4][2];
#pragma unroll
        for (int fu = 0; fu < 4; fu++) {
            int r = wn * 32 + fu * 8 + bRow;
            ldmatrix_x2(bPK[fu], sPK + (uint32_t)(r * LDS + bCol + ksp) * 2);
            ldmatrix_x2(bPQ[fu], sPQ + (uint32_t)(r * LDS + bCol + ksp) * 2);
        }
#pragma unroll
        for (int fi = 0; fi < 2; fi++)
#pragma unroll
            for (int fj = 0; fj < 2; fj++)
                mma_bf16(c2c[fi][fj], aQ[fi], bC[fj]);
#pragma unroll
        for (int fi = 0; fi < 2; fi++)
#pragma unroll
            for (int fu = 0; fu < 4; fu++) {
                mma_bf16(qw[fi][fu], aQ[fi], bPK[fu]);
                mma_bf16(kw[fi][fu], aK[fi], bPQ[fu]);
            }
    }

    __syncthreads();
    float* QWs = (float*)smem;                    // [64][132]
    float* KWs = QWs + 64 * QW_STRIDE;            // [64][132]
#pragma unroll
    for (int fi = 0; fi < 2; fi++) {
#pragma unroll
        for (int fu = 0; fu < 4; fu++) {
            int rl = wm * 32 + fi * 16 + (lane >> 2);
            int u  = wn * 32 + fu * 8 + (lane & 3) * 2;
            QWs[rl * QW_STRIDE + u]           = qw[fi][fu][0];
            QWs[rl * QW_STRIDE + u + 1]       = qw[fi][fu][1];
            QWs[(rl + 8) * QW_STRIDE + u]     = qw[fi][fu][2];
            QWs[(rl + 8) * QW_STRIDE + u + 1] = qw[fi][fu][3];
            KWs[rl * QW_STRIDE + u]           = kw[fi][fu][0];
            KWs[rl * QW_STRIDE + u + 1]       = kw[fi][fu][1];
            KWs[(rl + 8) * QW_STRIDE + u]     = kw[fi][fu][2];
            KWs[(rl + 8) * QW_STRIDE + u + 1] = kw[fi][fu][3];
        }
    }
    __syncthreads();

    const float sb_same  = same_bias[h];
    const float sb_cross = cross_bias[h];
    const float scale_h  = sep_scale[h];
    const float dx       = sep_decay[h];
    const float softp    = fmaxf(dx, 0.f) + log1pf(expf(-fabsf(dx)));
    const float decay    = softp + 1e-4f;
    const float inv      = 0.07216878364870322f;  // 1/sqrt(3*HD)

#pragma unroll
    for (int fi = 0; fi < 2; fi++) {
#pragma unroll
        for (int fj = 0; fj < 2; fj++) {
            int il0 = wm * 32 + fi * 16 + (lane >> 2);
            int jl0 = wn * 16 + fj * 8 + (lane & 3) * 2;
#pragma unroll
            for (int half = 0; half < 2; half++) {
                int il = il0 + half * 8;
                float raw0 = c2c[fi][fj][half * 2];
                float raw1 = c2c[fi][fj][half * 2 + 1];
                int   segi = s_segi[il];
                float sepi = s_sepi[il];
#pragma unroll
                for (int e = 0; e < 2; e++) {
                    int jl = jl0 + e;
                    int u  = il - jl + 63;
                    float val = ((e ? raw1 : raw0)
                                 + QWs[il * QW_STRIDE + u]
                                 + KWs[jl * QW_STRIDE + u]) * inv;
                    if (segi == s_segj[jl]) {
                        val += sb_same;
                    } else {
                        float gap = fabsf(sepi - s_sepj[jl]);
                        val += sb_cross + expf(-gap * decay) * scale_h;
                    }
                    if (s_maskj[jl] == 0) val = -9e15f;
                    logits[(((size_t)bh * kS) + i0 + il) * kS + j0 + jl] = val;
                }
            }
        }
    }
}

// ---------------------------------------------------------------------------
// Row softmax over S=384, writing hi/lo bf16 split probabilities.
// ---------------------------------------------------------------------------
__global__ __launch_bounds__(128) void softmax_bf16_kernel(
    const float* __restrict__ logits,
    unsigned short* __restrict__ ps, unsigned short* __restrict__ psl)
{
    const size_t row = blockIdx.x;
    const float* p = logits + row * kS;
    const int t = threadIdx.x;

    float v0 = p[t], v1 = p[t + 128], v2 = p[t + 256];
    float m = fmaxf(v0, fmaxf(v1, v2));

    __shared__ float red[4];
#pragma unroll
    for (int o = 16; o; o >>= 1) m = fmaxf(m, __shfl_xor_sync(0xffffffffu, m, o));
    if ((t & 31) == 0) red[t >> 5] = m;
    __syncthreads();
    m = fmaxf(fmaxf(red[0], red[1]), fmaxf(red[2], red[3]));

    float e0 = __expf(v0 - m), e1 = __expf(v1 - m), e2 = __expf(v2 - m);
    float s = e0 + e1 + e2;
#pragma unroll
    for (int o = 16; o; o >>= 1) s += __shfl_xor_sync(0xffffffffu, s, o);
    __shared__ float red2[4];
    if ((t & 31) == 0) red2[t >> 5] = s;
    __syncthreads();
    s = red2[0] + red2[1] + red2[2] + red2[3];

    float r = 1.f / s;
    float p0 = e0 * r, p1 = e1 * r, p2 = e2 * r;
    unsigned short* oh = ps  + row * kS;
    unsigned short* ol = psl + row * kS;
    __nv_bfloat16 h0 = __float2bfloat16_rn(p0);
    __nv_bfloat16 h1 = __float2bfloat16_rn(p1);
    __nv_bfloat16 h2 = __float2bfloat16_rn(p2);
    __nv_bfloat16 l0 = __float2bfloat16_rn(p0 - __bfloat162float(h0));
    __nv_bfloat16 l1 = __float2bfloat16_rn(p1 - __bfloat162float(h1));
    __nv_bfloat16 l2 = __float2bfloat16_rn(p2 - __bfloat162float(h2));
    oh[t]       = *(unsigned short*)&h0;
    oh[t + 128] = *(unsigned short*)&h1;
    oh[t + 256] = *(unsigned short*)&h2;
    ol[t]       = *(unsigned short*)&l0;
    ol[t + 128] = *(unsigned short*)&l1;
    ol[t + 256] = *(unsigned short*)&l2;
}

// ---------------------------------------------------------------------------
// Tensor AV: O[b,i,h*64+d] = sum_j P[bh,i,j] * V[bh,j,d]
// 3-term split per 64-j tile (K=192): A = [P_hi|P_hi|P_lo], B = V^T (hi|lo|hi).
// Epilogue writes O directly as the A-pattern bf16 split (hi|hi|lo, 2304-wide)
// consumed by the output-projection tgemm.
// ---------------------------------------------------------------------------
constexpr int LDP  = 392;   // P smem stride in halves (384 + 8)
constexpr int LDV  = 200;   // V smem stride in halves (192 + 8)
constexpr int AV_SMEM = 2 * 64 * LDP * 2 + 2 * 64 * LDV * 2;  // 100352+51200

__global__ __launch_bounds__(256) void av_mma_kernel(
    const unsigned short* __restrict__ ps, const unsigned short* __restrict__ psl,
    const unsigned short* __restrict__ vt,
    unsigned short* __restrict__ osplit)
{
    extern __shared__ __align__(16) char smem[];
    const uint32_t sPh = smem_to_u32(smem);
    const uint32_t sPl = sPh + 64 * LDP * 2;
    const uint32_t sV0 = sPl + 64 * LDP * 2;

    const int t = threadIdx.x, lane = t & 31, wid = t >> 5;
    const int wm = wid >> 2, wn = wid & 3;      // 2 x 4 warps
    const int bh = blockIdx.y, b = bh / kH, h = bh % kH;
    const int i0 = blockIdx.x * 64;

    {
        const unsigned short* gh = ps  + ((size_t)bh * kS + i0) * kS;
        const unsigned short* gl = psl + ((size_t)bh * kS + i0) * kS;
#pragma unroll
        for (int i = 0; i < 12; i++) {
            int idx = i * 256 + t;            // 0..3071
            int row = idx / 48, q = idx % 48;
            uint32_t so = (uint32_t)(row * LDP + q * 8) * 2;
            size_t  go = (size_t)row * kS + q * 8;
            cp_async16(sPh + so, gh + go);
            cp_async16(sPl + so, gl + go);
        }
    }
    auto stageV = [&](int jt) {
        const unsigned short* g = vt + (((size_t)bh * 6 + jt) * 64) * 192;
        const uint32_t dst = sV0 + (jt & 1) * 64 * LDV * 2;
#pragma unroll
        for (int i = 0; i < 6; i++) {
            int idx = i * 256 + t;            // 0..1535
            int row = idx / 24, ch = idx % 24;
            cp_async16(dst + (uint32_t)(row * LDV + ch * 8) * 2,
                       g + (size_t)row * 192 + ch * 8);
        }
    };
    stageV(0);
    CP_COMMIT();   // group 0: P + V0

    float d[2][2][4];
#pragma unroll
    for (int i = 0; i < 2; i++)
#pragma unroll
        for (int j = 0; j < 2; j++)
#pragma unroll
            for (int e = 0; e < 4; e++) d[i][j][e] = 0.f;

    const int aRow = lane & 15, aCol = (lane >> 4) * 8;
    const int bRow = lane & 7,  bCol = ((lane >> 3) & 1) * 8;

    for (int jt = 0; jt < 6; jt++) {
        if (jt + 1 < 6) { stageV(jt + 1); CP_COMMIT(); CP_WAIT(1); }
        else            { CP_WAIT(0); }
        __syncthreads();

        const uint32_t sV = sV0 + (jt & 1) * 64 * LDV * 2;

#pragma unroll
        for (int ksp = 0; ksp < 192; ksp += 16) {
            const uint32_t sPbuf = (ksp < 128) ? sPh : sPl;   // [hi|hi|lo]
            uint32_t a[2][4], bf[2][2];
#pragma unroll
            for (int fi = 0; fi < 2; fi++)
                ldmatrix_x4(a[fi], sPbuf + (uint32_t)((wm * 32 + fi * 16 + aRow) * LDP
                                                      + jt * 64 + (ksp & 63) + aCol) * 2);
#pragma unroll
            for (int fj = 0; fj < 2; fj++)
                ldmatrix_x2(bf[fj], sV + (uint32_t)((wn * 16 + fj * 8 + bRow) * LDV
                                                    + ksp + bCol) * 2);
#pragma unroll
            for (int fi = 0; fi < 2; fi++)
#pragma unroll
                for (int fj = 0; fj < 2; fj++)
                    mma_bf16(d[fi][fj], a[fi], bf[fj]);
        }
        __syncthreads();
    }

    // epilogue: write O as A-pattern split (hi|hi|lo) rows of g_ab
#pragma unroll
    for (int fi = 0; fi < 2; fi++) {
#pragma unroll
        for (int fj = 0; fj < 2; fj++) {
            int mm = i0 + wm * 32 + fi * 16 + (lane >> 2);
            int nn = h * 64 + wn * 16 + fj * 8 + (lane & 3) * 2;
            size_t row0 = (size_t)b * kS + mm;
            unsigned short* base0 = osplit + row0 * kK3 + nn;
            uint32_t hp, lp;
            split2_pack(d[fi][fj][0], d[fi][fj][1], hp, lp);
            *(uint32_t*)(base0)         = hp;
            *(uint32_t*)(base0 + 768)   = hp;
            *(uint32_t*)(base0 + 1536)  = lp;
            unsigned short* base1 = osplit + (row0 + 8) * kK3 + nn;
            split2_pack(d[fi][fj][2], d[fi][fj][3], hp, lp);
            *(uint32_t*)(base1)         = hp;
            *(uint32_t*)(base1 + 768)   = hp;
            *(uint32_t*)(base1 + 1536)  = lp;
        }
    }
}

// ---------------------------------------------------------------------------
// Launch
// ---------------------------------------------------------------------------
extern "C" void kernel_launch(void* const* d_in, const int* in_sizes, int n_in,
                              void* d_out, int out_size)
{
    const float* x    = (const float*)d_in[0];
    const int*   mask = (const int*)d_in[1];
    const int*   seg  = (const int*)d_in[2];
    const float* sep  = (const float*)d_in[3];
    const float* Wq   = (const float*)d_in[4];
    const float* bq   = (const float*)d_in[5];
    const float* Wk   = (const float*)d_in[6];
    const float* bk   = (const float*)d_in[7];
    const float* Wv   = (const float*)d_in[8];
    const float* bv   = (const float*)d_in[9];
    const float* rel  = (const float*)d_in[10];
    const float* Wpk  = (const float*)d_in[11];
    const float* bpk  = (const float*)d_in[12];
    const float* Wpq  = (const float*)d_in[13];
    const float* bpq  = (const float*)d_in[14];
    const float* same_b  = (const float*)d_in[15];
    const float* cross_b = (const float*)d_in[16];
    const float* sscale  = (const float*)d_in[17];
    const float* sdecay  = (const float*)d_in[18];
    const float* Wo   = (const float*)d_in[19];
    const float* bo   = (const float*)d_in[20];
    float* out = (float*)d_out;

    float *v_, *lg_;
    unsigned short *ab_, *wqkv_, *apos_, *wpos_, *qs_, *ks_, *pks_, *pqs_, *vt_, *ps_, *psl_;
    cudaGetSymbolAddress((void**)&v_,  g_v);
    cudaGetSymbolAddress((void**)&lg_, g_logits);
    cudaGetSymbolAddress((void**)&ab_,   g_ab);
    cudaGetSymbolAddress((void**)&wqkv_, g_wqkv);
    cudaGetSymbolAddress((void**)&apos_, g_apos);
    cudaGetSymbolAddress((void**)&wpos_, g_wpos);
    cudaGetSymbolAddress((void**)&qs_,  g_qs);
    cudaGetSymbolAddress((void**)&ks_,  g_ks);
    cudaGetSymbolAddress((void**)&pks_, g_pks);
    cudaGetSymbolAddress((void**)&pqs_, g_pqs);
    cudaGetSymbolAddress((void**)&vt_,  g_vt);
    cudaGetSymbolAddress((void**)&ps_,  g_ps);
    cudaGetSymbolAddress((void**)&psl_, g_psl);

    cudaFuncSetAttribute(tgemm_kernel,
                         cudaFuncAttributeMaxDynamicSharedMemorySize,
                         TGEMM_SMEM);
    cudaFuncSetAttribute(tgemm_dual_kernel,
                         cudaFuncAttributeMaxDynamicSharedMemorySize,
                         TGEMM_SMEM);
    cudaFuncSetAttribute(logits_mma_kernel,
                         cudaFuncAttributeMaxDynamicSharedMemorySize,
                         LOGMMA_SMEM);
    cudaFuncSetAttribute(av_mma_kernel,
                         cudaFuncAttributeMaxDynamicSharedMemorySize,
                         AV_SMEM);

    const int kq = kD / 4;  // 192

    // 1) operand splits (fp32 -> bf16 hi/lo, K-concat, duplicated-hi layout)
    split_a_kernel<<<(3072 * kq + 255) / 256, 256>>>(x, ab_, 3072, 3072, kD);
    split_w_kernel<<<(2304 * kq + 255) / 256, 256>>>(Wq, Wk, Wv, wqkv_, 3, kD);
    split_a_kernel<<<(768 * kq + 255) / 256, 256>>>(rel + (size_t)128 * kD, apos_, kR, 768, kD);
    split_w_kernel<<<(1536 * kq + 255) / 256, 256>>>(Wpk, Wpq, Wpq, wpos_, 2, kD);

    // 2) QKV + POS projections, merged into one launch (252 blocks)
    tgemm_dual_kernel<<<252, 256, TGEMM_SMEM>>>(
        (const __nv_bfloat16*)ab_, (const __nv_bfloat16*)wqkv_,
        bq, bk, bv, v_, qs_, ks_,
        (const __nv_bfloat16*)apos_, (const __nv_bfloat16*)wpos_,
        bpk, bpq, pks_, pqs_);

    // 2b) V transpose + split for tensor AV
    vtrans_kernel<<<dim3(6, 96), 256>>>(v_, vt_);

    // 3) fused banded-MMA logits + segment bias + mask
    dim3 glog(kS / 64, kS / 64, kB * kH);
    logits_mma_kernel<<<glog, 256, LOGMMA_SMEM>>>(
        qs_, ks_, pks_, pqs_, mask, seg, sep,
        same_b, cross_b, sscale, sdecay, lg_);

    // 4) softmax -> hi/lo bf16 probabilities
    softmax_bf16_kernel<<<kB * kH * kS, 128>>>(lg_, ps_, psl_);

    // 5) split Wo (independent of softmax/AV stream order)
    split_w_kernel<<<(768 * kq + 255) / 256, 256>>>(Wo, Wo, Wo, wpos_, 1, kE);

    // 6) tensor AV: P @ V -> A-pattern split rows directly into ab_
    av_mma_kernel<<<dim3(6, 96), 256, AV_SMEM>>>(ps_, psl_, vt_, ab_);

    // 7) Output projection: grid 3 n-tiles x 24 m-tiles
    tgemm_kernel<<<dim3(3, 24), 256, TGEMM_SMEM>>>(
        (const __nv_bfloat16*)ab_, (const __nv_bfloat16*)wpos_, 3072, bo, out);
}

// round 14
// speedup vs baseline: 1.0947x; 1.0947x over previous
#include <cuda_runtime.h>
#include <cuda_bf16.h>
#include <math.h>
#include <stdint.h>

// Problem constants
constexpr int kB  = 8;
constexpr int kS  = 384;
constexpr int kD  = 768;
constexpr int kE  = 768;
constexpr int kH  = 12;
constexpr int kHD = 64;
constexpr int kR  = 2 * kS - 1;   // 767 distinct relative positions actually used
constexpr int kK3 = 3 * kD;       // 2304: bf16-split concatenated K
constexpr int kKS = 192;          // 3*64: split head-dim for logits MMA

// ---------------------------------------------------------------------------
// Scratch (device globals; no runtime allocation allowed)
// ---------------------------------------------------------------------------
__device__ float g_v[kB * kH * kS * kHD];               // [B,H,S,HD] fp32
__device__ float g_logits[(size_t)kB * kH * kS * kS];   // [B,H,S,S]

// bf16-split operand buffers for projections (duplicated-hi layout)
__device__ unsigned short g_ab[3072 * kK3];      // A-split: x, then AV output
__device__ unsigned short g_wqkv[2304 * kK3];    // [Wq|Wk|Wv] split
__device__ unsigned short g_apos[768 * kK3];     // rel rows split (padded to 768)
__device__ unsigned short g_wpos[1536 * kK3];    // [Wpk|Wpq] split; reused for Wo

// bf16-split logits operands (written by tgemm epilogues)
__device__ unsigned short g_qs[96 * kS * kKS];   // [bh][s][192] pattern A (hi,hi,lo)
__device__ unsigned short g_ks[96 * kS * kKS];   // [bh][s][192] pattern B (hi,lo,hi)
__device__ unsigned short g_pks[kH * 768 * kKS]; // [h][r][192]  pattern B
__device__ unsigned short g_pqs[kH * 768 * kKS]; // [h][r][192]  pattern A

// attention probabilities, hi/lo bf16 split: [bh][i][384] each
__device__ unsigned short g_ps [(size_t)96 * kS * kS];
__device__ unsigned short g_psl[(size_t)96 * kS * kS];
// transposed split V for tensor AV: [bh][jt][d][192] pattern B (hi|lo|hi)
__device__ unsigned short g_vt[96 * 6 * 64 * 192];

// ---------------------------------------------------------------------------
// PTX helpers (target-independent: cp.async, ldmatrix, mma.sync — sm_80+)
// ---------------------------------------------------------------------------
__device__ __forceinline__ uint32_t smem_to_u32(const void* p) {
    uint32_t a;
    asm("{ .reg .u64 t; cvta.to.shared.u64 t, %1; cvt.u32.u64 %0, t; }"
        : "=r"(a) : "l"(p));
    return a;
}

__device__ __forceinline__ void cp_async16(uint32_t saddr, const void* gptr) {
    asm volatile("cp.async.cg.shared.global [%0], [%1], 16;\n"
                 :: "r"(saddr), "l"(gptr));
}
#define CP_COMMIT()  asm volatile("cp.async.commit_group;\n" ::: "memory")
#define CP_WAIT(n)   asm volatile("cp.async.wait_group %0;\n" :: "n"(n) : "memory")

__device__ __forceinline__ void ldmatrix_x4(uint32_t* r, uint32_t addr) {
    asm volatile("ldmatrix.sync.aligned.m8n8.x4.shared.b16 {%0,%1,%2,%3}, [%4];"
                 : "=r"(r[0]), "=r"(r[1]), "=r"(r[2]), "=r"(r[3]) : "r"(addr));
}
__device__ __forceinline__ void ldmatrix_x2(uint32_t* r, uint32_t addr) {
    asm volatile("ldmatrix.sync.aligned.m8n8.x2.shared.b16 {%0,%1}, [%2];"
                 : "=r"(r[0]), "=r"(r[1]) : "r"(addr));
}

__device__ __forceinline__ void mma_bf16(float* d, const uint32_t* a, const uint32_t* b) {
    asm volatile(
        "mma.sync.aligned.m16n8k16.row.col.f32.bf16.bf16.f32 "
        "{%0,%1,%2,%3}, {%4,%5,%6,%7}, {%8,%9}, {%0,%1,%2,%3};"
        : "+f"(d[0]), "+f"(d[1]), "+f"(d[2]), "+f"(d[3])
        : "r"(a[0]), "r"(a[1]), "r"(a[2]), "r"(a[3]),
          "r"(b[0]), "r"(b[1]));
}

// ---------------------------------------------------------------------------
// fp32 -> bf16 hi/lo split conversion kernels (duplicated-hi layouts)
// A pattern:  out[m, 0:K]=hi, [K:2K]=hi, [2K:3K]=lo
// W pattern:  out[n, 0:K]=hi, [K:2K]=lo, [2K:3K]=hi
// ---------------------------------------------------------------------------
union BF4 { __nv_bfloat16 h[4]; uint2 u; };

__device__ __forceinline__ void split4(float4 a, uint2& hi, uint2& lo)
{
    float v[4] = {a.x, a.y, a.z, a.w};
    BF4 H, L;
#pragma unroll
    for (int i = 0; i < 4; i++) {
        __nv_bfloat16 h1 = __float2bfloat16_rn(v[i]);
        float res = v[i] - __bfloat162float(h1);
        H.h[i] = h1;
        L.h[i] = __float2bfloat16_rn(res);
    }
    hi = H.u; lo = L.u;
}

__device__ __forceinline__ void split2_pack(float v0, float v1,
                                            uint32_t& hp, uint32_t& lp)
{
    __nv_bfloat16 h0 = __float2bfloat16_rn(v0), h1 = __float2bfloat16_rn(v1);
    float r0 = v0 - __bfloat162float(h0), r1 = v1 - __bfloat162float(h1);
    __nv_bfloat16 l0 = __float2bfloat16_rn(r0), l1 = __float2bfloat16_rn(r1);
    hp = (uint32_t)*(unsigned short*)&h0 | ((uint32_t)*(unsigned short*)&h1 << 16);
    lp = (uint32_t)*(unsigned short*)&l0 | ((uint32_t)*(unsigned short*)&l1 << 16);
}

__global__ __launch_bounds__(256) void split_a_kernel(
    const float* __restrict__ A, unsigned short* __restrict__ out,
    int Msrc, int Mpad, int K)
{
    int idx = blockIdx.x * 256 + threadIdx.x;
    int kq = K >> 2;
    if (idx >= Mpad * kq) return;
    int m = idx / kq;
    int c4 = (idx - m * kq) << 2;
    float4 a = (m < Msrc) ? *(const float4*)(A + (size_t)m * K + c4)
                          : make_float4(0.f, 0.f, 0.f, 0.f);
    uint2 hi, lo; split4(a, hi, lo);
    size_t base = (size_t)m * 3 * K + c4;
    *(uint2*)(out + base)         = hi;
    *(uint2*)(out + base + K)     = hi;
    *(uint2*)(out + base + 2 * K) = lo;
}

__global__ __launch_bounds__(256) void split_w_kernel(
    const float* __restrict__ W0, const float* __restrict__ W1,
    const float* __restrict__ W2, unsigned short* __restrict__ out,
    int nsrc, int K)
{
    int idx = blockIdx.x * 256 + threadIdx.x;
    int kq = K >> 2;
    int rows = nsrc * 768;
    if (idx >= rows * kq) return;
    int rr = idx / kq;
    int c4 = (idx - rr * kq) << 2;
    int s = rr / 768, r = rr - s * 768;
    const float* W = (s == 0) ? W0 : (s == 1) ? W1 : W2;
    float4 a = *(const float4*)(W + (size_t)r * K + c4);
    uint2 hi, lo; split4(a, hi, lo);
    size_t base = (size_t)rr * 3 * K + c4;
    *(uint2*)(out + base)         = hi;
    *(uint2*)(out + base + K)     = lo;
    *(uint2*)(out + base + 2 * K) = hi;
}

// ---------------------------------------------------------------------------
// bf16 HMMA GEMM body (projections). 128x128 CTA tile, BK=64, 256 threads.
// (round-12 winner shape: 2x4 warps, warp tile 64x32, double-buffered)
// mode 0: QKV   n<768 -> q split(A-pat), n<1536 -> k split(B-pat), else v fp32
// mode 1: POS   n<768 -> pk split(B-pat), else pq split(A-pat)
// mode 2: plain fp32 C[m*768+n]
// ---------------------------------------------------------------------------
constexpr int BK   = 64;
constexpr int LDT  = 72;                       // smem stride in halves (pad 8)
constexpr int TBUF = 128 * LDT * 2;            // bytes per tile buffer
constexpr int TGEMM_SMEM = 4 * TBUF;           // A0,B0,A1,B1 = 73728

__device__ __forceinline__ void store_split_pair(
    unsigned short* base, float v0, float v1, bool patA)
{
    uint32_t hp, lp;
    split2_pack(v0, v1, hp, lp);
    *(uint32_t*)(base)       = hp;
    *(uint32_t*)(base + 64)  = patA ? hp : lp;
    *(uint32_t*)(base + 128) = patA ? lp : hp;
}

__device__ __forceinline__ void store_pair(
    int mode, int Msrc, int mrow, int n, float v0, float v1,
    const float* __restrict__ b0, const float* __restrict__ b1,
    const float* __restrict__ b2,
    float* __restrict__ o0,
    unsigned short* __restrict__ s0, unsigned short* __restrict__ s1)
{
    if (mrow >= Msrc) return;
    if (mode == 2) {
        float2 w = make_float2(v0 + b0[n], v1 + b0[n + 1]);
        *(float2*)&o0[(size_t)mrow * 768 + n] = w;
        return;
    }
    int which = n / 768;
    int e = n - which * 768;
    int h = e >> 6, hd = e & 63;
    const float* bp = (which == 0) ? b0 : (which == 1) ? b1 : b2;
    float w0 = v0 + bp[e], w1 = v1 + bp[e + 1];
    if (mode == 0) {
        int bi = mrow / kS, s = mrow - bi * kS;
        if (which == 2) {
            *(float2*)&o0[((((size_t)bi * kH) + h) * kS + s) * (size_t)kHD + hd]
                = make_float2(w0, w1);
        } else {
            unsigned short* base = ((which == 0) ? s0 : s1)
                + (((size_t)(bi * kH + h) * kS) + s) * kKS + hd;
            store_split_pair(base, w0, w1, which == 0);  // q: A-pat, k: B-pat
        }
    } else {  // mode 1: pk (B-pat), pq (A-pat)
        unsigned short* base = ((which == 0) ? s0 : s1)
            + (((size_t)h * 768) + mrow) * kKS + hd;
        store_split_pair(base, w0, w1, which == 1);
    }
}

__device__ __forceinline__ void tgemm_body(
    const __nv_bfloat16* __restrict__ A, const __nv_bfloat16* __restrict__ B,
    int Msrc,
    const float* __restrict__ bias0, const float* __restrict__ bias1,
    const float* __restrict__ bias2,
    float* __restrict__ out0,
    unsigned short* __restrict__ s0, unsigned short* __restrict__ s1,
    int mode, int m0, int n0, char* smem)
{
    const uint32_t sbase = smem_to_u32(smem);

    const int t = threadIdx.x, lane = t & 31, wid = t >> 5;
    const int warp_m = wid & 1, warp_n = wid >> 1;   // 2 x 4

    const __nv_bfloat16* Ag = A + (size_t)m0 * kK3;
    const __nv_bfloat16* Bg = B + (size_t)n0 * kK3;
    const int NC = kK3 / BK;

    const int lrow = t >> 3;
    const int lc8  = (t & 7) * 8;

    auto issue = [&](int c) {
        const int buf = c & 1;
        const uint32_t dA = sbase + buf * 2 * TBUF;
        const uint32_t dB = dA + TBUF;
        const __nv_bfloat16* Ak = Ag + (size_t)c * BK;
        const __nv_bfloat16* Bk = Bg + (size_t)c * BK;
#pragma unroll
        for (int it = 0; it < 4; it++) {
            int r = lrow + it * 32;
            uint32_t so = (uint32_t)(r * LDT + lc8) * 2;
            cp_async16(dA + so, Ak + (size_t)r * kK3 + lc8);
            cp_async16(dB + so, Bk + (size_t)r * kK3 + lc8);
        }
        CP_COMMIT();
    };

    float d[4][4][4];
#pragma unroll
    for (int i = 0; i < 4; i++)
#pragma unroll
        for (int j = 0; j < 4; j++)
#pragma unroll
            for (int e = 0; e < 4; e++) d[i][j][e] = 0.f;

    const int a_row = warp_m * 64 + (lane & 15);
    const int a_col = (lane >> 4) * 8;
    const int b_row = warp_n * 32 + (lane & 7);
    const int b_col = ((lane >> 3) & 1) * 8;

    issue(0);

    for (int c = 0; c < NC; c++) {
        if (c + 1 < NC) { issue(c + 1); CP_WAIT(1); }
        else           { CP_WAIT(0); }
        __syncthreads();

        const int buf = c & 1;
        const uint32_t sA = sbase + buf * 2 * TBUF;
        const uint32_t sB = sA + TBUF;

#pragma unroll
        for (int ks = 0; ks < BK; ks += 16) {
            uint32_t a[4][4], b[4][2];
#pragma unroll
            for (int i = 0; i < 4; i++)
                ldmatrix_x4(a[i], sA + (uint32_t)((a_row + i * 16) * LDT + a_col + ks) * 2);
#pragma unroll
            for (int j = 0; j < 4; j++)
                ldmatrix_x2(b[j], sB + (uint32_t)((b_row + j * 8) * LDT + b_col + ks) * 2);
#pragma unroll
            for (int i = 0; i < 4; i++)
#pragma unroll
                for (int j = 0; j < 4; j++)
                    mma_bf16(d[i][j], a[i], b[j]);
        }
        __syncthreads();
    }

    const int mbase = m0 + warp_m * 64 + (lane >> 2);
    const int nbase = n0 + warp_n * 32 + (lane & 3) * 2;
#pragma unroll
    for (int i = 0; i < 4; i++) {
#pragma unroll
        for (int j = 0; j < 4; j++) {
            int mm = mbase + i * 16;
            int nn = nbase + j * 8;
            store_pair(mode, Msrc, mm,     nn, d[i][j][0], d[i][j][1],
                       bias0, bias1, bias2, out0, s0, s1);
            store_pair(mode, Msrc, mm + 8, nn, d[i][j][2], d[i][j][3],
                       bias0, bias1, bias2, out0, s0, s1);
        }
    }
}

// Plain entry (used for the output projection, mode 2)
__global__ __launch_bounds__(256) void tgemm_kernel(
    const __nv_bfloat16* __restrict__ A, const __nv_bfloat16* __restrict__ B,
    int Msrc,
    const float* __restrict__ bias0,
    float* __restrict__ out0)
{
    extern __shared__ __align__(16) char smem[];
    tgemm_body(A, B, Msrc, bias0, nullptr, nullptr, out0, nullptr, nullptr,
               2, blockIdx.y * 128, blockIdx.x * 128, smem);
}

// Merged QKV + POS entry: flat grid of 432 + 72 = 504 blocks.
__global__ __launch_bounds__(256) void tgemm_dual_kernel(
    const __nv_bfloat16* __restrict__ Aq, const __nv_bfloat16* __restrict__ Bq,
    const float* __restrict__ bq, const float* __restrict__ bk,
    const float* __restrict__ bv,
    float* __restrict__ v_out,
    unsigned short* __restrict__ qs, unsigned short* __restrict__ ks,
    const __nv_bfloat16* __restrict__ Ap, const __nv_bfloat16* __restrict__ Bp,
    const float* __restrict__ bpk, const float* __restrict__ bpq,
    unsigned short* __restrict__ pks, unsigned short* __restrict__ pqs)
{
    extern __shared__ __align__(16) char smem[];
    const int bx = blockIdx.x;
    if (bx < 432) {
        int m0 = (bx / 18) * 128, n0 = (bx % 18) * 128;
        tgemm_body(Aq, Bq, 3072, bq, bk, bv, v_out, qs, ks, 0, m0, n0, smem);
    } else {
        int i = bx - 432;
        int m0 = (i / 12) * 128, n0 = (i % 12) * 128;
        tgemm_body(Ap, Bp, kR, bpk, bpq, nullptr, nullptr, pks, pqs, 1, m0, n0, smem);
    }
}

// ---------------------------------------------------------------------------
// V transpose + split: g_v [bh][s][64] fp32 -> g_vt [bh][jt][d][192] (hi|lo|hi)
// ---------------------------------------------------------------------------
__global__ __launch_bounds__(256) void vtrans_kernel(
    const float* __restrict__ v, unsigned short* __restrict__ vt)
{
    __shared__ float tile[64][65];
    const int bh = blockIdx.y, jt = blockIdx.x;
    const int t = threadIdx.x;
    const float* src = v + ((size_t)bh * kS + jt * 64) * kHD;

#pragma unroll
    for (int i = 0; i < 16; i++) {
        int idx = i * 256 + t;
        tile[idx >> 6][idx & 63] = src[idx];
    }
    __syncthreads();

    unsigned short* dst = vt + (((size_t)bh * 6 + jt) * 64) * 192;
#pragma unroll
    for (int i = 0; i < 8; i++) {
        int idx = i * 256 + t;            // 0..2047
        int dd  = idx >> 5;               // d row
        int jp  = (idx & 31) * 2;         // j pair
        uint32_t hp, lp;
        split2_pack(tile[jp][dd], tile[jp + 1][dd], hp, lp);
        unsigned short* base = dst + (size_t)dd * 192 + jp;
        *(uint32_t*)(base)       = hp;    // pattern B: hi, lo, hi
        *(uint32_t*)(base + 64)  = lp;
        *(uint32_t*)(base + 128) = hp;
    }
}

// ---------------------------------------------------------------------------
// Fused banded-MMA logits kernel. Staging split into two cp.async groups at
// the k=128 boundary so the tail of the operand load overlaps the first 8
// k-steps of MMA. Accumulation order unchanged (bit-identical results).
// ---------------------------------------------------------------------------
constexpr int LDS = 200;  // smem stride in halves for all operand tiles
constexpr int LOGMMA_SMEM = (2 * 64 * LDS + 2 * 128 * LDS) * 2;  // 153600 B
constexpr int QW_STRIDE = 132;

__global__ __launch_bounds__(256) void logits_mma_kernel(
    const unsigned short* __restrict__ qs, const unsigned short* __restrict__ ks,
    const unsigned short* __restrict__ pks, const unsigned short* __restrict__ pqs,
    const int* __restrict__ mask, const int* __restrict__ seg,
    const float* __restrict__ sep,
    const float* __restrict__ same_bias, const float* __restrict__ cross_bias,
    const float* __restrict__ sep_scale, const float* __restrict__ sep_decay,
    float* __restrict__ logits)
{
    extern __shared__ __align__(16) char smem[];
    const uint32_t sb = smem_to_u32(smem);

    __shared__ int   s_segi[64], s_segj[64], s_maskj[64];
    __shared__ float s_sepi[64], s_sepj[64];

    const int t = threadIdx.x, lane = t & 31, wid = t >> 5;
    const int wm = wid >> 2, wn = wid & 3;          // 2 x 4 warps
    const int bh = blockIdx.z, b = bh / kH, h = bh % kH;
    const int i0 = blockIdx.y * 64, j0 = blockIdx.x * 64;
    const int rb = i0 - j0 + 320;                   // window base: r = rb + u

    const uint32_t sQ  = sb;
    const uint32_t sK  = sQ + 64 * LDS * 2;
    const uint32_t sPK = sK + 64 * LDS * 2;
    const uint32_t sPQ = sPK + 128 * LDS * 2;

    if (t < 64) {
        s_segi[t] = seg[b * kS + i0 + t];
        s_sepi[t] = fabsf(sep[b * kS + i0 + t]);
    } else if (t < 128) {
        int u = t - 64;
        s_segj[u]  = seg[b * kS + j0 + u];
        s_sepj[u]  = fabsf(sep[b * kS + j0 + u]);
        s_maskj[u] = mask[b * kS + j0 + u];
    }

    {
        const unsigned short* gq  = qs  + ((size_t)bh * kS + i0) * kKS;
        const unsigned short* gk  = ks  + ((size_t)bh * kS + j0) * kKS;
        const unsigned short* gpk = pks + ((size_t)h * 768 + rb) * kKS;
        const unsigned short* gpq = pqs + ((size_t)h * 768 + rb) * kKS;
        const int r0 = t >> 3;
        const int c0 = (t & 7);
        // group 1: chunks 0..15 (k-halves 0..127)
#pragma unroll
        for (int rh = 0; rh < 2; rh++) {
#pragma unroll
            for (int cc = 0; cc < 2; cc++) {
                int row = r0 + rh * 32, ch = c0 + cc * 8;
                uint32_t so = (uint32_t)(row * LDS + ch * 8) * 2;
                cp_async16(sQ + so, gq + (size_t)row * kKS + ch * 8);
                cp_async16(sK + so, gk + (size_t)row * kKS + ch * 8);
            }
        }
#pragma unroll
        for (int rh = 0; rh < 4; rh++) {
#pragma unroll
            for (int cc = 0; cc < 2; cc++) {
                int row = r0 + rh * 32, ch = c0 + cc * 8;
                uint32_t so = (uint32_t)(row * LDS + ch * 8) * 2;
                cp_async16(sPK + so, gpk + (size_t)row * kKS + ch * 8);
                cp_async16(sPQ + so, gpq + (size_t)row * kKS + ch * 8);
            }
        }
        CP_COMMIT();
        // group 2: chunks 16..23 (k-halves 128..191)
#pragma unroll
        for (int rh = 0; rh < 2; rh++) {
            int row = r0 + rh * 32, ch = c0 + 16;
            uint32_t so = (uint32_t)(row * LDS + ch * 8) * 2;
            cp_async16(sQ + so, gq + (size_t)row * kKS + ch * 8);
            cp_async16(sK + so, gk + (size_t)row * kKS + ch * 8);
        }
#pragma unroll
        for (int rh = 0; rh < 4; rh++) {
            int row = r0 + rh * 32, ch = c0 + 16;
            uint32_t so = (uint32_t)(row * LDS + ch * 8) * 2;
            cp_async16(sPK + so, gpk + (size_t)row * kKS + ch * 8);
            cp_async16(sPQ + so, gpq + (size_t)row * kKS + ch * 8);
        }
        CP_COMMIT();
        CP_WAIT(1);   // group 1 landed; group 2 still in flight
    }
    __syncthreads();

    float c2c[2][2][4], qw[2][4][4], kw[2][4][4];
#pragma unroll
    for (int i = 0; i < 2; i++) {
#pragma unroll
        for (int j = 0; j < 2; j++)
#pragma unroll
            for (int e = 0; e < 4; e++) c2c[i][j][e] = 0.f;
#pragma unroll
        for (int j = 0; j < 4; j++)
#pragma unroll
            for (int e = 0; e < 4; e++) { qw[i][j][e] = 0.f; kw[i][j][e] = 0.f; }
    }

    const int aRow = (lane & 15);
    const int aCol = (lane >> 4) * 8;
    const int bRow = (lane & 7);
    const int bCol = ((lane >> 3) & 1) * 8;

    auto mma_phase = [&](int ks_lo, int ks_hi) {
        for (int ksp = ks_lo; ksp < ks_hi; ksp += 16) {
            uint32_t aQ[2][4], aK[2][4];
#pragma unroll
            for (int fi = 0; fi < 2; fi++) {
                int r = wm * 32 + fi * 16 + aRow;
                ldmatrix_x4(aQ[fi], sQ + (uint32_t)(r * LDS + aCol + ksp) * 2);
                ldmatrix_x4(aK[fi], sK + (uint32_t)(r * LDS + aCol + ksp) * 2);
            }
            uint32_t bC[2][2];
#pragma unroll
            for (int fj = 0; fj < 2; fj++) {
                int r = wn * 16 + fj * 8 + bRow;
                ldmatrix_x2(bC[fj], sK + (uint32_t)(r * LDS + bCol + ksp) * 2);
            }
            uint32_t bPK[4][2], bPQ[4][2];
#pragma unroll
            for (int fu = 0; fu < 4; fu++) {
                int r = wn * 32 + fu * 8 + bRow;
                ldmatrix_x2(bPK[fu], sPK + (uint32_t)(r * LDS + bCol + ksp) * 2);
                ldmatrix_x2(bPQ[fu], sPQ + (uint32_t)(r * LDS + bCol + ksp) * 2);
            }
#pragma unroll
            for (int fi = 0; fi < 2; fi++)
#pragma unroll
                for (int fj = 0; fj < 2; fj++)
                    mma_bf16(c2c[fi][fj], aQ[fi], bC[fj]);
#pragma unroll
            for (int fi = 0; fi < 2; fi++)
#pragma unroll
                for (int fu = 0; fu < 4; fu++) {
                    mma_bf16(qw[fi][fu], aQ[fi], bPK[fu]);
                    mma_bf16(kw[fi][fu], aK[fi], bPQ[fu]);
                }
        }
    };

    mma_phase(0, 128);          // overlaps with group-2 loads
    CP_WAIT(0);
    __syncthreads();
    mma_phase(128, kKS);

    __syncthreads();
    float* QWs = (float*)smem;                    // [64][132]
    float* KWs = QWs + 64 * QW_STRIDE;            // [64][132]
#pragma unroll
    for (int fi = 0; fi < 2; fi++) {
#pragma unroll
        for (int fu = 0; fu < 4; fu++) {
            int rl = wm * 32 + fi * 16 + (lane >> 2);
            int u  = wn * 32 + fu * 8 + (lane & 3) * 2;
            QWs[rl * QW_STRIDE + u]           = qw[fi][fu][0];
            QWs[rl * QW_STRIDE + u + 1]       = qw[fi][fu][1];
            QWs[(rl + 8) * QW_STRIDE + u]     = qw[fi][fu][2];
            QWs[(rl + 8) * QW_STRIDE + u + 1] = qw[fi][fu][3];
            KWs[rl * QW_STRIDE + u]           = kw[fi][fu][0];
            KWs[rl * QW_STRIDE + u + 1]       = kw[fi][fu][1];
            KWs[(rl + 8) * QW_STRIDE + u]     = kw[fi][fu][2];
            KWs[(rl + 8) * QW_STRIDE + u + 1] = kw[fi][fu][3];
        }
    }
    __syncthreads();

    const float sb_same  = same_bias[h];
    const float sb_cross = cross_bias[h];
    const float scale_h  = sep_scale[h];
    const float dx       = sep_decay[h];
    const float softp    = fmaxf(dx, 0.f) + log1pf(expf(-fabsf(dx)));
    const float decay    = softp + 1e-4f;
    const float inv      = 0.07216878364870322f;  // 1/sqrt(3*HD)

#pragma unroll
    for (int fi = 0; fi < 2; fi++) {
#pragma unroll
        for (int fj = 0; fj < 2; fj++) {
            int il0 = wm * 32 + fi * 16 + (lane >> 2);
            int jl0 = wn * 16 + fj * 8 + (lane & 3) * 2;
#pragma unroll
            for (int half = 0; half < 2; half++) {
                int il = il0 + half * 8;
                float raw0 = c2c[fi][fj][half * 2];
                float raw1 = c2c[fi][fj][half * 2 + 1];
                int   segi = s_segi[il];
                float sepi = s_sepi[il];
#pragma unroll
                for (int e = 0; e < 2; e++) {
                    int jl = jl0 + e;
                    int u  = il - jl + 63;
                    float val = ((e ? raw1 : raw0)
                                 + QWs[il * QW_STRIDE + u]
                                 + KWs[jl * QW_STRIDE + u]) * inv;
                    if (segi == s_segj[jl]) {
                        val += sb_same;
                    } else {
                        float gap = fabsf(sepi - s_sepj[jl]);
                        val += sb_cross + expf(-gap * decay) * scale_h;
                    }
                    if (s_maskj[jl] == 0) val = -9e15f;
                    logits[(((size_t)bh * kS) + i0 + il) * kS + j0 + jl] = val;
                }
            }
        }
    }
}

// ---------------------------------------------------------------------------
// Row softmax over S=384, writing hi/lo bf16 split probabilities.
// ---------------------------------------------------------------------------
__global__ __launch_bounds__(128) void softmax_bf16_kernel(
    const float* __restrict__ logits,
    unsigned short* __restrict__ ps, unsigned short* __restrict__ psl)
{
    const size_t row = blockIdx.x;
    const float* p = logits + row * kS;
    const int t = threadIdx.x;

    float v0 = p[t], v1 = p[t + 128], v2 = p[t + 256];
    float m = fmaxf(v0, fmaxf(v1, v2));

    __shared__ float red[4];
#pragma unroll
    for (int o = 16; o; o >>= 1) m = fmaxf(m, __shfl_xor_sync(0xffffffffu, m, o));
    if ((t & 31) == 0) red[t >> 5] = m;
    __syncthreads();
    m = fmaxf(fmaxf(red[0], red[1]), fmaxf(red[2], red[3]));

    float e0 = __expf(v0 - m), e1 = __expf(v1 - m), e2 = __expf(v2 - m);
    float s = e0 + e1 + e2;
#pragma unroll
    for (int o = 16; o; o >>= 1) s += __shfl_xor_sync(0xffffffffu, s, o);
    __shared__ float red2[4];
    if ((t & 31) == 0) red2[t >> 5] = s;
    __syncthreads();
    s = red2[0] + red2[1] + red2[2] + red2[3];

    float r = 1.f / s;
    float p0 = e0 * r, p1 = e1 * r, p2 = e2 * r;
    unsigned short* oh = ps  + row * kS;
    unsigned short* ol = psl + row * kS;
    __nv_bfloat16 h0 = __float2bfloat16_rn(p0);
    __nv_bfloat16 h1 = __float2bfloat16_rn(p1);
    __nv_bfloat16 h2 = __float2bfloat16_rn(p2);
    __nv_bfloat16 l0 = __float2bfloat16_rn(p0 - __bfloat162float(h0));
    __nv_bfloat16 l1 = __float2bfloat16_rn(p1 - __bfloat162float(h1));
    __nv_bfloat16 l2 = __float2bfloat16_rn(p2 - __bfloat162float(h2));
    oh[t]       = *(unsigned short*)&h0;
    oh[t + 128] = *(unsigned short*)&h1;
    oh[t + 256] = *(unsigned short*)&h2;
    ol[t]       = *(unsigned short*)&l0;
    ol[t + 128] = *(unsigned short*)&l1;
    ol[t + 256] = *(unsigned short*)&l2;
}

// ---------------------------------------------------------------------------
// Tensor AV: O[b,i,h*64+d] = sum_j P[bh,i,j] * V[bh,j,d]
// 3-term split per 64-j tile (K=192): A = [P_hi|P_hi|P_lo], B = V^T (hi|lo|hi).
// Epilogue writes O directly as the A-pattern bf16 split (hi|hi|lo, 2304-wide)
// consumed by the output-projection tgemm.
// ---------------------------------------------------------------------------
constexpr int LDP  = 392;   // P smem stride in halves (384 + 8)
constexpr int LDV  = 200;   // V smem stride in halves (192 + 8)
constexpr int AV_SMEM = 2 * 64 * LDP * 2 + 2 * 64 * LDV * 2;  // 100352+51200

__global__ __launch_bounds__(256) void av_mma_kernel(
    const unsigned short* __restrict__ ps, const unsigned short* __restrict__ psl,
    const unsigned short* __restrict__ vt,
    unsigned short* __restrict__ osplit)
{
    extern __shared__ __align__(16) char smem[];
    const uint32_t sPh = smem_to_u32(smem);
    const uint32_t sPl = sPh + 64 * LDP * 2;
    const uint32_t sV0 = sPl + 64 * LDP * 2;

    const int t = threadIdx.x, lane = t & 31, wid = t >> 5;
    const int wm = wid >> 2, wn = wid & 3;      // 2 x 4 warps
    const int bh = blockIdx.y, b = bh / kH, h = bh % kH;
    const int i0 = blockIdx.x * 64;

    {
        const unsigned short* gh = ps  + ((size_t)bh * kS + i0) * kS;
        const unsigned short* gl = psl + ((size_t)bh * kS + i0) * kS;
#pragma unroll
        for (int i = 0; i < 12; i++) {
            int idx = i * 256 + t;            // 0..3071
            int row = idx / 48, q = idx % 48;
            uint32_t so = (uint32_t)(row * LDP + q * 8) * 2;
            size_t  go = (size_t)row * kS + q * 8;
            cp_async16(sPh + so, gh + go);
            cp_async16(sPl + so, gl + go);
        }
    }
    auto stageV = [&](int jt) {
        const unsigned short* g = vt + (((size_t)bh * 6 + jt) * 64) * 192;
        const uint32_t dst = sV0 + (jt & 1) * 64 * LDV * 2;
#pragma unroll
        for (int i = 0; i < 6; i++) {
            int idx = i * 256 + t;            // 0..1535
            int row = idx / 24, ch = idx % 24;
            cp_async16(dst + (uint32_t)(row * LDV + ch * 8) * 2,
                       g + (size_t)row * 192 + ch * 8);
        }
    };
    stageV(0);
    CP_COMMIT();   // group 0: P + V0

    float d[2][2][4];
#pragma unroll
    for (int i = 0; i < 2; i++)
#pragma unroll
        for (int j = 0; j < 2; j++)
#pragma unroll
            for (int e = 0; e < 4; e++) d[i][j][e] = 0.f;

    const int aRow = lane & 15, aCol = (lane >> 4) * 8;
    const int bRow = lane & 7,  bCol = ((lane >> 3) & 1) * 8;

    for (int jt = 0; jt < 6; jt++) {
        if (jt + 1 < 6) { stageV(jt + 1); CP_COMMIT(); CP_WAIT(1); }
        else            { CP_WAIT(0); }
        __syncthreads();

        const uint32_t sV = sV0 + (jt & 1) * 64 * LDV * 2;

#pragma unroll
        for (int ksp = 0; ksp < 192; ksp += 16) {
            const uint32_t sPbuf = (ksp < 128) ? sPh : sPl;   // [hi|hi|lo]
            uint32_t a[2][4], bf[2][2];
#pragma unroll
            for (int fi = 0; fi < 2; fi++)
                ldmatrix_x4(a[fi], sPbuf + (uint32_t)((wm * 32 + fi * 16 + aRow) * LDP
                                                      + jt * 64 + (ksp & 63) + aCol) * 2);
#pragma unroll
            for (int fj = 0; fj < 2; fj++)
                ldmatrix_x2(bf[fj], sV + (uint32_t)((wn * 16 + fj * 8 + bRow) * LDV
                                                    + ksp + bCol) * 2);
#pragma unroll
            for (int fi = 0; fi < 2; fi++)
#pragma unroll
                for (int fj = 0; fj < 2; fj++)
                    mma_bf16(d[fi][fj], a[fi], bf[fj]);
        }
        __syncthreads();
    }

    // epilogue: write O as A-pattern split (hi|hi|lo) rows of g_ab
#pragma unroll
    for (int fi = 0; fi < 2; fi++) {
#pragma unroll
        for (int fj = 0; fj < 2; fj++) {
            int mm = i0 + wm * 32 + fi * 16 + (lane >> 2);
            int nn = h * 64 + wn * 16 + fj * 8 + (lane & 3) * 2;
            size_t row0 = (size_t)b * kS + mm;
            unsigned short* base0 = osplit + row0 * kK3 + nn;
            uint32_t hp, lp;
            split2_pack(d[fi][fj][0], d[fi][fj][1], hp, lp);
            *(uint32_t*)(base0)         = hp;
            *(uint32_t*)(base0 + 768)   = hp;
            *(uint32_t*)(base0 + 1536)  = lp;
            unsigned short* base1 = osplit + (row0 + 8) * kK3 + nn;
            split2_pack(d[fi][fj][2], d[fi][fj][3], hp, lp);
            *(uint32_t*)(base1)         = hp;
            *(uint32_t*)(base1 + 768)   = hp;
            *(uint32_t*)(base1 + 1536)  = lp;
        }
    }
}

// ---------------------------------------------------------------------------
// Launch
// ---------------------------------------------------------------------------
extern "C" void kernel_launch(void* const* d_in, const int* in_sizes, int n_in,
                              void* d_out, int out_size)
{
    const float* x    = (const float*)d_in[0];
    const int*   mask = (const int*)d_in[1];
    const int*   seg  = (const int*)d_in[2];
    const float* sep  = (const float*)d_in[3];
    const float* Wq   = (const float*)d_in[4];
    const float* bq   = (const float*)d_in[5];
    const float* Wk   = (const float*)d_in[6];
    const float* bk   = (const float*)d_in[7];
    const float* Wv   = (const float*)d_in[8];
    const float* bv   = (const float*)d_in[9];
    const float* rel  = (const float*)d_in[10];
    const float* Wpk  = (const float*)d_in[11];
    const float* bpk  = (const float*)d_in[12];
    const float* Wpq  = (const float*)d_in[13];
    const float* bpq  = (const float*)d_in[14];
    const float* same_b  = (const float*)d_in[15];
    const float* cross_b = (const float*)d_in[16];
    const float* sscale  = (const float*)d_in[17];
    const float* sdecay  = (const float*)d_in[18];
    const float* Wo   = (const float*)d_in[19];
    const float* bo   = (const float*)d_in[20];
    float* out = (float*)d_out;

    float *v_, *lg_;
    unsigned short *ab_, *wqkv_, *apos_, *wpos_, *qs_, *ks_, *pks_, *pqs_, *vt_, *ps_, *psl_;
    cudaGetSymbolAddress((void**)&v_,  g_v);
    cudaGetSymbolAddress((void**)&lg_, g_logits);
    cudaGetSymbolAddress((void**)&ab_,   g_ab);
    cudaGetSymbolAddress((void**)&wqkv_, g_wqkv);
    cudaGetSymbolAddress((void**)&apos_, g_apos);
    cudaGetSymbolAddress((void**)&wpos_, g_wpos);
    cudaGetSymbolAddress((void**)&qs_,  g_qs);
    cudaGetSymbolAddress((void**)&ks_,  g_ks);
    cudaGetSymbolAddress((void**)&pks_, g_pks);
    cudaGetSymbolAddress((void**)&pqs_, g_pqs);
    cudaGetSymbolAddress((void**)&vt_,  g_vt);
    cudaGetSymbolAddress((void**)&ps_,  g_ps);
    cudaGetSymbolAddress((void**)&psl_, g_psl);

    cudaFuncSetAttribute(tgemm_kernel,
                         cudaFuncAttributeMaxDynamicSharedMemorySize,
                         TGEMM_SMEM);
    cudaFuncSetAttribute(tgemm_dual_kernel,
                         cudaFuncAttributeMaxDynamicSharedMemorySize,
                         TGEMM_SMEM);
    cudaFuncSetAttribute(logits_mma_kernel,
                         cudaFuncAttributeMaxDynamicSharedMemorySize,
                         LOGMMA_SMEM);
    cudaFuncSetAttribute(av_mma_kernel,
                         cudaFuncAttributeMaxDynamicSharedMemorySize,
                         AV_SMEM);

    const int kq = kD / 4;  // 192

    // 1) operand splits (fp32 -> bf16 hi/lo, K-concat, duplicated-hi layout)
    split_a_kernel<<<(3072 * kq + 255) / 256, 256>>>(x, ab_, 3072, 3072, kD);
    split_w_kernel<<<(2304 * kq + 255) / 256, 256>>>(Wq, Wk, Wv, wqkv_, 3, kD);
    split_a_kernel<<<(768 * kq + 255) / 256, 256>>>(rel + (size_t)128 * kD, apos_, kR, 768, kD);
    split_w_kernel<<<(1536 * kq + 255) / 256, 256>>>(Wpk, Wpq, Wpq, wpos_, 2, kD);

    // 2) QKV + POS projections, merged into one launch (504 blocks)
    tgemm_dual_kernel<<<504, 256, TGEMM_SMEM>>>(
        (const __nv_bfloat16*)ab_, (const __nv_bfloat16*)wqkv_,
        bq, bk, bv, v_, qs_, ks_,
        (const __nv_bfloat16*)apos_, (const __nv_bfloat16*)wpos_,
        bpk, bpq, pks_, pqs_);

    // 2b) V transpose + split for tensor AV
    vtrans_kernel<<<dim3(6, 96), 256>>>(v_, vt_);

    // 3) fused banded-MMA logits + segment bias + mask
    dim3 glog(kS / 64, kS / 64, kB * kH);
    logits_mma_kernel<<<glog, 256, LOGMMA_SMEM>>>(
        qs_, ks_, pks_, pqs_, mask, seg, sep,
        same_b, cross_b, sscale, sdecay, lg_);

    // 4) softmax -> hi/lo bf16 probabilities
    softmax_bf16_kernel<<<kB * kH * kS, 128>>>(lg_, ps_, psl_);

    // 5) split Wo (independent of softmax/AV stream order)
    split_w_kernel<<<(768 * kq + 255) / 256, 256>>>(Wo, Wo, Wo, wpos_, 1, kE);

    // 6) tensor AV: P @ V -> A-pattern split rows directly into ab_
    av_mma_kernel<<<dim3(6, 96), 256, AV_SMEM>>>(ps_, psl_, vt_, ab_);

    // 7) Output projection (A operand = av output split, already in ab_)
    tgemm_kernel<<<dim3(6, 24), 256, TGEMM_SMEM>>>(
        (const __nv_bfloat16*)ab_, (const __nv_bfloat16*)wpos_, 3072, bo, out);
}

// round 15
// speedup vs baseline: 1.1611x; 1.0606x over previous
#include <cuda_runtime.h>
#include <cuda_bf16.h>
#include <math.h>
#include <stdint.h>

// Problem constants
constexpr int kB  = 8;
constexpr int kS  = 384;
constexpr int kD  = 768;
constexpr int kE  = 768;
constexpr int kH  = 12;
constexpr int kHD = 64;
constexpr int kR  = 2 * kS - 1;   // 767 distinct relative positions actually used
constexpr int kK3 = 3 * kD;       // 2304: bf16-split concatenated K
constexpr int kKS = 192;          // 3*64: split head-dim for logits MMA

// ---------------------------------------------------------------------------
// Scratch (device globals; no runtime allocation allowed)
// ---------------------------------------------------------------------------
__device__ float g_v[kB * kH * kS * kHD];               // [B,H,S,HD] fp32
__device__ float g_logits[(size_t)kB * kH * kS * kS];   // [B,H,S,S]

// bf16-split operand buffers for projections (duplicated-hi layout)
__device__ unsigned short g_ab[3072 * kK3];      // A-split: x, then AV output
__device__ unsigned short g_wqkv[2304 * kK3];    // [Wq|Wk|Wv] split
__device__ unsigned short g_apos[768 * kK3];     // rel rows split (padded to 768)
__device__ unsigned short g_wpos[1536 * kK3];    // [Wpk|Wpq] split; reused for Wo

// bf16-split logits operands (written by tgemm epilogues)
__device__ unsigned short g_qs[96 * kS * kKS];   // [bh][s][192] pattern A (hi,hi,lo)
__device__ unsigned short g_ks[96 * kS * kKS];   // [bh][s][192] pattern B (hi,lo,hi)
__device__ unsigned short g_pks[kH * 768 * kKS]; // [h][r][192]  pattern B
__device__ unsigned short g_pqs[kH * 768 * kKS]; // [h][r][192]  pattern A

// attention probabilities, hi/lo bf16 split: [bh][i][384] each
__device__ unsigned short g_ps [(size_t)96 * kS * kS];
__device__ unsigned short g_psl[(size_t)96 * kS * kS];
// transposed split V for tensor AV: [bh][jt][d][192] pattern B (hi|lo|hi)
__device__ unsigned short g_vt[96 * 6 * 64 * 192];

// ---------------------------------------------------------------------------
// PTX helpers (target-independent: cp.async, ldmatrix, mma.sync — sm_80+)
// ---------------------------------------------------------------------------
__device__ __forceinline__ uint32_t smem_to_u32(const void* p) {
    uint32_t a;
    asm("{ .reg .u64 t; cvta.to.shared.u64 t, %1; cvt.u32.u64 %0, t; }"
        : "=r"(a) : "l"(p));
    return a;
}

__device__ __forceinline__ void cp_async16(uint32_t saddr, const void* gptr) {
    asm volatile("cp.async.cg.shared.global [%0], [%1], 16;\n"
                 :: "r"(saddr), "l"(gptr));
}
#define CP_COMMIT()  asm volatile("cp.async.commit_group;\n" ::: "memory")
#define CP_WAIT(n)   asm volatile("cp.async.wait_group %0;\n" :: "n"(n) : "memory")

__device__ __forceinline__ void ldmatrix_x4(uint32_t* r, uint32_t addr) {
    asm volatile("ldmatrix.sync.aligned.m8n8.x4.shared.b16 {%0,%1,%2,%3}, [%4];"
                 : "=r"(r[0]), "=r"(r[1]), "=r"(r[2]), "=r"(r[3]) : "r"(addr));
}
__device__ __forceinline__ void ldmatrix_x2(uint32_t* r, uint32_t addr) {
    asm volatile("ldmatrix.sync.aligned.m8n8.x2.shared.b16 {%0,%1}, [%2];"
                 : "=r"(r[0]), "=r"(r[1]) : "r"(addr));
}

__device__ __forceinline__ void mma_bf16(float* d, const uint32_t* a, const uint32_t* b) {
    asm volatile(
        "mma.sync.aligned.m16n8k16.row.col.f32.bf16.bf16.f32 "
        "{%0,%1,%2,%3}, {%4,%5,%6,%7}, {%8,%9}, {%0,%1,%2,%3};"
        : "+f"(d[0]), "+f"(d[1]), "+f"(d[2]), "+f"(d[3])
        : "r"(a[0]), "r"(a[1]), "r"(a[2]), "r"(a[3]),
          "r"(b[0]), "r"(b[1]));
}

// ---------------------------------------------------------------------------
// fp32 -> bf16 hi/lo split conversion kernels (duplicated-hi layouts)
// A pattern:  out[m, 0:K]=hi, [K:2K]=hi, [2K:3K]=lo
// W pattern:  out[n, 0:K]=hi, [K:2K]=lo, [2K:3K]=hi
// ---------------------------------------------------------------------------
union BF4 { __nv_bfloat16 h[4]; uint2 u; };

__device__ __forceinline__ void split4(float4 a, uint2& hi, uint2& lo)
{
    float v[4] = {a.x, a.y, a.z, a.w};
    BF4 H, L;
#pragma unroll
    for (int i = 0; i < 4; i++) {
        __nv_bfloat16 h1 = __float2bfloat16_rn(v[i]);
        float res = v[i] - __bfloat162float(h1);
        H.h[i] = h1;
        L.h[i] = __float2bfloat16_rn(res);
    }
    hi = H.u; lo = L.u;
}

__device__ __forceinline__ void split2_pack(float v0, float v1,
                                            uint32_t& hp, uint32_t& lp)
{
    __nv_bfloat16 h0 = __float2bfloat16_rn(v0), h1 = __float2bfloat16_rn(v1);
    float r0 = v0 - __bfloat162float(h0), r1 = v1 - __bfloat162float(h1);
    __nv_bfloat16 l0 = __float2bfloat16_rn(r0), l1 = __float2bfloat16_rn(r1);
    hp = (uint32_t)*(unsigned short*)&h0 | ((uint32_t)*(unsigned short*)&h1 << 16);
    lp = (uint32_t)*(unsigned short*)&l0 | ((uint32_t)*(unsigned short*)&l1 << 16);
}

__global__ __launch_bounds__(256) void split_a_kernel(
    const float* __restrict__ A, unsigned short* __restrict__ out,
    int Msrc, int Mpad, int K)
{
    int idx = blockIdx.x * 256 + threadIdx.x;
    int kq = K >> 2;
    if (idx >= Mpad * kq) return;
    int m = idx / kq;
    int c4 = (idx - m * kq) << 2;
    float4 a = (m < Msrc) ? *(const float4*)(A + (size_t)m * K + c4)
                          : make_float4(0.f, 0.f, 0.f, 0.f);
    uint2 hi, lo; split4(a, hi, lo);
    size_t base = (size_t)m * 3 * K + c4;
    *(uint2*)(out + base)         = hi;
    *(uint2*)(out + base + K)     = hi;
    *(uint2*)(out + base + 2 * K) = lo;
}

__global__ __launch_bounds__(256) void split_w_kernel(
    const float* __restrict__ W0, const float* __restrict__ W1,
    const float* __restrict__ W2, unsigned short* __restrict__ out,
    int nsrc, int K)
{
    int idx = blockIdx.x * 256 + threadIdx.x;
    int kq = K >> 2;
    int rows = nsrc * 768;
    if (idx >= rows * kq) return;
    int rr = idx / kq;
    int c4 = (idx - rr * kq) << 2;
    int s = rr / 768, r = rr - s * 768;
    const float* W = (s == 0) ? W0 : (s == 1) ? W1 : W2;
    float4 a = *(const float4*)(W + (size_t)r * K + c4);
    uint2 hi, lo; split4(a, hi, lo);
    size_t base = (size_t)rr * 3 * K + c4;
    *(uint2*)(out + base)         = hi;
    *(uint2*)(out + base + K)     = lo;
    *(uint2*)(out + base + 2 * K) = hi;
}

// ---------------------------------------------------------------------------
// bf16 HMMA GEMM body (projections). 128x128 CTA tile, BK=64, 256 threads.
// (round-12 winner shape: 2x4 warps, warp tile 64x32, double-buffered)
// mode 0: QKV   n<768 -> q split(A-pat), n<1536 -> k split(B-pat), else v fp32
// mode 1: POS   n<768 -> pk split(B-pat), else pq split(A-pat)
// mode 2: plain fp32 C[m*768+n]
// ---------------------------------------------------------------------------
constexpr int BK   = 64;
constexpr int LDT  = 72;                       // smem stride in halves (pad 8)
constexpr int TBUF = 128 * LDT * 2;            // bytes per tile buffer
constexpr int TGEMM_SMEM = 4 * TBUF;           // A0,B0,A1,B1 = 73728

__device__ __forceinline__ void store_split_pair(
    unsigned short* base, float v0, float v1, bool patA)
{
    uint32_t hp, lp;
    split2_pack(v0, v1, hp, lp);
    *(uint32_t*)(base)       = hp;
    *(uint32_t*)(base + 64)  = patA ? hp : lp;
    *(uint32_t*)(base + 128) = patA ? lp : hp;
}

__device__ __forceinline__ void store_pair(
    int mode, int Msrc, int mrow, int n, float v0, float v1,
    const float* __restrict__ b0, const float* __restrict__ b1,
    const float* __restrict__ b2,
    float* __restrict__ o0,
    unsigned short* __restrict__ s0, unsigned short* __restrict__ s1)
{
    if (mrow >= Msrc) return;
    if (mode == 2) {
        float2 w = make_float2(v0 + b0[n], v1 + b0[n + 1]);
        *(float2*)&o0[(size_t)mrow * 768 + n] = w;
        return;
    }
    int which = n / 768;
    int e = n - which * 768;
    int h = e >> 6, hd = e & 63;
    const float* bp = (which == 0) ? b0 : (which == 1) ? b1 : b2;
    float w0 = v0 + bp[e], w1 = v1 + bp[e + 1];
    if (mode == 0) {
        int bi = mrow / kS, s = mrow - bi * kS;
        if (which == 2) {
            *(float2*)&o0[((((size_t)bi * kH) + h) * kS + s) * (size_t)kHD + hd]
                = make_float2(w0, w1);
        } else {
            unsigned short* base = ((which == 0) ? s0 : s1)
                + (((size_t)(bi * kH + h) * kS) + s) * kKS + hd;
            store_split_pair(base, w0, w1, which == 0);  // q: A-pat, k: B-pat
        }
    } else {  // mode 1: pk (B-pat), pq (A-pat)
        unsigned short* base = ((which == 0) ? s0 : s1)
            + (((size_t)h * 768) + mrow) * kKS + hd;
        store_split_pair(base, w0, w1, which == 1);
    }
}

__device__ __forceinline__ void tgemm_body(
    const __nv_bfloat16* __restrict__ A, const __nv_bfloat16* __restrict__ B,
    int Msrc,
    const float* __restrict__ bias0, const float* __restrict__ bias1,
    const float* __restrict__ bias2,
    float* __restrict__ out0,
    unsigned short* __restrict__ s0, unsigned short* __restrict__ s1,
    int mode, int m0, int n0, char* smem)
{
    const uint32_t sbase = smem_to_u32(smem);

    const int t = threadIdx.x, lane = t & 31, wid = t >> 5;
    const int warp_m = wid & 1, warp_n = wid >> 1;   // 2 x 4

    const __nv_bfloat16* Ag = A + (size_t)m0 * kK3;
    const __nv_bfloat16* Bg = B + (size_t)n0 * kK3;
    const int NC = kK3 / BK;

    const int lrow = t >> 3;
    const int lc8  = (t & 7) * 8;

    auto issue = [&](int c) {
        const int buf = c & 1;
        const uint32_t dA = sbase + buf * 2 * TBUF;
        const uint32_t dB = dA + TBUF;
        const __nv_bfloat16* Ak = Ag + (size_t)c * BK;
        const __nv_bfloat16* Bk = Bg + (size_t)c * BK;
#pragma unroll
        for (int it = 0; it < 4; it++) {
            int r = lrow + it * 32;
            uint32_t so = (uint32_t)(r * LDT + lc8) * 2;
            cp_async16(dA + so, Ak + (size_t)r * kK3 + lc8);
            cp_async16(dB + so, Bk + (size_t)r * kK3 + lc8);
        }
        CP_COMMIT();
    };

    float d[4][4][4];
#pragma unroll
    for (int i = 0; i < 4; i++)
#pragma unroll
        for (int j = 0; j < 4; j++)
#pragma unroll
            for (int e = 0; e < 4; e++) d[i][j][e] = 0.f;

    const int a_row = warp_m * 64 + (lane & 15);
    const int a_col = (lane >> 4) * 8;
    const int b_row = warp_n * 32 + (lane & 7);
    const int b_col = ((lane >> 3) & 1) * 8;

    issue(0);

    for (int c = 0; c < NC; c++) {
        if (c + 1 < NC) { issue(c + 1); CP_WAIT(1); }
        else           { CP_WAIT(0); }
        __syncthreads();

        const int buf = c & 1;
        const uint32_t sA = sbase + buf * 2 * TBUF;
        const uint32_t sB = sA + TBUF;

#pragma unroll
        for (int ks = 0; ks < BK; ks += 16) {
            uint32_t a[4][4], b[4][2];
#pragma unroll
            for (int i = 0; i < 4; i++)
                ldmatrix_x4(a[i], sA + (uint32_t)((a_row + i * 16) * LDT + a_col + ks) * 2);
#pragma unroll
            for (int j = 0; j < 4; j++)
                ldmatrix_x2(b[j], sB + (uint32_t)((b_row + j * 8) * LDT + b_col + ks) * 2);
#pragma unroll
            for (int i = 0; i < 4; i++)
#pragma unroll
                for (int j = 0; j < 4; j++)
                    mma_bf16(d[i][j], a[i], b[j]);
        }
        __syncthreads();
    }

    const int mbase = m0 + warp_m * 64 + (lane >> 2);
    const int nbase = n0 + warp_n * 32 + (lane & 3) * 2;
#pragma unroll
    for (int i = 0; i < 4; i++) {
#pragma unroll
        for (int j = 0; j < 4; j++) {
            int mm = mbase + i * 16;
            int nn = nbase + j * 8;
            store_pair(mode, Msrc, mm,     nn, d[i][j][0], d[i][j][1],
                       bias0, bias1, bias2, out0, s0, s1);
            store_pair(mode, Msrc, mm + 8, nn, d[i][j][2], d[i][j][3],
                       bias0, bias1, bias2, out0, s0, s1);
        }
    }
}

// Plain entry (used for the output projection, mode 2)
__global__ __launch_bounds__(256) void tgemm_kernel(
    const __nv_bfloat16* __restrict__ A, const __nv_bfloat16* __restrict__ B,
    int Msrc,
    const float* __restrict__ bias0,
    float* __restrict__ out0)
{
    extern __shared__ __align__(16) char smem[];
    tgemm_body(A, B, Msrc, bias0, nullptr, nullptr, out0, nullptr, nullptr,
               2, blockIdx.y * 128, blockIdx.x * 128, smem);
}

// Merged QKV + POS entry: flat grid of 432 + 72 = 504 blocks.
__global__ __launch_bounds__(256) void tgemm_dual_kernel(
    const __nv_bfloat16* __restrict__ Aq, const __nv_bfloat16* __restrict__ Bq,
    const float* __restrict__ bq, const float* __restrict__ bk,
    const float* __restrict__ bv,
    float* __restrict__ v_out,
    unsigned short* __restrict__ qs, unsigned short* __restrict__ ks,
    const __nv_bfloat16* __restrict__ Ap, const __nv_bfloat16* __restrict__ Bp,
    const float* __restrict__ bpk, const float* __restrict__ bpq,
    unsigned short* __restrict__ pks, unsigned short* __restrict__ pqs)
{
    extern __shared__ __align__(16) char smem[];
    const int bx = blockIdx.x;
    if (bx < 432) {
        int m0 = (bx / 18) * 128, n0 = (bx % 18) * 128;
        tgemm_body(Aq, Bq, 3072, bq, bk, bv, v_out, qs, ks, 0, m0, n0, smem);
    } else {
        int i = bx - 432;
        int m0 = (i / 12) * 128, n0 = (i % 12) * 128;
        tgemm_body(Ap, Bp, kR, bpk, bpq, nullptr, nullptr, pks, pqs, 1, m0, n0, smem);
    }
}

// ---------------------------------------------------------------------------
// V transpose + split: g_v [bh][s][64] fp32 -> g_vt [bh][jt][d][192] (hi|lo|hi)
// ---------------------------------------------------------------------------
__global__ __launch_bounds__(256) void vtrans_kernel(
    const float* __restrict__ v, unsigned short* __restrict__ vt)
{
    __shared__ float tile[64][65];
    const int bh = blockIdx.y, jt = blockIdx.x;
    const int t = threadIdx.x;
    const float* src = v + ((size_t)bh * kS + jt * 64) * kHD;

#pragma unroll
    for (int i = 0; i < 16; i++) {
        int idx = i * 256 + t;
        tile[idx >> 6][idx & 63] = src[idx];
    }
    __syncthreads();

    unsigned short* dst = vt + (((size_t)bh * 6 + jt) * 64) * 192;
#pragma unroll
    for (int i = 0; i < 8; i++) {
        int idx = i * 256 + t;            // 0..2047
        int dd  = idx >> 5;               // d row
        int jp  = (idx & 31) * 2;         // j pair
        uint32_t hp, lp;
        split2_pack(tile[jp][dd], tile[jp + 1][dd], hp, lp);
        unsigned short* base = dst + (size_t)dd * 192 + jp;
        *(uint32_t*)(base)       = hp;    // pattern B: hi, lo, hi
        *(uint32_t*)(base + 64)  = lp;
        *(uint32_t*)(base + 128) = hp;
    }
}

// ---------------------------------------------------------------------------
// Fused banded-MMA logits kernel — two-pass window variant.
// smem halved (PK/PQ single 64-row buffers, window processed in two u-passes)
// -> 102.4 KB -> 2 CTAs/SM. Warp wn covers u = p*64 + wn*16 + fu2*8.
// Per-u accumulation order over ksp unchanged => bit-identical results.
// ---------------------------------------------------------------------------
constexpr int LDS = 200;  // smem stride in halves for all operand tiles
constexpr int LOGMMA_SMEM = 4 * 64 * LDS * 2;  // 102400 B
constexpr int QW_STRIDE = 132;

__global__ __launch_bounds__(256, 2) void logits_mma_kernel(
    const unsigned short* __restrict__ qs, const unsigned short* __restrict__ ks,
    const unsigned short* __restrict__ pks, const unsigned short* __restrict__ pqs,
    const int* __restrict__ mask, const int* __restrict__ seg,
    const float* __restrict__ sep,
    const float* __restrict__ same_bias, const float* __restrict__ cross_bias,
    const float* __restrict__ sep_scale, const float* __restrict__ sep_decay,
    float* __restrict__ logits)
{
    extern __shared__ __align__(16) char smem[];
    const uint32_t sb = smem_to_u32(smem);

    __shared__ int   s_segi[64], s_segj[64], s_maskj[64];
    __shared__ float s_sepi[64], s_sepj[64];

    const int t = threadIdx.x, lane = t & 31, wid = t >> 5;
    const int wm = wid >> 2, wn = wid & 3;          // 2 x 4 warps
    const int bh = blockIdx.z, b = bh / kH, h = bh % kH;
    const int i0 = blockIdx.y * 64, j0 = blockIdx.x * 64;
    const int rb = i0 - j0 + 320;                   // window base: r = rb + u

    const uint32_t sQ  = sb;
    const uint32_t sK  = sQ + 64 * LDS * 2;
    const uint32_t sPK = sK + 64 * LDS * 2;         // 64-row window buffer
    const uint32_t sPQ = sPK + 64 * LDS * 2;        // 64-row window buffer

    if (t < 64) {
        s_segi[t] = seg[b * kS + i0 + t];
        s_sepi[t] = fabsf(sep[b * kS + i0 + t]);
    } else if (t < 128) {
        int u = t - 64;
        s_segj[u]  = seg[b * kS + j0 + u];
        s_sepj[u]  = fabsf(sep[b * kS + j0 + u]);
        s_maskj[u] = mask[b * kS + j0 + u];
    }

    const unsigned short* gq  = qs  + ((size_t)bh * kS + i0) * kKS;
    const unsigned short* gk  = ks  + ((size_t)bh * kS + j0) * kKS;
    const unsigned short* gpk = pks + ((size_t)h * 768 + rb) * kKS;
    const unsigned short* gpq = pqs + ((size_t)h * 768 + rb) * kKS;
    const int r0 = t >> 3;
    const int c0 = (t & 7);

    // stage pass 0: Q, K + PK/PQ rows [0,64)
#pragma unroll
    for (int rh = 0; rh < 2; rh++) {
#pragma unroll
        for (int cc = 0; cc < 3; cc++) {
            int row = r0 + rh * 32, ch = c0 + cc * 8;
            uint32_t so = (uint32_t)(row * LDS + ch * 8) * 2;
            size_t  go = (size_t)row * kKS + ch * 8;
            cp_async16(sQ + so,  gq + go);
            cp_async16(sK + so,  gk + go);
            cp_async16(sPK + so, gpk + go);
            cp_async16(sPQ + so, gpq + go);
        }
    }
    CP_COMMIT();
    CP_WAIT(0);
    __syncthreads();

    float c2c[2][2][4], qw[2][4][4], kw[2][4][4];
#pragma unroll
    for (int i = 0; i < 2; i++) {
#pragma unroll
        for (int j = 0; j < 2; j++)
#pragma unroll
            for (int e = 0; e < 4; e++) c2c[i][j][e] = 0.f;
#pragma unroll
        for (int j = 0; j < 4; j++)
#pragma unroll
            for (int e = 0; e < 4; e++) { qw[i][j][e] = 0.f; kw[i][j][e] = 0.f; }
    }

    const int aRow = (lane & 15);
    const int aCol = (lane >> 4) * 8;
    const int bRow = (lane & 7);
    const int bCol = ((lane >> 3) & 1) * 8;

    auto mma_pass = [&](int p) {
#pragma unroll
        for (int ksp = 0; ksp < kKS; ksp += 16) {
            uint32_t aQ[2][4], aK[2][4];
#pragma unroll
            for (int fi = 0; fi < 2; fi++) {
                int r = wm * 32 + fi * 16 + aRow;
                ldmatrix_x4(aQ[fi], sQ + (uint32_t)(r * LDS + aCol + ksp) * 2);
                ldmatrix_x4(aK[fi], sK + (uint32_t)(r * LDS + aCol + ksp) * 2);
            }
            if (p == 0) {
                uint32_t bC[2][2];
#pragma unroll
                for (int fj = 0; fj < 2; fj++) {
                    int r = wn * 16 + fj * 8 + bRow;
                    ldmatrix_x2(bC[fj], sK + (uint32_t)(r * LDS + bCol + ksp) * 2);
                }
#pragma unroll
                for (int fi = 0; fi < 2; fi++)
#pragma unroll
                    for (int fj = 0; fj < 2; fj++)
                        mma_bf16(c2c[fi][fj], aQ[fi], bC[fj]);
            }
            uint32_t bPK[2][2], bPQ[2][2];
#pragma unroll
            for (int f2 = 0; f2 < 2; f2++) {
                int r = wn * 16 + f2 * 8 + bRow;   // local u row in 64-row buf
                ldmatrix_x2(bPK[f2], sPK + (uint32_t)(r * LDS + bCol + ksp) * 2);
                ldmatrix_x2(bPQ[f2], sPQ + (uint32_t)(r * LDS + bCol + ksp) * 2);
            }
#pragma unroll
            for (int fi = 0; fi < 2; fi++)
#pragma unroll
                for (int f2 = 0; f2 < 2; f2++) {
                    mma_bf16(qw[fi][p * 2 + f2], aQ[fi], bPK[f2]);
                    mma_bf16(kw[fi][p * 2 + f2], aK[fi], bPQ[f2]);
                }
        }
    };

    mma_pass(0);
    __syncthreads();   // window buffers reusable

    // stage pass 1: PK/PQ rows [64,128)
#pragma unroll
    for (int rh = 0; rh < 2; rh++) {
#pragma unroll
        for (int cc = 0; cc < 3; cc++) {
            int row = r0 + rh * 32, ch = c0 + cc * 8;
            uint32_t so = (uint32_t)(row * LDS + ch * 8) * 2;
            size_t  go = (size_t)(row + 64) * kKS + ch * 8;
            cp_async16(sPK + so, gpk + go);
            cp_async16(sPQ + so, gpq + go);
        }
    }
    CP_COMMIT();
    CP_WAIT(0);
    __syncthreads();

    mma_pass(1);

    __syncthreads();
    float* QWs = (float*)smem;                    // [64][132]
    float* KWs = QWs + 64 * QW_STRIDE;            // [64][132]
#pragma unroll
    for (int fi = 0; fi < 2; fi++) {
#pragma unroll
        for (int fu = 0; fu < 4; fu++) {
            int rl = wm * 32 + fi * 16 + (lane >> 2);
            int u  = (fu >> 1) * 64 + wn * 16 + (fu & 1) * 8 + (lane & 3) * 2;
            QWs[rl * QW_STRIDE + u]           = qw[fi][fu][0];
            QWs[rl * QW_STRIDE + u + 1]       = qw[fi][fu][1];
            QWs[(rl + 8) * QW_STRIDE + u]     = qw[fi][fu][2];
            QWs[(rl + 8) * QW_STRIDE + u + 1] = qw[fi][fu][3];
            KWs[rl * QW_STRIDE + u]           = kw[fi][fu][0];
            KWs[rl * QW_STRIDE + u + 1]       = kw[fi][fu][1];
            KWs[(rl + 8) * QW_STRIDE + u]     = kw[fi][fu][2];
            KWs[(rl + 8) * QW_STRIDE + u + 1] = kw[fi][fu][3];
        }
    }
    __syncthreads();

    const float sb_same  = same_bias[h];
    const float sb_cross = cross_bias[h];
    const float scale_h  = sep_scale[h];
    const float dx       = sep_decay[h];
    const float softp    = fmaxf(dx, 0.f) + log1pf(expf(-fabsf(dx)));
    const float decay    = softp + 1e-4f;
    const float inv      = 0.07216878364870322f;  // 1/sqrt(3*HD)

#pragma unroll
    for (int fi = 0; fi < 2; fi++) {
#pragma unroll
        for (int fj = 0; fj < 2; fj++) {
            int il0 = wm * 32 + fi * 16 + (lane >> 2);
            int jl0 = wn * 16 + fj * 8 + (lane & 3) * 2;
#pragma unroll
            for (int half = 0; half < 2; half++) {
                int il = il0 + half * 8;
                float raw0 = c2c[fi][fj][half * 2];
                float raw1 = c2c[fi][fj][half * 2 + 1];
                int   segi = s_segi[il];
                float sepi = s_sepi[il];
#pragma unroll
                for (int e = 0; e < 2; e++) {
                    int jl = jl0 + e;
                    int u  = il - jl + 63;
                    float val = ((e ? raw1 : raw0)
                                 + QWs[il * QW_STRIDE + u]
                                 + KWs[jl * QW_STRIDE + u]) * inv;
                    if (segi == s_segj[jl]) {
                        val += sb_same;
                    } else {
                        float gap = fabsf(sepi - s_sepj[jl]);
                        val += sb_cross + expf(-gap * decay) * scale_h;
                    }
                    if (s_maskj[jl] == 0) val = -9e15f;
                    logits[(((size_t)bh * kS) + i0 + il) * kS + j0 + jl] = val;
                }
            }
        }
    }
}

// ---------------------------------------------------------------------------
// Row softmax over S=384, writing hi/lo bf16 split probabilities.
// ---------------------------------------------------------------------------
__global__ __launch_bounds__(128) void softmax_bf16_kernel(
    const float* __restrict__ logits,
    unsigned short* __restrict__ ps, unsigned short* __restrict__ psl)
{
    const size_t row = blockIdx.x;
    const float* p = logits + row * kS;
    const int t = threadIdx.x;

    float v0 = p[t], v1 = p[t + 128], v2 = p[t + 256];
    float m = fmaxf(v0, fmaxf(v1, v2));

    __shared__ float red[4];
#pragma unroll
    for (int o = 16; o; o >>= 1) m = fmaxf(m, __shfl_xor_sync(0xffffffffu, m, o));
    if ((t & 31) == 0) red[t >> 5] = m;
    __syncthreads();
    m = fmaxf(fmaxf(red[0], red[1]), fmaxf(red[2], red[3]));

    float e0 = __expf(v0 - m), e1 = __expf(v1 - m), e2 = __expf(v2 - m);
    float s = e0 + e1 + e2;
#pragma unroll
    for (int o = 16; o; o >>= 1) s += __shfl_xor_sync(0xffffffffu, s, o);
    __shared__ float red2[4];
    if ((t & 31) == 0) red2[t >> 5] = s;
    __syncthreads();
    s = red2[0] + red2[1] + red2[2] + red2[3];

    float r = 1.f / s;
    float p0 = e0 * r, p1 = e1 * r, p2 = e2 * r;
    unsigned short* oh = ps  + row * kS;
    unsigned short* ol = psl + row * kS;
    __nv_bfloat16 h0 = __float2bfloat16_rn(p0);
    __nv_bfloat16 h1 = __float2bfloat16_rn(p1);
    __nv_bfloat16 h2 = __float2bfloat16_rn(p2);
    __nv_bfloat16 l0 = __float2bfloat16_rn(p0 - __bfloat162float(h0));
    __nv_bfloat16 l1 = __float2bfloat16_rn(p1 - __bfloat162float(h1));
    __nv_bfloat16 l2 = __float2bfloat16_rn(p2 - __bfloat162float(h2));
    oh[t]       = *(unsigned short*)&h0;
    oh[t + 128] = *(unsigned short*)&h1;
    oh[t + 256] = *(unsigned short*)&h2;
    ol[t]       = *(unsigned short*)&l0;
    ol[t + 128] = *(unsigned short*)&l1;
    ol[t + 256] = *(unsigned short*)&l2;
}

// ---------------------------------------------------------------------------
// Tensor AV: O[b,i,h*64+d] = sum_j P[bh,i,j] * V[bh,j,d]
// 3-term split per 64-j tile (K=192): A = [P_hi|P_hi|P_lo], B = V^T (hi|lo|hi).
// Epilogue writes O directly as the A-pattern bf16 split (hi|hi|lo, 2304-wide)
// consumed by the output-projection tgemm.
// ---------------------------------------------------------------------------
constexpr int LDP  = 392;   // P smem stride in halves (384 + 8)
constexpr int LDV  = 200;   // V smem stride in halves (192 + 8)
constexpr int AV_SMEM = 2 * 64 * LDP * 2 + 2 * 64 * LDV * 2;  // 100352+51200

__global__ __launch_bounds__(256) void av_mma_kernel(
    const unsigned short* __restrict__ ps, const unsigned short* __restrict__ psl,
    const unsigned short* __restrict__ vt,
    unsigned short* __restrict__ osplit)
{
    extern __shared__ __align__(16) char smem[];
    const uint32_t sPh = smem_to_u32(smem);
    const uint32_t sPl = sPh + 64 * LDP * 2;
    const uint32_t sV0 = sPl + 64 * LDP * 2;

    const int t = threadIdx.x, lane = t & 31, wid = t >> 5;
    const int wm = wid >> 2, wn = wid & 3;      // 2 x 4 warps
    const int bh = blockIdx.y, b = bh / kH, h = bh % kH;
    const int i0 = blockIdx.x * 64;

    {
        const unsigned short* gh = ps  + ((size_t)bh * kS + i0) * kS;
        const unsigned short* gl = psl + ((size_t)bh * kS + i0) * kS;
#pragma unroll
        for (int i = 0; i < 12; i++) {
            int idx = i * 256 + t;            // 0..3071
            int row = idx / 48, q = idx % 48;
            uint32_t so = (uint32_t)(row * LDP + q * 8) * 2;
            size_t  go = (size_t)row * kS + q * 8;
            cp_async16(sPh + so, gh + go);
            cp_async16(sPl + so, gl + go);
        }
    }
    auto stageV = [&](int jt) {
        const unsigned short* g = vt + (((size_t)bh * 6 + jt) * 64) * 192;
        const uint32_t dst = sV0 + (jt & 1) * 64 * LDV * 2;
#pragma unroll
        for (int i = 0; i < 6; i++) {
            int idx = i * 256 + t;            // 0..1535
            int row = idx / 24, ch = idx % 24;
            cp_async16(dst + (uint32_t)(row * LDV + ch * 8) * 2,
                       g + (size_t)row * 192 + ch * 8);
        }
    };
    stageV(0);
    CP_COMMIT();   // group 0: P + V0

    float d[2][2][4];
#pragma unroll
    for (int i = 0; i < 2; i++)
#pragma unroll
        for (int j = 0; j < 2; j++)
#pragma unroll
            for (int e = 0; e < 4; e++) d[i][j][e] = 0.f;

    const int aRow = lane & 15, aCol = (lane >> 4) * 8;
    const int bRow = lane & 7,  bCol = ((lane >> 3) & 1) * 8;

    for (int jt = 0; jt < 6; jt++) {
        if (jt + 1 < 6) { stageV(jt + 1); CP_COMMIT(); CP_WAIT(1); }
        else            { CP_WAIT(0); }
        __syncthreads();

        const uint32_t sV = sV0 + (jt & 1) * 64 * LDV * 2;

#pragma unroll
        for (int ksp = 0; ksp < 192; ksp += 16) {
            const uint32_t sPbuf = (ksp < 128) ? sPh : sPl;   // [hi|hi|lo]
            uint32_t a[2][4], bf[2][2];
#pragma unroll
            for (int fi = 0; fi < 2; fi++)
                ldmatrix_x4(a[fi], sPbuf + (uint32_t)((wm * 32 + fi * 16 + aRow) * LDP
                                                      + jt * 64 + (ksp & 63) + aCol) * 2);
#pragma unroll
            for (int fj = 0; fj < 2; fj++)
                ldmatrix_x2(bf[fj], sV + (uint32_t)((wn * 16 + fj * 8 + bRow) * LDV
                                                    + ksp + bCol) * 2);
#pragma unroll
            for (int fi = 0; fi < 2; fi++)
#pragma unroll
                for (int fj = 0; fj < 2; fj++)
                    mma_bf16(d[fi][fj], a[fi], bf[fj]);
        }
        __syncthreads();
    }

    // epilogue: write O as A-pattern split (hi|hi|lo) rows of g_ab
#pragma unroll
    for (int fi = 0; fi < 2; fi++) {
#pragma unroll
        for (int fj = 0; fj < 2; fj++) {
            int mm = i0 + wm * 32 + fi * 16 + (lane >> 2);
            int nn = h * 64 + wn * 16 + fj * 8 + (lane & 3) * 2;
            size_t row0 = (size_t)b * kS + mm;
            unsigned short* base0 = osplit + row0 * kK3 + nn;
            uint32_t hp, lp;
            split2_pack(d[fi][fj][0], d[fi][fj][1], hp, lp);
            *(uint32_t*)(base0)         = hp;
            *(uint32_t*)(base0 + 768)   = hp;
            *(uint32_t*)(base0 + 1536)  = lp;
            unsigned short* base1 = osplit + (row0 + 8) * kK3 + nn;
            split2_pack(d[fi][fj][2], d[fi][fj][3], hp, lp);
            *(uint32_t*)(base1)         = hp;
            *(uint32_t*)(base1 + 768)   = hp;
            *(uint32_t*)(base1 + 1536)  = lp;
        }
    }
}

// ---------------------------------------------------------------------------
// Launch
// ---------------------------------------------------------------------------
extern "C" void kernel_launch(void* const* d_in, const int* in_sizes, int n_in,
                              void* d_out, int out_size)
{
    const float* x    = (const float*)d_in[0];
    const int*   mask = (const int*)d_in[1];
    const int*   seg  = (const int*)d_in[2];
    const float* sep  = (const float*)d_in[3];
    const float* Wq   = (const float*)d_in[4];
    const float* bq   = (const float*)d_in[5];
    const float* Wk   = (const float*)d_in[6];
    const float* bk   = (const float*)d_in[7];
    const float* Wv   = (const float*)d_in[8];
    const float* bv   = (const float*)d_in[9];
    const float* rel  = (const float*)d_in[10];
    const float* Wpk  = (const float*)d_in[11];
    const float* bpk  = (const float*)d_in[12];
    const float* Wpq  = (const float*)d_in[13];
    const float* bpq  = (const float*)d_in[14];
    const float* same_b  = (const float*)d_in[15];
    const float* cross_b = (const float*)d_in[16];
    const float* sscale  = (const float*)d_in[17];
    const float* sdecay  = (const float*)d_in[18];
    const float* Wo   = (const float*)d_in[19];
    const float* bo   = (const float*)d_in[20];
    float* out = (float*)d_out;

    float *v_, *lg_;
    unsigned short *ab_, *wqkv_, *apos_, *wpos_, *qs_, *ks_, *pks_, *pqs_, *vt_, *ps_, *psl_;
    cudaGetSymbolAddress((void**)&v_,  g_v);
    cudaGetSymbolAddress((void**)&lg_, g_logits);
    cudaGetSymbolAddress((void**)&ab_,   g_ab);
    cudaGetSymbolAddress((void**)&wqkv_, g_wqkv);
    cudaGetSymbolAddress((void**)&apos_, g_apos);
    cudaGetSymbolAddress((void**)&wpos_, g_wpos);
    cudaGetSymbolAddress((void**)&qs_,  g_qs);
    cudaGetSymbolAddress((void**)&ks_,  g_ks);
    cudaGetSymbolAddress((void**)&pks_, g_pks);
    cudaGetSymbolAddress((void**)&pqs_, g_pqs);
    cudaGetSymbolAddress((void**)&vt_,  g_vt);
    cudaGetSymbolAddress((void**)&ps_,  g_ps);
    cudaGetSymbolAddress((void**)&psl_, g_psl);

    cudaFuncSetAttribute(tgemm_kernel,
                         cudaFuncAttributeMaxDynamicSharedMemorySize,
                         TGEMM_SMEM);
    cudaFuncSetAttribute(tgemm_dual_kernel,
                         cudaFuncAttributeMaxDynamicSharedMemorySize,
                         TGEMM_SMEM);
    cudaFuncSetAttribute(logits_mma_kernel,
                         cudaFuncAttributeMaxDynamicSharedMemorySize,
                         LOGMMA_SMEM);
    cudaFuncSetAttribute(av_mma_kernel,
                         cudaFuncAttributeMaxDynamicSharedMemorySize,
                         AV_SMEM);

    const int kq = kD / 4;  // 192

    // 1) operand splits (fp32 -> bf16 hi/lo, K-concat, duplicated-hi layout)
    split_a_kernel<<<(3072 * kq + 255) / 256, 256>>>(x, ab_, 3072, 3072, kD);
    split_w_kernel<<<(2304 * kq + 255) / 256, 256>>>(Wq, Wk, Wv, wqkv_, 3, kD);
    split_a_kernel<<<(768 * kq + 255) / 256, 256>>>(rel + (size_t)128 * kD, apos_, kR, 768, kD);
    split_w_kernel<<<(1536 * kq + 255) / 256, 256>>>(Wpk, Wpq, Wpq, wpos_, 2, kD);

    // 2) QKV + POS projections, merged into one launch (504 blocks)
    tgemm_dual_kernel<<<504, 256, TGEMM_SMEM>>>(
        (const __nv_bfloat16*)ab_, (const __nv_bfloat16*)wqkv_,
        bq, bk, bv, v_, qs_, ks_,
        (const __nv_bfloat16*)apos_, (const __nv_bfloat16*)wpos_,
        bpk, bpq, pks_, pqs_);

    // 2b) V transpose + split for tensor AV
    vtrans_kernel<<<dim3(6, 96), 256>>>(v_, vt_);

    // 3) fused banded-MMA logits + segment bias + mask (two-pass, 2 CTA/SM)
    dim3 glog(kS / 64, kS / 64, kB * kH);
    logits_mma_kernel<<<glog, 256, LOGMMA_SMEM>>>(
        qs_, ks_, pks_, pqs_, mask, seg, sep,
        same_b, cross_b, sscale, sdecay, lg_);

    // 4) softmax -> hi/lo bf16 probabilities
    softmax_bf16_kernel<<<kB * kH * kS, 128>>>(lg_, ps_, psl_);

    // 5) split Wo (independent of softmax/AV stream order)
    split_w_kernel<<<(768 * kq + 255) / 256, 256>>>(Wo, Wo, Wo, wpos_, 1, kE);

    // 6) tensor AV: P @ V -> A-pattern split rows directly into ab_
    av_mma_kernel<<<dim3(6, 96), 256, AV_SMEM>>>(ps_, psl_, vt_, ab_);

    // 7) Output projection (A operand = av output split, already in ab_)
    tgemm_kernel<<<dim3(6, 24), 256, TGEMM_SMEM>>>(
        (const __nv_bfloat16*)ab_, (const __nv_bfloat16*)wpos_, 3072, bo, out);
}

// round 16
// speedup vs baseline: 1.2168x; 1.0480x over previous
#include <cuda_runtime.h>
#include <cuda_bf16.h>
#include <math.h>
#include <stdint.h>

// Problem constants
constexpr int kB  = 8;
constexpr int kS  = 384;
constexpr int kD  = 768;
constexpr int kE  = 768;
constexpr int kH  = 12;
constexpr int kHD = 64;
constexpr int kR  = 2 * kS - 1;   // 767 distinct relative positions actually used
constexpr int kK3 = 3 * kD;       // 2304: bf16-split concatenated K
constexpr int kKS = 192;          // 3*64: split head-dim for logits MMA

// ---------------------------------------------------------------------------
// Scratch (device globals; no runtime allocation allowed)
// ---------------------------------------------------------------------------
__device__ float g_v[kB * kH * kS * kHD];               // [B,H,S,HD] fp32
__device__ float g_logits[(size_t)kB * kH * kS * kS];   // [B,H,S,S]

// bf16-split operand buffers for projections (duplicated-hi layout)
__device__ unsigned short g_ab[3072 * kK3];      // A-split: x, then AV output
__device__ unsigned short g_wqkv[2304 * kK3];    // [Wq|Wk|Wv] split
__device__ unsigned short g_apos[768 * kK3];     // rel rows split (padded to 768)
__device__ unsigned short g_wpos[1536 * kK3];    // [Wpk|Wpq] split; reused for Wo

// bf16-split logits operands (written by tgemm epilogues)
__device__ unsigned short g_qs[96 * kS * kKS];   // [bh][s][192] pattern A (hi,hi,lo)
__device__ unsigned short g_ks[96 * kS * kKS];   // [bh][s][192] pattern B (hi,lo,hi)
__device__ unsigned short g_pks[kH * 768 * kKS]; // [h][r][192]  pattern B
__device__ unsigned short g_pqs[kH * 768 * kKS]; // [h][r][192]  pattern A

// attention probabilities, hi/lo bf16 split: [bh][i][384] each
__device__ unsigned short g_ps [(size_t)96 * kS * kS];
__device__ unsigned short g_psl[(size_t)96 * kS * kS];
// transposed split V for tensor AV: [bh][jt][d][192] pattern B (hi|lo|hi)
__device__ unsigned short g_vt[96 * 6 * 64 * 192];

// ---------------------------------------------------------------------------
// PTX helpers (target-independent: cp.async, ldmatrix, mma.sync — sm_80+)
// ---------------------------------------------------------------------------
__device__ __forceinline__ uint32_t smem_to_u32(const void* p) {
    uint32_t a;
    asm("{ .reg .u64 t; cvta.to.shared.u64 t, %1; cvt.u32.u64 %0, t; }"
        : "=r"(a) : "l"(p));
    return a;
}

__device__ __forceinline__ void cp_async16(uint32_t saddr, const void* gptr) {
    asm volatile("cp.async.cg.shared.global [%0], [%1], 16;\n"
                 :: "r"(saddr), "l"(gptr));
}
#define CP_COMMIT()  asm volatile("cp.async.commit_group;\n" ::: "memory")
#define CP_WAIT(n)   asm volatile("cp.async.wait_group %0;\n" :: "n"(n) : "memory")

__device__ __forceinline__ void ldmatrix_x4(uint32_t* r, uint32_t addr) {
    asm volatile("ldmatrix.sync.aligned.m8n8.x4.shared.b16 {%0,%1,%2,%3}, [%4];"
                 : "=r"(r[0]), "=r"(r[1]), "=r"(r[2]), "=r"(r[3]) : "r"(addr));
}
__device__ __forceinline__ void ldmatrix_x2(uint32_t* r, uint32_t addr) {
    asm volatile("ldmatrix.sync.aligned.m8n8.x2.shared.b16 {%0,%1}, [%2];"
                 : "=r"(r[0]), "=r"(r[1]) : "r"(addr));
}

__device__ __forceinline__ void mma_bf16(float* d, const uint32_t* a, const uint32_t* b) {
    asm volatile(
        "mma.sync.aligned.m16n8k16.row.col.f32.bf16.bf16.f32 "
        "{%0,%1,%2,%3}, {%4,%5,%6,%7}, {%8,%9}, {%0,%1,%2,%3};"
        : "+f"(d[0]), "+f"(d[1]), "+f"(d[2]), "+f"(d[3])
        : "r"(a[0]), "r"(a[1]), "r"(a[2]), "r"(a[3]),
          "r"(b[0]), "r"(b[1]));
}

// ---------------------------------------------------------------------------
// fp32 -> bf16 hi/lo split conversion kernels (duplicated-hi layouts)
// A pattern:  out[m, 0:K]=hi, [K:2K]=hi, [2K:3K]=lo
// W pattern:  out[n, 0:K]=hi, [K:2K]=lo, [2K:3K]=hi
// ---------------------------------------------------------------------------
union BF4 { __nv_bfloat16 h[4]; uint2 u; };

__device__ __forceinline__ void split4(float4 a, uint2& hi, uint2& lo)
{
    float v[4] = {a.x, a.y, a.z, a.w};
    BF4 H, L;
#pragma unroll
    for (int i = 0; i < 4; i++) {
        __nv_bfloat16 h1 = __float2bfloat16_rn(v[i]);
        float res = v[i] - __bfloat162float(h1);
        H.h[i] = h1;
        L.h[i] = __float2bfloat16_rn(res);
    }
    hi = H.u; lo = L.u;
}

__device__ __forceinline__ void split2_pack(float v0, float v1,
                                            uint32_t& hp, uint32_t& lp)
{
    __nv_bfloat16 h0 = __float2bfloat16_rn(v0), h1 = __float2bfloat16_rn(v1);
    float r0 = v0 - __bfloat162float(h0), r1 = v1 - __bfloat162float(h1);
    __nv_bfloat16 l0 = __float2bfloat16_rn(r0), l1 = __float2bfloat16_rn(r1);
    hp = (uint32_t)*(unsigned short*)&h0 | ((uint32_t)*(unsigned short*)&h1 << 16);
    lp = (uint32_t)*(unsigned short*)&l0 | ((uint32_t)*(unsigned short*)&l1 << 16);
}

__global__ __launch_bounds__(256) void split_a_kernel(
    const float* __restrict__ A, unsigned short* __restrict__ out,
    int Msrc, int Mpad, int K)
{
    int idx = blockIdx.x * 256 + threadIdx.x;
    int kq = K >> 2;
    if (idx >= Mpad * kq) return;
    int m = idx / kq;
    int c4 = (idx - m * kq) << 2;
    float4 a = (m < Msrc) ? *(const float4*)(A + (size_t)m * K + c4)
                          : make_float4(0.f, 0.f, 0.f, 0.f);
    uint2 hi, lo; split4(a, hi, lo);
    size_t base = (size_t)m * 3 * K + c4;
    *(uint2*)(out + base)         = hi;
    *(uint2*)(out + base + K)     = hi;
    *(uint2*)(out + base + 2 * K) = lo;
}

__global__ __launch_bounds__(256) void split_w_kernel(
    const float* __restrict__ W0, const float* __restrict__ W1,
    const float* __restrict__ W2, unsigned short* __restrict__ out,
    int nsrc, int K)
{
    int idx = blockIdx.x * 256 + threadIdx.x;
    int kq = K >> 2;
    int rows = nsrc * 768;
    if (idx >= rows * kq) return;
    int rr = idx / kq;
    int c4 = (idx - rr * kq) << 2;
    int s = rr / 768, r = rr - s * 768;
    const float* W = (s == 0) ? W0 : (s == 1) ? W1 : W2;
    float4 a = *(const float4*)(W + (size_t)r * K + c4);
    uint2 hi, lo; split4(a, hi, lo);
    size_t base = (size_t)rr * 3 * K + c4;
    *(uint2*)(out + base)         = hi;
    *(uint2*)(out + base + K)     = lo;
    *(uint2*)(out + base + 2 * K) = hi;
}

// ---------------------------------------------------------------------------
// bf16 HMMA GEMM body (projections). 128x128 CTA tile, BK=64, 256 threads.
// mode 0: QKV   n<768 -> q split(A-pat), n<1536 -> k split(B-pat), else v fp32
// mode 1: POS   n<768 -> pk split(B-pat), else pq split(A-pat)
// mode 2: plain fp32 C[m*768+n]
// ---------------------------------------------------------------------------
constexpr int BK   = 64;
constexpr int LDT  = 72;                       // smem stride in halves (pad 8)
constexpr int TBUF = 128 * LDT * 2;            // bytes per tile buffer
constexpr int TGEMM_SMEM = 4 * TBUF;           // A0,B0,A1,B1 = 73728

__device__ __forceinline__ void store_split_pair(
    unsigned short* base, float v0, float v1, bool patA)
{
    uint32_t hp, lp;
    split2_pack(v0, v1, hp, lp);
    *(uint32_t*)(base)       = hp;
    *(uint32_t*)(base + 64)  = patA ? hp : lp;
    *(uint32_t*)(base + 128) = patA ? lp : hp;
}

__device__ __forceinline__ void store_pair(
    int mode, int Msrc, int mrow, int n, float v0, float v1,
    const float* __restrict__ b0, const float* __restrict__ b1,
    const float* __restrict__ b2,
    float* __restrict__ o0,
    unsigned short* __restrict__ s0, unsigned short* __restrict__ s1)
{
    if (mrow >= Msrc) return;
    if (mode == 2) {
        float2 w = make_float2(v0 + b0[n], v1 + b0[n + 1]);
        *(float2*)&o0[(size_t)mrow * 768 + n] = w;
        return;
    }
    int which = n / 768;
    int e = n - which * 768;
    int h = e >> 6, hd = e & 63;
    const float* bp = (which == 0) ? b0 : (which == 1) ? b1 : b2;
    float w0 = v0 + bp[e], w1 = v1 + bp[e + 1];
    if (mode == 0) {
        int bi = mrow / kS, s = mrow - bi * kS;
        if (which == 2) {
            *(float2*)&o0[((((size_t)bi * kH) + h) * kS + s) * (size_t)kHD + hd]
                = make_float2(w0, w1);
        } else {
            unsigned short* base = ((which == 0) ? s0 : s1)
                + (((size_t)(bi * kH + h) * kS) + s) * kKS + hd;
            store_split_pair(base, w0, w1, which == 0);  // q: A-pat, k: B-pat
        }
    } else {  // mode 1: pk (B-pat), pq (A-pat)
        unsigned short* base = ((which == 0) ? s0 : s1)
            + (((size_t)h * 768) + mrow) * kKS + hd;
        store_split_pair(base, w0, w1, which == 1);
    }
}

__device__ __forceinline__ void tgemm_body(
    const __nv_bfloat16* __restrict__ A, const __nv_bfloat16* __restrict__ B,
    int Msrc,
    const float* __restrict__ bias0, const float* __restrict__ bias1,
    const float* __restrict__ bias2,
    float* __restrict__ out0,
    unsigned short* __restrict__ s0, unsigned short* __restrict__ s1,
    int mode, int m0, int n0, char* smem)
{
    const uint32_t sbase = smem_to_u32(smem);

    const int t = threadIdx.x, lane = t & 31, wid = t >> 5;
    const int warp_m = wid & 1, warp_n = wid >> 1;   // 2 x 4

    const __nv_bfloat16* Ag = A + (size_t)m0 * kK3;
    const __nv_bfloat16* Bg = B + (size_t)n0 * kK3;
    const int NC = kK3 / BK;

    const int lrow = t >> 3;
    const int lc8  = (t & 7) * 8;

    auto issue = [&](int c) {
        const int buf = c & 1;
        const uint32_t dA = sbase + buf * 2 * TBUF;
        const uint32_t dB = dA + TBUF;
        const __nv_bfloat16* Ak = Ag + (size_t)c * BK;
        const __nv_bfloat16* Bk = Bg + (size_t)c * BK;
#pragma unroll
        for (int it = 0; it < 4; it++) {
            int r = lrow + it * 32;
            uint32_t so = (uint32_t)(r * LDT + lc8) * 2;
            cp_async16(dA + so, Ak + (size_t)r * kK3 + lc8);
            cp_async16(dB + so, Bk + (size_t)r * kK3 + lc8);
        }
        CP_COMMIT();
    };

    float d[4][4][4];
#pragma unroll
    for (int i = 0; i < 4; i++)
#pragma unroll
        for (int j = 0; j < 4; j++)
#pragma unroll
            for (int e = 0; e < 4; e++) d[i][j][e] = 0.f;

    const int a_row = warp_m * 64 + (lane & 15);
    const int a_col = (lane >> 4) * 8;
    const int b_row = warp_n * 32 + (lane & 7);
    const int b_col = ((lane >> 3) & 1) * 8;

    issue(0);

    for (int c = 0; c < NC; c++) {
        if (c + 1 < NC) { issue(c + 1); CP_WAIT(1); }
        else           { CP_WAIT(0); }
        __syncthreads();

        const int buf = c & 1;
        const uint32_t sA = sbase + buf * 2 * TBUF;
        const uint32_t sB = sA + TBUF;

#pragma unroll
        for (int ks = 0; ks < BK; ks += 16) {
            uint32_t a[4][4], b[4][2];
#pragma unroll
            for (int i = 0; i < 4; i++)
                ldmatrix_x4(a[i], sA + (uint32_t)((a_row + i * 16) * LDT + a_col + ks) * 2);
#pragma unroll
            for (int j = 0; j < 4; j++)
                ldmatrix_x2(b[j], sB + (uint32_t)((b_row + j * 8) * LDT + b_col + ks) * 2);
#pragma unroll
            for (int i = 0; i < 4; i++)
#pragma unroll
                for (int j = 0; j < 4; j++)
                    mma_bf16(d[i][j], a[i], b[j]);
        }
        __syncthreads();
    }

    const int mbase = m0 + warp_m * 64 + (lane >> 2);
    const int nbase = n0 + warp_n * 32 + (lane & 3) * 2;
#pragma unroll
    for (int i = 0; i < 4; i++) {
#pragma unroll
        for (int j = 0; j < 4; j++) {
            int mm = mbase + i * 16;
            int nn = nbase + j * 8;
            store_pair(mode, Msrc, mm,     nn, d[i][j][0], d[i][j][1],
                       bias0, bias1, bias2, out0, s0, s1);
            store_pair(mode, Msrc, mm + 8, nn, d[i][j][2], d[i][j][3],
                       bias0, bias1, bias2, out0, s0, s1);
        }
    }
}

// Plain entry (used for the output projection, mode 2)
__global__ __launch_bounds__(256) void tgemm_kernel(
    const __nv_bfloat16* __restrict__ A, const __nv_bfloat16* __restrict__ B,
    int Msrc,
    const float* __restrict__ bias0,
    float* __restrict__ out0)
{
    extern __shared__ __align__(16) char smem[];
    tgemm_body(A, B, Msrc, bias0, nullptr, nullptr, out0, nullptr, nullptr,
               2, blockIdx.y * 128, blockIdx.x * 128, smem);
}

// Merged QKV + POS entry: flat grid of 432 + 72 = 504 blocks.
__global__ __launch_bounds__(256) void tgemm_dual_kernel(
    const __nv_bfloat16* __restrict__ Aq, const __nv_bfloat16* __restrict__ Bq,
    const float* __restrict__ bq, const float* __restrict__ bk,
    const float* __restrict__ bv,
    float* __restrict__ v_out,
    unsigned short* __restrict__ qs, unsigned short* __restrict__ ks,
    const __nv_bfloat16* __restrict__ Ap, const __nv_bfloat16* __restrict__ Bp,
    const float* __restrict__ bpk, const float* __restrict__ bpq,
    unsigned short* __restrict__ pks, unsigned short* __restrict__ pqs)
{
    extern __shared__ __align__(16) char smem[];
    const int bx = blockIdx.x;
    if (bx < 432) {
        int m0 = (bx / 18) * 128, n0 = (bx % 18) * 128;
        tgemm_body(Aq, Bq, 3072, bq, bk, bv, v_out, qs, ks, 0, m0, n0, smem);
    } else {
        int i = bx - 432;
        int m0 = (i / 12) * 128, n0 = (i % 12) * 128;
        tgemm_body(Ap, Bp, kR, bpk, bpq, nullptr, nullptr, pks, pqs, 1, m0, n0, smem);
    }
}

// ---------------------------------------------------------------------------
// V transpose + split: g_v [bh][s][64] fp32 -> g_vt [bh][jt][d][192] (hi|lo|hi)
// ---------------------------------------------------------------------------
__global__ __launch_bounds__(256) void vtrans_kernel(
    const float* __restrict__ v, unsigned short* __restrict__ vt)
{
    __shared__ float tile[64][65];
    const int bh = blockIdx.y, jt = blockIdx.x;
    const int t = threadIdx.x;
    const float* src = v + ((size_t)bh * kS + jt * 64) * kHD;

#pragma unroll
    for (int i = 0; i < 16; i++) {
        int idx = i * 256 + t;
        tile[idx >> 6][idx & 63] = src[idx];
    }
    __syncthreads();

    unsigned short* dst = vt + (((size_t)bh * 6 + jt) * 64) * 192;
#pragma unroll
    for (int i = 0; i < 8; i++) {
        int idx = i * 256 + t;            // 0..2047
        int dd  = idx >> 5;               // d row
        int jp  = (idx & 31) * 2;         // j pair
        uint32_t hp, lp;
        split2_pack(tile[jp][dd], tile[jp + 1][dd], hp, lp);
        unsigned short* base = dst + (size_t)dd * 192 + jp;
        *(uint32_t*)(base)       = hp;    // pattern B: hi, lo, hi
        *(uint32_t*)(base + 64)  = lp;
        *(uint32_t*)(base + 128) = hp;
    }
}

// ---------------------------------------------------------------------------
// Fused banded-MMA logits kernel — two-pass window variant (round-15 winner).
// ---------------------------------------------------------------------------
constexpr int LDS = 200;  // smem stride in halves for all operand tiles
constexpr int LOGMMA_SMEM = 4 * 64 * LDS * 2;  // 102400 B
constexpr int QW_STRIDE = 132;

__global__ __launch_bounds__(256, 2) void logits_mma_kernel(
    const unsigned short* __restrict__ qs, const unsigned short* __restrict__ ks,
    const unsigned short* __restrict__ pks, const unsigned short* __restrict__ pqs,
    const int* __restrict__ mask, const int* __restrict__ seg,
    const float* __restrict__ sep,
    const float* __restrict__ same_bias, const float* __restrict__ cross_bias,
    const float* __restrict__ sep_scale, const float* __restrict__ sep_decay,
    float* __restrict__ logits)
{
    extern __shared__ __align__(16) char smem[];
    const uint32_t sb = smem_to_u32(smem);

    __shared__ int   s_segi[64], s_segj[64], s_maskj[64];
    __shared__ float s_sepi[64], s_sepj[64];

    const int t = threadIdx.x, lane = t & 31, wid = t >> 5;
    const int wm = wid >> 2, wn = wid & 3;          // 2 x 4 warps
    const int bh = blockIdx.z, b = bh / kH, h = bh % kH;
    const int i0 = blockIdx.y * 64, j0 = blockIdx.x * 64;
    const int rb = i0 - j0 + 320;                   // window base: r = rb + u

    const uint32_t sQ  = sb;
    const uint32_t sK  = sQ + 64 * LDS * 2;
    const uint32_t sPK = sK + 64 * LDS * 2;         // 64-row window buffer
    const uint32_t sPQ = sPK + 64 * LDS * 2;        // 64-row window buffer

    if (t < 64) {
        s_segi[t] = seg[b * kS + i0 + t];
        s_sepi[t] = fabsf(sep[b * kS + i0 + t]);
    } else if (t < 128) {
        int u = t - 64;
        s_segj[u]  = seg[b * kS + j0 + u];
        s_sepj[u]  = fabsf(sep[b * kS + j0 + u]);
        s_maskj[u] = mask[b * kS + j0 + u];
    }

    const unsigned short* gq  = qs  + ((size_t)bh * kS + i0) * kKS;
    const unsigned short* gk  = ks  + ((size_t)bh * kS + j0) * kKS;
    const unsigned short* gpk = pks + ((size_t)h * 768 + rb) * kKS;
    const unsigned short* gpq = pqs + ((size_t)h * 768 + rb) * kKS;
    const int r0 = t >> 3;
    const int c0 = (t & 7);

    // stage pass 0: Q, K + PK/PQ rows [0,64)
#pragma unroll
    for (int rh = 0; rh < 2; rh++) {
#pragma unroll
        for (int cc = 0; cc < 3; cc++) {
            int row = r0 + rh * 32, ch = c0 + cc * 8;
            uint32_t so = (uint32_t)(row * LDS + ch * 8) * 2;
            size_t  go = (size_t)row * kKS + ch * 8;
            cp_async16(sQ + so,  gq + go);
            cp_async16(sK + so,  gk + go);
            cp_async16(sPK + so, gpk + go);
            cp_async16(sPQ + so, gpq + go);
        }
    }
    CP_COMMIT();
    CP_WAIT(0);
    __syncthreads();

    float c2c[2][2][4], qw[2][4][4], kw[2][4][4];
#pragma unroll
    for (int i = 0; i < 2; i++) {
#pragma unroll
        for (int j = 0; j < 2; j++)
#pragma unroll
            for (int e = 0; e < 4; e++) c2c[i][j][e] = 0.f;
#pragma unroll
        for (int j = 0; j < 4; j++)
#pragma unroll
            for (int e = 0; e < 4; e++) { qw[i][j][e] = 0.f; kw[i][j][e] = 0.f; }
    }

    const int aRow = (lane & 15);
    const int aCol = (lane >> 4) * 8;
    const int bRow = (lane & 7);
    const int bCol = ((lane >> 3) & 1) * 8;

    auto mma_pass = [&](int p) {
#pragma unroll
        for (int ksp = 0; ksp < kKS; ksp += 16) {
            uint32_t aQ[2][4], aK[2][4];
#pragma unroll
            for (int fi = 0; fi < 2; fi++) {
                int r = wm * 32 + fi * 16 + aRow;
                ldmatrix_x4(aQ[fi], sQ + (uint32_t)(r * LDS + aCol + ksp) * 2);
                ldmatrix_x4(aK[fi], sK + (uint32_t)(r * LDS + aCol + ksp) * 2);
            }
            if (p == 0) {
                uint32_t bC[2][2];
#pragma unroll
                for (int fj = 0; fj < 2; fj++) {
                    int r = wn * 16 + fj * 8 + bRow;
                    ldmatrix_x2(bC[fj], sK + (uint32_t)(r * LDS + bCol + ksp) * 2);
                }
#pragma unroll
                for (int fi = 0; fi < 2; fi++)
#pragma unroll
                    for (int fj = 0; fj < 2; fj++)
                        mma_bf16(c2c[fi][fj], aQ[fi], bC[fj]);
            }
            uint32_t bPK[2][2], bPQ[2][2];
#pragma unroll
            for (int f2 = 0; f2 < 2; f2++) {
                int r = wn * 16 + f2 * 8 + bRow;   // local u row in 64-row buf
                ldmatrix_x2(bPK[f2], sPK + (uint32_t)(r * LDS + bCol + ksp) * 2);
                ldmatrix_x2(bPQ[f2], sPQ + (uint32_t)(r * LDS + bCol + ksp) * 2);
            }
#pragma unroll
            for (int fi = 0; fi < 2; fi++)
#pragma unroll
                for (int f2 = 0; f2 < 2; f2++) {
                    mma_bf16(qw[fi][p * 2 + f2], aQ[fi], bPK[f2]);
                    mma_bf16(kw[fi][p * 2 + f2], aK[fi], bPQ[f2]);
                }
        }
    };

    mma_pass(0);
    __syncthreads();   // window buffers reusable

    // stage pass 1: PK/PQ rows [64,128)
#pragma unroll
    for (int rh = 0; rh < 2; rh++) {
#pragma unroll
        for (int cc = 0; cc < 3; cc++) {
            int row = r0 + rh * 32, ch = c0 + cc * 8;
            uint32_t so = (uint32_t)(row * LDS + ch * 8) * 2;
            size_t  go = (size_t)(row + 64) * kKS + ch * 8;
            cp_async16(sPK + so, gpk + go);
            cp_async16(sPQ + so, gpq + go);
        }
    }
    CP_COMMIT();
    CP_WAIT(0);
    __syncthreads();

    mma_pass(1);

    __syncthreads();
    float* QWs = (float*)smem;                    // [64][132]
    float* KWs = QWs + 64 * QW_STRIDE;            // [64][132]
#pragma unroll
    for (int fi = 0; fi < 2; fi++) {
#pragma unroll
        for (int fu = 0; fu < 4; fu++) {
            int rl = wm * 32 + fi * 16 + (lane >> 2);
            int u  = (fu >> 1) * 64 + wn * 16 + (fu & 1) * 8 + (lane & 3) * 2;
            QWs[rl * QW_STRIDE + u]           = qw[fi][fu][0];
            QWs[rl * QW_STRIDE + u + 1]       = qw[fi][fu][1];
            QWs[(rl + 8) * QW_STRIDE + u]     = qw[fi][fu][2];
            QWs[(rl + 8) * QW_STRIDE + u + 1] = qw[fi][fu][3];
            KWs[rl * QW_STRIDE + u]           = kw[fi][fu][0];
            KWs[rl * QW_STRIDE + u + 1]       = kw[fi][fu][1];
            KWs[(rl + 8) * QW_STRIDE + u]     = kw[fi][fu][2];
            KWs[(rl + 8) * QW_STRIDE + u + 1] = kw[fi][fu][3];
        }
    }
    __syncthreads();

    const float sb_same  = same_bias[h];
    const float sb_cross = cross_bias[h];
    const float scale_h  = sep_scale[h];
    const float dx       = sep_decay[h];
    const float softp    = fmaxf(dx, 0.f) + log1pf(expf(-fabsf(dx)));
    const float decay    = softp + 1e-4f;
    const float inv      = 0.07216878364870322f;  // 1/sqrt(3*HD)

#pragma unroll
    for (int fi = 0; fi < 2; fi++) {
#pragma unroll
        for (int fj = 0; fj < 2; fj++) {
            int il0 = wm * 32 + fi * 16 + (lane >> 2);
            int jl0 = wn * 16 + fj * 8 + (lane & 3) * 2;
#pragma unroll
            for (int half = 0; half < 2; half++) {
                int il = il0 + half * 8;
                float raw0 = c2c[fi][fj][half * 2];
                float raw1 = c2c[fi][fj][half * 2 + 1];
                int   segi = s_segi[il];
                float sepi = s_sepi[il];
#pragma unroll
                for (int e = 0; e < 2; e++) {
                    int jl = jl0 + e;
                    int u  = il - jl + 63;
                    float val = ((e ? raw1 : raw0)
                                 + QWs[il * QW_STRIDE + u]
                                 + KWs[jl * QW_STRIDE + u]) * inv;
                    if (segi == s_segj[jl]) {
                        val += sb_same;
                    } else {
                        float gap = fabsf(sepi - s_sepj[jl]);
                        val += sb_cross + expf(-gap * decay) * scale_h;
                    }
                    if (s_maskj[jl] == 0) val = -9e15f;
                    logits[(((size_t)bh * kS) + i0 + il) * kS + j0 + jl] = val;
                }
            }
        }
    }
}

// ---------------------------------------------------------------------------
// Row softmax, one WARP per row (8 rows / 256-thread block), shuffle-only
// reductions, writing hi/lo bf16 split probabilities.
// ---------------------------------------------------------------------------
__global__ __launch_bounds__(256) void softmax_bf16_kernel(
    const float* __restrict__ logits,
    unsigned short* __restrict__ ps, unsigned short* __restrict__ psl)
{
    const int lane = threadIdx.x & 31, w = threadIdx.x >> 5;
    const size_t row = (size_t)blockIdx.x * 8 + w;
    const float* p = logits + row * kS;

    float4 v[3];
#pragma unroll
    for (int c = 0; c < 3; c++)
        v[c] = *(const float4*)(p + (c * 32 + lane) * 4);

    float m = -INFINITY;
#pragma unroll
    for (int c = 0; c < 3; c++)
        m = fmaxf(m, fmaxf(fmaxf(v[c].x, v[c].y), fmaxf(v[c].z, v[c].w)));
#pragma unroll
    for (int o = 16; o; o >>= 1) m = fmaxf(m, __shfl_xor_sync(0xffffffffu, m, o));

    float e[3][4];
    float s = 0.f;
#pragma unroll
    for (int c = 0; c < 3; c++) {
        e[c][0] = __expf(v[c].x - m); e[c][1] = __expf(v[c].y - m);
        e[c][2] = __expf(v[c].z - m); e[c][3] = __expf(v[c].w - m);
        s += e[c][0] + e[c][1] + e[c][2] + e[c][3];
    }
#pragma unroll
    for (int o = 16; o; o >>= 1) s += __shfl_xor_sync(0xffffffffu, s, o);
    const float r = 1.f / s;

    unsigned short* oh = ps  + row * kS;
    unsigned short* ol = psl + row * kS;
#pragma unroll
    for (int c = 0; c < 3; c++) {
        uint32_t h01, l01, h23, l23;
        split2_pack(e[c][0] * r, e[c][1] * r, h01, l01);
        split2_pack(e[c][2] * r, e[c][3] * r, h23, l23);
        int off = (c * 32 + lane) * 4;
        *(uint2*)(oh + off) = make_uint2(h01, h23);
        *(uint2*)(ol + off) = make_uint2(l01, l23);
    }
}

// ---------------------------------------------------------------------------
// Tensor AV: O[b,i,h*64+d] = sum_j P[bh,i,j] * V[bh,j,d]
// 3-term split per 64-j tile (K=192): A = [P_hi|P_hi|P_lo], B = V^T (hi|lo|hi).
// P staged PER j-tile (64x64 hi+lo) inside the V double-buffer pipeline:
// smem 151.5 -> 86 KB -> 2 CTAs/SM. Per-jt accumulation order unchanged.
// Epilogue writes O directly as the A-pattern bf16 split (hi|hi|lo).
// ---------------------------------------------------------------------------
constexpr int LDP  = 72;    // P tile stride in halves (64 + 8)
constexpr int LDV  = 200;   // V smem stride in halves (192 + 8)
constexpr int PBUF = 64 * LDP * 2;              // 9216 B (one of hi/lo)
constexpr int AVSTAGE = 2 * PBUF + 64 * LDV * 2; // 18432 + 25600 = 44032
constexpr int AV_SMEM = 2 * AVSTAGE;             // 88064 B

__global__ __launch_bounds__(256, 2) void av_mma_kernel(
    const unsigned short* __restrict__ ps, const unsigned short* __restrict__ psl,
    const unsigned short* __restrict__ vt,
    unsigned short* __restrict__ osplit)
{
    extern __shared__ __align__(16) char smem[];
    const uint32_t sb = smem_to_u32(smem);

    const int t = threadIdx.x, lane = t & 31, wid = t >> 5;
    const int wm = wid >> 2, wn = wid & 3;      // 2 x 4 warps
    const int bh = blockIdx.y, b = bh / kH, h = bh % kH;
    const int i0 = blockIdx.x * 64;

    const unsigned short* gh = ps  + ((size_t)bh * kS + i0) * kS;
    const unsigned short* gl = psl + ((size_t)bh * kS + i0) * kS;

    // stage P tile (64x64 hi + lo) + V tile for j-tile jt into buffer jt&1
    auto stage = [&](int jt) {
        const uint32_t base = sb + (jt & 1) * AVSTAGE;
        const uint32_t dPh = base, dPl = base + PBUF, dV = base + 2 * PBUF;
        // P: 64 rows x 8 chunks (hi and lo) = 512 each
#pragma unroll
        for (int i = 0; i < 2; i++) {
            int idx = i * 256 + t;
            int row = idx >> 3, ch = idx & 7;
            uint32_t so = (uint32_t)(row * LDP + ch * 8) * 2;
            size_t  go = (size_t)row * kS + jt * 64 + ch * 8;
            cp_async16(dPh + so, gh + go);
            cp_async16(dPl + so, gl + go);
        }
        // V: 64 rows x 24 chunks = 1536
        const unsigned short* g = vt + (((size_t)bh * 6 + jt) * 64) * 192;
#pragma unroll
        for (int i = 0; i < 6; i++) {
            int idx = i * 256 + t;
            int row = idx / 24, ch = idx % 24;
            cp_async16(dV + (uint32_t)(row * LDV + ch * 8) * 2,
                       g + (size_t)row * 192 + ch * 8);
        }
        CP_COMMIT();
    };

    stage(0);

    float d[2][2][4];
#pragma unroll
    for (int i = 0; i < 2; i++)
#pragma unroll
        for (int j = 0; j < 2; j++)
#pragma unroll
            for (int e = 0; e < 4; e++) d[i][j][e] = 0.f;

    const int aRow = lane & 15, aCol = (lane >> 4) * 8;
    const int bRow = lane & 7,  bCol = ((lane >> 3) & 1) * 8;

    for (int jt = 0; jt < 6; jt++) {
        if (jt + 1 < 6) { stage(jt + 1); CP_WAIT(1); }
        else            { CP_WAIT(0); }
        __syncthreads();

        const uint32_t base = sb + (jt & 1) * AVSTAGE;
        const uint32_t sPh = base, sPl = base + PBUF, sV = base + 2 * PBUF;

#pragma unroll
        for (int ksp = 0; ksp < 192; ksp += 16) {
            const uint32_t sPbuf = (ksp < 128) ? sPh : sPl;   // [hi|hi|lo]
            uint32_t a[2][4], bf[2][2];
#pragma unroll
            for (int fi = 0; fi < 2; fi++)
                ldmatrix_x4(a[fi], sPbuf + (uint32_t)((wm * 32 + fi * 16 + aRow) * LDP
                                                      + (ksp & 63) + aCol) * 2);
#pragma unroll
            for (int fj = 0; fj < 2; fj++)
                ldmatrix_x2(bf[fj], sV + (uint32_t)((wn * 16 + fj * 8 + bRow) * LDV
                                                    + ksp + bCol) * 2);
#pragma unroll
            for (int fi = 0; fi < 2; fi++)
#pragma unroll
                for (int fj = 0; fj < 2; fj++)
                    mma_bf16(d[fi][fj], a[fi], bf[fj]);
        }
        __syncthreads();
    }

    // epilogue: write O as A-pattern split (hi|hi|lo) rows of g_ab
#pragma unroll
    for (int fi = 0; fi < 2; fi++) {
#pragma unroll
        for (int fj = 0; fj < 2; fj++) {
            int mm = i0 + wm * 32 + fi * 16 + (lane >> 2);
            int nn = h * 64 + wn * 16 + fj * 8 + (lane & 3) * 2;
            size_t row0 = (size_t)b * kS + mm;
            unsigned short* base0 = osplit + row0 * kK3 + nn;
            uint32_t hp, lp;
            split2_pack(d[fi][fj][0], d[fi][fj][1], hp, lp);
            *(uint32_t*)(base0)         = hp;
            *(uint32_t*)(base0 + 768)   = hp;
            *(uint32_t*)(base0 + 1536)  = lp;
            unsigned short* base1 = osplit + (row0 + 8) * kK3 + nn;
            split2_pack(d[fi][fj][2], d[fi][fj][3], hp, lp);
            *(uint32_t*)(base1)         = hp;
            *(uint32_t*)(base1 + 768)   = hp;
            *(uint32_t*)(base1 + 1536)  = lp;
        }
    }
}

// ---------------------------------------------------------------------------
// Launch
// ---------------------------------------------------------------------------
extern "C" void kernel_launch(void* const* d_in, const int* in_sizes, int n_in,
                              void* d_out, int out_size)
{
    const float* x    = (const float*)d_in[0];
    const int*   mask = (const int*)d_in[1];
    const int*   seg  = (const int*)d_in[2];
    const float* sep  = (const float*)d_in[3];
    const float* Wq   = (const float*)d_in[4];
    const float* bq   = (const float*)d_in[5];
    const float* Wk   = (const float*)d_in[6];
    const float* bk   = (const float*)d_in[7];
    const float* Wv   = (const float*)d_in[8];
    const float* bv   = (const float*)d_in[9];
    const float* rel  = (const float*)d_in[10];
    const float* Wpk  = (const float*)d_in[11];
    const float* bpk  = (const float*)d_in[12];
    const float* Wpq  = (const float*)d_in[13];
    const float* bpq  = (const float*)d_in[14];
    const float* same_b  = (const float*)d_in[15];
    const float* cross_b = (const float*)d_in[16];
    const float* sscale  = (const float*)d_in[17];
    const float* sdecay  = (const float*)d_in[18];
    const float* Wo   = (const float*)d_in[19];
    const float* bo   = (const float*)d_in[20];
    float* out = (float*)d_out;

    float *v_, *lg_;
    unsigned short *ab_, *wqkv_, *apos_, *wpos_, *qs_, *ks_, *pks_, *pqs_, *vt_, *ps_, *psl_;
    cudaGetSymbolAddress((void**)&v_,  g_v);
    cudaGetSymbolAddress((void**)&lg_, g_logits);
    cudaGetSymbolAddress((void**)&ab_,   g_ab);
    cudaGetSymbolAddress((void**)&wqkv_, g_wqkv);
    cudaGetSymbolAddress((void**)&apos_, g_apos);
    cudaGetSymbolAddress((void**)&wpos_, g_wpos);
    cudaGetSymbolAddress((void**)&qs_,  g_qs);
    cudaGetSymbolAddress((void**)&ks_,  g_ks);
    cudaGetSymbolAddress((void**)&pks_, g_pks);
    cudaGetSymbolAddress((void**)&pqs_, g_pqs);
    cudaGetSymbolAddress((void**)&vt_,  g_vt);
    cudaGetSymbolAddress((void**)&ps_,  g_ps);
    cudaGetSymbolAddress((void**)&psl_, g_psl);

    cudaFuncSetAttribute(tgemm_kernel,
                         cudaFuncAttributeMaxDynamicSharedMemorySize,
                         TGEMM_SMEM);
    cudaFuncSetAttribute(tgemm_dual_kernel,
                         cudaFuncAttributeMaxDynamicSharedMemorySize,
                         TGEMM_SMEM);
    cudaFuncSetAttribute(logits_mma_kernel,
                         cudaFuncAttributeMaxDynamicSharedMemorySize,
                         LOGMMA_SMEM);
    cudaFuncSetAttribute(av_mma_kernel,
                         cudaFuncAttributeMaxDynamicSharedMemorySize,
                         AV_SMEM);

    const int kq = kD / 4;  // 192

    // 1) operand splits (fp32 -> bf16 hi/lo, K-concat, duplicated-hi layout)
    split_a_kernel<<<(3072 * kq + 255) / 256, 256>>>(x, ab_, 3072, 3072, kD);
    split_w_kernel<<<(2304 * kq + 255) / 256, 256>>>(Wq, Wk, Wv, wqkv_, 3, kD);
    split_a_kernel<<<(768 * kq + 255) / 256, 256>>>(rel + (size_t)128 * kD, apos_, kR, 768, kD);
    split_w_kernel<<<(1536 * kq + 255) / 256, 256>>>(Wpk, Wpq, Wpq, wpos_, 2, kD);

    // 2) QKV + POS projections, merged into one launch (504 blocks)
    tgemm_dual_kernel<<<504, 256, TGEMM_SMEM>>>(
        (const __nv_bfloat16*)ab_, (const __nv_bfloat16*)wqkv_,
        bq, bk, bv, v_, qs_, ks_,
        (const __nv_bfloat16*)apos_, (const __nv_bfloat16*)wpos_,
        bpk, bpq, pks_, pqs_);

    // 2b) V transpose + split for tensor AV
    vtrans_kernel<<<dim3(6, 96), 256>>>(v_, vt_);

    // 3) fused banded-MMA logits + segment bias + mask (two-pass, 2 CTA/SM)
    dim3 glog(kS / 64, kS / 64, kB * kH);
    logits_mma_kernel<<<glog, 256, LOGMMA_SMEM>>>(
        qs_, ks_, pks_, pqs_, mask, seg, sep,
        same_b, cross_b, sscale, sdecay, lg_);

    // 4) softmax -> hi/lo bf16 probabilities (1 warp per row)
    softmax_bf16_kernel<<<kB * kH * kS / 8, 256>>>(lg_, ps_, psl_);

    // 5) split Wo (independent of softmax/AV stream order)
    split_w_kernel<<<(768 * kq + 255) / 256, 256>>>(Wo, Wo, Wo, wpos_, 1, kE);

    // 6) tensor AV: P @ V -> A-pattern split rows directly into ab_ (2 CTA/SM)
    av_mma_kernel<<<dim3(6, 96), 256, AV_SMEM>>>(ps_, psl_, vt_, ab_);

    // 7) Output projection (A operand = av output split, already in ab_)
    tgemm_kernel<<<dim3(6, 24), 256, TGEMM_SMEM>>>(
        (const __nv_bfloat16*)ab_, (const __nv_bfloat16*)wpos_, 3072, bo, out);
}

// round 17
// speedup vs baseline: 1.2431x; 1.0216x over previous
#include <cuda_runtime.h>
#include <cuda_bf16.h>
#include <math.h>
#include <stdint.h>

// Problem constants
constexpr int kB  = 8;
constexpr int kS  = 384;
constexpr int kD  = 768;
constexpr int kE  = 768;
constexpr int kH  = 12;
constexpr int kHD = 64;
constexpr int kR  = 2 * kS - 1;   // 767 distinct relative positions actually used
constexpr int kK3 = 3 * kD;       // 2304: bf16-split concatenated K
constexpr int kKS = 192;          // 3*64: split head-dim for logits MMA

// ---------------------------------------------------------------------------
// Scratch (device globals; no runtime allocation allowed)
// ---------------------------------------------------------------------------
__device__ float g_v[kB * kH * kS * kHD];               // [B,H,S,HD] fp32
__device__ float g_logits[(size_t)kB * kH * kS * kS];   // [B,H,S,S]

// bf16-split operand buffers for projections (duplicated-hi layout)
__device__ unsigned short g_ab[3072 * kK3];      // A-split: x, then AV output
__device__ unsigned short g_wqkv[2304 * kK3];    // [Wq|Wk|Wv] split
__device__ unsigned short g_apos[768 * kK3];     // rel rows split (padded to 768)
__device__ unsigned short g_wpos[1536 * kK3];    // [Wpk|Wpq] split; reused for Wo

// bf16-split logits operands (written by tgemm epilogues)
__device__ unsigned short g_qs[96 * kS * kKS];   // [bh][s][192] pattern A (hi,hi,lo)
__device__ unsigned short g_ks[96 * kS * kKS];   // [bh][s][192] pattern B (hi,lo,hi)
__device__ unsigned short g_pks[kH * 768 * kKS]; // [h][r][192]  pattern B
__device__ unsigned short g_pqs[kH * 768 * kKS]; // [h][r][192]  pattern A

// attention probabilities, hi/lo bf16 split: [bh][i][384] each
__device__ unsigned short g_ps [(size_t)96 * kS * kS];
__device__ unsigned short g_psl[(size_t)96 * kS * kS];
// transposed split V for tensor AV: [bh][jt][d][192] pattern B (hi|lo|hi)
__device__ unsigned short g_vt[96 * 6 * 64 * 192];

// ---------------------------------------------------------------------------
// PTX helpers (target-independent: cp.async, ldmatrix, mma.sync — sm_80+)
// ---------------------------------------------------------------------------
__device__ __forceinline__ uint32_t smem_to_u32(const void* p) {
    uint32_t a;
    asm("{ .reg .u64 t; cvta.to.shared.u64 t, %1; cvt.u32.u64 %0, t; }"
        : "=r"(a) : "l"(p));
    return a;
}

__device__ __forceinline__ void cp_async16(uint32_t saddr, const void* gptr) {
    asm volatile("cp.async.cg.shared.global [%0], [%1], 16;\n"
                 :: "r"(saddr), "l"(gptr));
}
#define CP_COMMIT()  asm volatile("cp.async.commit_group;\n" ::: "memory")
#define CP_WAIT(n)   asm volatile("cp.async.wait_group %0;\n" :: "n"(n) : "memory")

__device__ __forceinline__ void ldmatrix_x4(uint32_t* r, uint32_t addr) {
    asm volatile("ldmatrix.sync.aligned.m8n8.x4.shared.b16 {%0,%1,%2,%3}, [%4];"
                 : "=r"(r[0]), "=r"(r[1]), "=r"(r[2]), "=r"(r[3]) : "r"(addr));
}
__device__ __forceinline__ void ldmatrix_x2(uint32_t* r, uint32_t addr) {
    asm volatile("ldmatrix.sync.aligned.m8n8.x2.shared.b16 {%0,%1}, [%2];"
                 : "=r"(r[0]), "=r"(r[1]) : "r"(addr));
}

__device__ __forceinline__ void mma_bf16(float* d, const uint32_t* a, const uint32_t* b) {
    asm volatile(
        "mma.sync.aligned.m16n8k16.row.col.f32.bf16.bf16.f32 "
        "{%0,%1,%2,%3}, {%4,%5,%6,%7}, {%8,%9}, {%0,%1,%2,%3};"
        : "+f"(d[0]), "+f"(d[1]), "+f"(d[2]), "+f"(d[3])
        : "r"(a[0]), "r"(a[1]), "r"(a[2]), "r"(a[3]),
          "r"(b[0]), "r"(b[1]));
}

// ---------------------------------------------------------------------------
// fp32 -> bf16 hi/lo split conversion kernels (duplicated-hi layouts)
// A pattern:  out[m, 0:K]=hi, [K:2K]=hi, [2K:3K]=lo
// W pattern:  out[n, 0:K]=hi, [K:2K]=lo, [2K:3K]=hi
// ---------------------------------------------------------------------------
union BF4 { __nv_bfloat16 h[4]; uint2 u; };

__device__ __forceinline__ void split4(float4 a, uint2& hi, uint2& lo)
{
    float v[4] = {a.x, a.y, a.z, a.w};
    BF4 H, L;
#pragma unroll
    for (int i = 0; i < 4; i++) {
        __nv_bfloat16 h1 = __float2bfloat16_rn(v[i]);
        float res = v[i] - __bfloat162float(h1);
        H.h[i] = h1;
        L.h[i] = __float2bfloat16_rn(res);
    }
    hi = H.u; lo = L.u;
}

__device__ __forceinline__ void split2_pack(float v0, float v1,
                                            uint32_t& hp, uint32_t& lp)
{
    __nv_bfloat16 h0 = __float2bfloat16_rn(v0), h1 = __float2bfloat16_rn(v1);
    float r0 = v0 - __bfloat162float(h0), r1 = v1 - __bfloat162float(h1);
    __nv_bfloat16 l0 = __float2bfloat16_rn(r0), l1 = __float2bfloat16_rn(r1);
    hp = (uint32_t)*(unsigned short*)&h0 | ((uint32_t)*(unsigned short*)&h1 << 16);
    lp = (uint32_t)*(unsigned short*)&l0 | ((uint32_t)*(unsigned short*)&l1 << 16);
}

__global__ __launch_bounds__(256) void split_a_kernel(
    const float* __restrict__ A, unsigned short* __restrict__ out,
    int Msrc, int Mpad, int K)
{
    int idx = blockIdx.x * 256 + threadIdx.x;
    int kq = K >> 2;
    if (idx >= Mpad * kq) return;
    int m = idx / kq;
    int c4 = (idx - m * kq) << 2;
    float4 a = (m < Msrc) ? *(const float4*)(A + (size_t)m * K + c4)
                          : make_float4(0.f, 0.f, 0.f, 0.f);
    uint2 hi, lo; split4(a, hi, lo);
    size_t base = (size_t)m * 3 * K + c4;
    *(uint2*)(out + base)         = hi;
    *(uint2*)(out + base + K)     = hi;
    *(uint2*)(out + base + 2 * K) = lo;
}

__global__ __launch_bounds__(256) void split_w_kernel(
    const float* __restrict__ W0, const float* __restrict__ W1,
    const float* __restrict__ W2, unsigned short* __restrict__ out,
    int nsrc, int K)
{
    int idx = blockIdx.x * 256 + threadIdx.x;
    int kq = K >> 2;
    int rows = nsrc * 768;
    if (idx >= rows * kq) return;
    int rr = idx / kq;
    int c4 = (idx - rr * kq) << 2;
    int s = rr / 768, r = rr - s * 768;
    const float* W = (s == 0) ? W0 : (s == 1) ? W1 : W2;
    float4 a = *(const float4*)(W + (size_t)r * K + c4);
    uint2 hi, lo; split4(a, hi, lo);
    size_t base = (size_t)rr * 3 * K + c4;
    *(uint2*)(out + base)         = hi;
    *(uint2*)(out + base + K)     = lo;
    *(uint2*)(out + base + 2 * K) = hi;
}

// ---------------------------------------------------------------------------
// bf16 HMMA GEMM body (projections). 128x128 CTA tile, BK=64, 256 threads.
// mode 0: QKV   n<768 -> q split(A-pat), n<1536 -> k split(B-pat), else v fp32
// mode 1: POS   n<768 -> pk split(B-pat), else pq split(A-pat)
// mode 2: plain fp32 C[m*768+n]
// ---------------------------------------------------------------------------
constexpr int BK   = 64;
constexpr int LDT  = 72;                       // smem stride in halves (pad 8)
constexpr int TBUF = 128 * LDT * 2;            // bytes per tile buffer
constexpr int TGEMM_SMEM = 4 * TBUF;           // A0,B0,A1,B1 = 73728

__device__ __forceinline__ void store_split_pair(
    unsigned short* base, float v0, float v1, bool patA)
{
    uint32_t hp, lp;
    split2_pack(v0, v1, hp, lp);
    *(uint32_t*)(base)       = hp;
    *(uint32_t*)(base + 64)  = patA ? hp : lp;
    *(uint32_t*)(base + 128) = patA ? lp : hp;
}

__device__ __forceinline__ void store_pair(
    int mode, int Msrc, int mrow, int n, float v0, float v1,
    const float* __restrict__ b0, const float* __restrict__ b1,
    const float* __restrict__ b2,
    float* __restrict__ o0,
    unsigned short* __restrict__ s0, unsigned short* __restrict__ s1)
{
    if (mrow >= Msrc) return;
    if (mode == 2) {
        float2 w = make_float2(v0 + b0[n], v1 + b0[n + 1]);
        *(float2*)&o0[(size_t)mrow * 768 + n] = w;
        return;
    }
    int which = n / 768;
    int e = n - which * 768;
    int h = e >> 6, hd = e & 63;
    const float* bp = (which == 0) ? b0 : (which == 1) ? b1 : b2;
    float w0 = v0 + bp[e], w1 = v1 + bp[e + 1];
    if (mode == 0) {
        int bi = mrow / kS, s = mrow - bi * kS;
        if (which == 2) {
            *(float2*)&o0[((((size_t)bi * kH) + h) * kS + s) * (size_t)kHD + hd]
                = make_float2(w0, w1);
        } else {
            unsigned short* base = ((which == 0) ? s0 : s1)
                + (((size_t)(bi * kH + h) * kS) + s) * kKS + hd;
            store_split_pair(base, w0, w1, which == 0);  // q: A-pat, k: B-pat
        }
    } else {  // mode 1: pk (B-pat), pq (A-pat)
        unsigned short* base = ((which == 0) ? s0 : s1)
            + (((size_t)h * 768) + mrow) * kKS + hd;
        store_split_pair(base, w0, w1, which == 1);
    }
}

__device__ __forceinline__ void tgemm_body(
    const __nv_bfloat16* __restrict__ A, const __nv_bfloat16* __restrict__ B,
    int Msrc,
    const float* __restrict__ bias0, const float* __restrict__ bias1,
    const float* __restrict__ bias2,
    float* __restrict__ out0,
    unsigned short* __restrict__ s0, unsigned short* __restrict__ s1,
    int mode, int m0, int n0, char* smem)
{
    const uint32_t sbase = smem_to_u32(smem);

    const int t = threadIdx.x, lane = t & 31, wid = t >> 5;
    const int warp_m = wid & 1, warp_n = wid >> 1;   // 2 x 4

    const __nv_bfloat16* Ag = A + (size_t)m0 * kK3;
    const __nv_bfloat16* Bg = B + (size_t)n0 * kK3;
    const int NC = kK3 / BK;

    const int lrow = t >> 3;
    const int lc8  = (t & 7) * 8;

    auto issue = [&](int c) {
        const int buf = c & 1;
        const uint32_t dA = sbase + buf * 2 * TBUF;
        const uint32_t dB = dA + TBUF;
        const __nv_bfloat16* Ak = Ag + (size_t)c * BK;
        const __nv_bfloat16* Bk = Bg + (size_t)c * BK;
#pragma unroll
        for (int it = 0; it < 4; it++) {
            int r = lrow + it * 32;
            uint32_t so = (uint32_t)(r * LDT + lc8) * 2;
            cp_async16(dA + so, Ak + (size_t)r * kK3 + lc8);
            cp_async16(dB + so, Bk + (size_t)r * kK3 + lc8);
        }
        CP_COMMIT();
    };

    float d[4][4][4];
#pragma unroll
    for (int i = 0; i < 4; i++)
#pragma unroll
        for (int j = 0; j < 4; j++)
#pragma unroll
            for (int e = 0; e < 4; e++) d[i][j][e] = 0.f;

    const int a_row = warp_m * 64 + (lane & 15);
    const int a_col = (lane >> 4) * 8;
    const int b_row = warp_n * 32 + (lane & 7);
    const int b_col = ((lane >> 3) & 1) * 8;

    issue(0);

    for (int c = 0; c < NC; c++) {
        if (c + 1 < NC) { issue(c + 1); CP_WAIT(1); }
        else           { CP_WAIT(0); }
        __syncthreads();

        const int buf = c & 1;
        const uint32_t sA = sbase + buf * 2 * TBUF;
        const uint32_t sB = sA + TBUF;

#pragma unroll
        for (int ks = 0; ks < BK; ks += 16) {
            uint32_t a[4][4], b[4][2];
#pragma unroll
            for (int i = 0; i < 4; i++)
                ldmatrix_x4(a[i], sA + (uint32_t)((a_row + i * 16) * LDT + a_col + ks) * 2);
#pragma unroll
            for (int j = 0; j < 4; j++)
                ldmatrix_x2(b[j], sB + (uint32_t)((b_row + j * 8) * LDT + b_col + ks) * 2);
#pragma unroll
            for (int i = 0; i < 4; i++)
#pragma unroll
                for (int j = 0; j < 4; j++)
                    mma_bf16(d[i][j], a[i], b[j]);
        }
        __syncthreads();
    }

    const int mbase = m0 + warp_m * 64 + (lane >> 2);
    const int nbase = n0 + warp_n * 32 + (lane & 3) * 2;
#pragma unroll
    for (int i = 0; i < 4; i++) {
#pragma unroll
        for (int j = 0; j < 4; j++) {
            int mm = mbase + i * 16;
            int nn = nbase + j * 8;
            store_pair(mode, Msrc, mm,     nn, d[i][j][0], d[i][j][1],
                       bias0, bias1, bias2, out0, s0, s1);
            store_pair(mode, Msrc, mm + 8, nn, d[i][j][2], d[i][j][3],
                       bias0, bias1, bias2, out0, s0, s1);
        }
    }
}

// Plain entry (used for the output projection, mode 2) — force 2 CTAs/SM
__global__ __launch_bounds__(256, 2) void tgemm_kernel(
    const __nv_bfloat16* __restrict__ A, const __nv_bfloat16* __restrict__ B,
    int Msrc,
    const float* __restrict__ bias0,
    float* __restrict__ out0)
{
    extern __shared__ __align__(16) char smem[];
    tgemm_body(A, B, Msrc, bias0, nullptr, nullptr, out0, nullptr, nullptr,
               2, blockIdx.y * 128, blockIdx.x * 128, smem);
}

// Merged QKV + POS entry: flat grid of 432 + 72 = 504 blocks — force 2 CTAs/SM
__global__ __launch_bounds__(256, 2) void tgemm_dual_kernel(
    const __nv_bfloat16* __restrict__ Aq, const __nv_bfloat16* __restrict__ Bq,
    const float* __restrict__ bq, const float* __restrict__ bk,
    const float* __restrict__ bv,
    float* __restrict__ v_out,
    unsigned short* __restrict__ qs, unsigned short* __restrict__ ks,
    const __nv_bfloat16* __restrict__ Ap, const __nv_bfloat16* __restrict__ Bp,
    const float* __restrict__ bpk, const float* __restrict__ bpq,
    unsigned short* __restrict__ pks, unsigned short* __restrict__ pqs)
{
    extern __shared__ __align__(16) char smem[];
    const int bx = blockIdx.x;
    if (bx < 432) {
        int m0 = (bx / 18) * 128, n0 = (bx % 18) * 128;
        tgemm_body(Aq, Bq, 3072, bq, bk, bv, v_out, qs, ks, 0, m0, n0, smem);
    } else {
        int i = bx - 432;
        int m0 = (i / 12) * 128, n0 = (i % 12) * 128;
        tgemm_body(Ap, Bp, kR, bpk, bpq, nullptr, nullptr, pks, pqs, 1, m0, n0, smem);
    }
}

// ---------------------------------------------------------------------------
// V transpose + split: g_v [bh][s][64] fp32 -> g_vt [bh][jt][d][192] (hi|lo|hi)
// ---------------------------------------------------------------------------
__global__ __launch_bounds__(256) void vtrans_kernel(
    const float* __restrict__ v, unsigned short* __restrict__ vt)
{
    __shared__ float tile[64][65];
    const int bh = blockIdx.y, jt = blockIdx.x;
    const int t = threadIdx.x;
    const float* src = v + ((size_t)bh * kS + jt * 64) * kHD;

#pragma unroll
    for (int i = 0; i < 16; i++) {
        int idx = i * 256 + t;
        tile[idx >> 6][idx & 63] = src[idx];
    }
    __syncthreads();

    unsigned short* dst = vt + (((size_t)bh * 6 + jt) * 64) * 192;
#pragma unroll
    for (int i = 0; i < 8; i++) {
        int idx = i * 256 + t;            // 0..2047
        int dd  = idx >> 5;               // d row
        int jp  = (idx & 31) * 2;         // j pair
        uint32_t hp, lp;
        split2_pack(tile[jp][dd], tile[jp + 1][dd], hp, lp);
        unsigned short* base = dst + (size_t)dd * 192 + jp;
        *(uint32_t*)(base)       = hp;    // pattern B: hi, lo, hi
        *(uint32_t*)(base + 64)  = lp;
        *(uint32_t*)(base + 128) = hp;
    }
}

// ---------------------------------------------------------------------------
// Fused banded-MMA logits kernel — two-pass window variant (round-15 winner).
// ---------------------------------------------------------------------------
constexpr int LDS = 200;  // smem stride in halves for all operand tiles
constexpr int LOGMMA_SMEM = 4 * 64 * LDS * 2;  // 102400 B
constexpr int QW_STRIDE = 132;

__global__ __launch_bounds__(256, 2) void logits_mma_kernel(
    const unsigned short* __restrict__ qs, const unsigned short* __restrict__ ks,
    const unsigned short* __restrict__ pks, const unsigned short* __restrict__ pqs,
    const int* __restrict__ mask, const int* __restrict__ seg,
    const float* __restrict__ sep,
    const float* __restrict__ same_bias, const float* __restrict__ cross_bias,
    const float* __restrict__ sep_scale, const float* __restrict__ sep_decay,
    float* __restrict__ logits)
{
    extern __shared__ __align__(16) char smem[];
    const uint32_t sb = smem_to_u32(smem);

    __shared__ int   s_segi[64], s_segj[64], s_maskj[64];
    __shared__ float s_sepi[64], s_sepj[64];

    const int t = threadIdx.x, lane = t & 31, wid = t >> 5;
    const int wm = wid >> 2, wn = wid & 3;          // 2 x 4 warps
    const int bh = blockIdx.z, b = bh / kH, h = bh % kH;
    const int i0 = blockIdx.y * 64, j0 = blockIdx.x * 64;
    const int rb = i0 - j0 + 320;                   // window base: r = rb + u

    const uint32_t sQ  = sb;
    const uint32_t sK  = sQ + 64 * LDS * 2;
    const uint32_t sPK = sK + 64 * LDS * 2;         // 64-row window buffer
    const uint32_t sPQ = sPK + 64 * LDS * 2;        // 64-row window buffer

    if (t < 64) {
        s_segi[t] = seg[b * kS + i0 + t];
        s_sepi[t] = fabsf(sep[b * kS + i0 + t]);
    } else if (t < 128) {
        int u = t - 64;
        s_segj[u]  = seg[b * kS + j0 + u];
        s_sepj[u]  = fabsf(sep[b * kS + j0 + u]);
        s_maskj[u] = mask[b * kS + j0 + u];
    }

    const unsigned short* gq  = qs  + ((size_t)bh * kS + i0) * kKS;
    const unsigned short* gk  = ks  + ((size_t)bh * kS + j0) * kKS;
    const unsigned short* gpk = pks + ((size_t)h * 768 + rb) * kKS;
    const unsigned short* gpq = pqs + ((size_t)h * 768 + rb) * kKS;
    const int r0 = t >> 3;
    const int c0 = (t & 7);

    // stage pass 0: Q, K + PK/PQ rows [0,64)
#pragma unroll
    for (int rh = 0; rh < 2; rh++) {
#pragma unroll
        for (int cc = 0; cc < 3; cc++) {
            int row = r0 + rh * 32, ch = c0 + cc * 8;
            uint32_t so = (uint32_t)(row * LDS + ch * 8) * 2;
            size_t  go = (size_t)row * kKS + ch * 8;
            cp_async16(sQ + so,  gq + go);
            cp_async16(sK + so,  gk + go);
            cp_async16(sPK + so, gpk + go);
            cp_async16(sPQ + so, gpq + go);
        }
    }
    CP_COMMIT();
    CP_WAIT(0);
    __syncthreads();

    float c2c[2][2][4], qw[2][4][4], kw[2][4][4];
#pragma unroll
    for (int i = 0; i < 2; i++) {
#pragma unroll
        for (int j = 0; j < 2; j++)
#pragma unroll
            for (int e = 0; e < 4; e++) c2c[i][j][e] = 0.f;
#pragma unroll
        for (int j = 0; j < 4; j++)
#pragma unroll
            for (int e = 0; e < 4; e++) { qw[i][j][e] = 0.f; kw[i][j][e] = 0.f; }
    }

    const int aRow = (lane & 15);
    const int aCol = (lane >> 4) * 8;
    const int bRow = (lane & 7);
    const int bCol = ((lane >> 3) & 1) * 8;

    auto mma_pass = [&](int p) {
#pragma unroll
        for (int ksp = 0; ksp < kKS; ksp += 16) {
            uint32_t aQ[2][4], aK[2][4];
#pragma unroll
            for (int fi = 0; fi < 2; fi++) {
                int r = wm * 32 + fi * 16 + aRow;
                ldmatrix_x4(aQ[fi], sQ + (uint32_t)(r * LDS + aCol + ksp) * 2);
                ldmatrix_x4(aK[fi], sK + (uint32_t)(r * LDS + aCol + ksp) * 2);
            }
            if (p == 0) {
                uint32_t bC[2][2];
#pragma unroll
                for (int fj = 0; fj < 2; fj++) {
                    int r = wn * 16 + fj * 8 + bRow;
                    ldmatrix_x2(bC[fj], sK + (uint32_t)(r * LDS + bCol + ksp) * 2);
                }
#pragma unroll
                for (int fi = 0; fi < 2; fi++)
#pragma unroll
                    for (int fj = 0; fj < 2; fj++)
                        mma_bf16(c2c[fi][fj], aQ[fi], bC[fj]);
            }
            uint32_t bPK[2][2], bPQ[2][2];
#pragma unroll
            for (int f2 = 0; f2 < 2; f2++) {
                int r = wn * 16 + f2 * 8 + bRow;   // local u row in 64-row buf
                ldmatrix_x2(bPK[f2], sPK + (uint32_t)(r * LDS + bCol + ksp) * 2);
                ldmatrix_x2(bPQ[f2], sPQ + (uint32_t)(r * LDS + bCol + ksp) * 2);
            }
#pragma unroll
            for (int fi = 0; fi < 2; fi++)
#pragma unroll
                for (int f2 = 0; f2 < 2; f2++) {
                    mma_bf16(qw[fi][p * 2 + f2], aQ[fi], bPK[f2]);
                    mma_bf16(kw[fi][p * 2 + f2], aK[fi], bPQ[f2]);
                }
        }
    };

    mma_pass(0);
    __syncthreads();   // window buffers reusable

    // stage pass 1: PK/PQ rows [64,128)
#pragma unroll
    for (int rh = 0; rh < 2; rh++) {
#pragma unroll
        for (int cc = 0; cc < 3; cc++) {
            int row = r0 + rh * 32, ch = c0 + cc * 8;
            uint32_t so = (uint32_t)(row * LDS + ch * 8) * 2;
            size_t  go = (size_t)(row + 64) * kKS + ch * 8;
            cp_async16(sPK + so, gpk + go);
            cp_async16(sPQ + so, gpq + go);
        }
    }
    CP_COMMIT();
    CP_WAIT(0);
    __syncthreads();

    mma_pass(1);

    __syncthreads();
    float* QWs = (float*)smem;                    // [64][132]
    float* KWs = QWs + 64 * QW_STRIDE;            // [64][132]
#pragma unroll
    for (int fi = 0; fi < 2; fi++) {
#pragma unroll
        for (int fu = 0; fu < 4; fu++) {
            int rl = wm * 32 + fi * 16 + (lane >> 2);
            int u  = (fu >> 1) * 64 + wn * 16 + (fu & 1) * 8 + (lane & 3) * 2;
            QWs[rl * QW_STRIDE + u]           = qw[fi][fu][0];
            QWs[rl * QW_STRIDE + u + 1]       = qw[fi][fu][1];
            QWs[(rl + 8) * QW_STRIDE + u]     = qw[fi][fu][2];
            QWs[(rl + 8) * QW_STRIDE + u + 1] = qw[fi][fu][3];
            KWs[rl * QW_STRIDE + u]           = kw[fi][fu][0];
            KWs[rl * QW_STRIDE + u + 1]       = kw[fi][fu][1];
            KWs[(rl + 8) * QW_STRIDE + u]     = kw[fi][fu][2];
            KWs[(rl + 8) * QW_STRIDE + u + 1] = kw[fi][fu][3];
        }
    }
    __syncthreads();

    const float sb_same  = same_bias[h];
    const float sb_cross = cross_bias[h];
    const float scale_h  = sep_scale[h];
    const float dx       = sep_decay[h];
    const float softp    = fmaxf(dx, 0.f) + log1pf(expf(-fabsf(dx)));
    const float decay    = softp + 1e-4f;
    const float inv      = 0.07216878364870322f;  // 1/sqrt(3*HD)

#pragma unroll
    for (int fi = 0; fi < 2; fi++) {
#pragma unroll
        for (int fj = 0; fj < 2; fj++) {
            int il0 = wm * 32 + fi * 16 + (lane >> 2);
            int jl0 = wn * 16 + fj * 8 + (lane & 3) * 2;
#pragma unroll
            for (int half = 0; half < 2; half++) {
                int il = il0 + half * 8;
                float raw0 = c2c[fi][fj][half * 2];
                float raw1 = c2c[fi][fj][half * 2 + 1];
                int   segi = s_segi[il];
                float sepi = s_sepi[il];
#pragma unroll
                for (int e = 0; e < 2; e++) {
                    int jl = jl0 + e;
                    int u  = il - jl + 63;
                    float val = ((e ? raw1 : raw0)
                                 + QWs[il * QW_STRIDE + u]
                                 + KWs[jl * QW_STRIDE + u]) * inv;
                    if (segi == s_segj[jl]) {
                        val += sb_same;
                    } else {
                        float gap = fabsf(sepi - s_sepj[jl]);
                        val += sb_cross + expf(-gap * decay) * scale_h;
                    }
                    if (s_maskj[jl] == 0) val = -9e15f;
                    logits[(((size_t)bh * kS) + i0 + il) * kS + j0 + jl] = val;
                }
            }
        }
    }
}

// ---------------------------------------------------------------------------
// Row softmax, one WARP per row (8 rows / 256-thread block), shuffle-only
// reductions, writing hi/lo bf16 split probabilities.
// ---------------------------------------------------------------------------
__global__ __launch_bounds__(256) void softmax_bf16_kernel(
    const float* __restrict__ logits,
    unsigned short* __restrict__ ps, unsigned short* __restrict__ psl)
{
    const int lane = threadIdx.x & 31, w = threadIdx.x >> 5;
    const size_t row = (size_t)blockIdx.x * 8 + w;
    const float* p = logits + row * kS;

    float4 v[3];
#pragma unroll
    for (int c = 0; c < 3; c++)
        v[c] = *(const float4*)(p + (c * 32 + lane) * 4);

    float m = -INFINITY;
#pragma unroll
    for (int c = 0; c < 3; c++)
        m = fmaxf(m, fmaxf(fmaxf(v[c].x, v[c].y), fmaxf(v[c].z, v[c].w)));
#pragma unroll
    for (int o = 16; o; o >>= 1) m = fmaxf(m, __shfl_xor_sync(0xffffffffu, m, o));

    float e[3][4];
    float s = 0.f;
#pragma unroll
    for (int c = 0; c < 3; c++) {
        e[c][0] = __expf(v[c].x - m); e[c][1] = __expf(v[c].y - m);
        e[c][2] = __expf(v[c].z - m); e[c][3] = __expf(v[c].w - m);
        s += e[c][0] + e[c][1] + e[c][2] + e[c][3];
    }
#pragma unroll
    for (int o = 16; o; o >>= 1) s += __shfl_xor_sync(0xffffffffu, s, o);
    const float r = 1.f / s;

    unsigned short* oh = ps  + row * kS;
    unsigned short* ol = psl + row * kS;
#pragma unroll
    for (int c = 0; c < 3; c++) {
        uint32_t h01, l01, h23, l23;
        split2_pack(e[c][0] * r, e[c][1] * r, h01, l01);
        split2_pack(e[c][2] * r, e[c][3] * r, h23, l23);
        int off = (c * 32 + lane) * 4;
        *(uint2*)(oh + off) = make_uint2(h01, h23);
        *(uint2*)(ol + off) = make_uint2(l01, l23);
    }
}

// ---------------------------------------------------------------------------
// Tensor AV: O[b,i,h*64+d] = sum_j P[bh,i,j] * V[bh,j,d]
// 3-term split per 64-j tile (K=192): A = [P_hi|P_hi|P_lo], B = V^T (hi|lo|hi).
// P staged PER j-tile inside the V double-buffer pipeline (2 CTAs/SM).
// Epilogue writes O directly as the A-pattern bf16 split (hi|hi|lo).
// ---------------------------------------------------------------------------
constexpr int LDP  = 72;    // P tile stride in halves (64 + 8)
constexpr int LDV  = 200;   // V smem stride in halves (192 + 8)
constexpr int PBUF = 64 * LDP * 2;              // 9216 B (one of hi/lo)
constexpr int AVSTAGE = 2 * PBUF + 64 * LDV * 2; // 18432 + 25600 = 44032
constexpr int AV_SMEM = 2 * AVSTAGE;             // 88064 B

__global__ __launch_bounds__(256, 2) void av_mma_kernel(
    const unsigned short* __restrict__ ps, const unsigned short* __restrict__ psl,
    const unsigned short* __restrict__ vt,
    unsigned short* __restrict__ osplit)
{
    extern __shared__ __align__(16) char smem[];
    const uint32_t sb = smem_to_u32(smem);

    const int t = threadIdx.x, lane = t & 31, wid = t >> 5;
    const int wm = wid >> 2, wn = wid & 3;      // 2 x 4 warps
    const int bh = blockIdx.y, b = bh / kH, h = bh % kH;
    const int i0 = blockIdx.x * 64;

    const unsigned short* gh = ps  + ((size_t)bh * kS + i0) * kS;
    const unsigned short* gl = psl + ((size_t)bh * kS + i0) * kS;

    // stage P tile (64x64 hi + lo) + V tile for j-tile jt into buffer jt&1
    auto stage = [&](int jt) {
        const uint32_t base = sb + (jt & 1) * AVSTAGE;
        const uint32_t dPh = base, dPl = base + PBUF, dV = base + 2 * PBUF;
        // P: 64 rows x 8 chunks (hi and lo) = 512 each
#pragma unroll
        for (int i = 0; i < 2; i++) {
            int idx = i * 256 + t;
            int row = idx >> 3, ch = idx & 7;
            uint32_t so = (uint32_t)(row * LDP + ch * 8) * 2;
            size_t  go = (size_t)row * kS + jt * 64 + ch * 8;
            cp_async16(dPh + so, gh + go);
            cp_async16(dPl + so, gl + go);
        }
        // V: 64 rows x 24 chunks = 1536
        const unsigned short* g = vt + (((size_t)bh * 6 + jt) * 64) * 192;
#pragma unroll
        for (int i = 0; i < 6; i++) {
            int idx = i * 256 + t;
            int row = idx / 24, ch = idx % 24;
            cp_async16(dV + (uint32_t)(row * LDV + ch * 8) * 2,
                       g + (size_t)row * 192 + ch * 8);
        }
        CP_COMMIT();
    };

    stage(0);

    float d[2][2][4];
#pragma unroll
    for (int i = 0; i < 2; i++)
#pragma unroll
        for (int j = 0; j < 2; j++)
#pragma unroll
            for (int e = 0; e < 4; e++) d[i][j][e] = 0.f;

    const int aRow = lane & 15, aCol = (lane >> 4) * 8;
    const int bRow = lane & 7,  bCol = ((lane >> 3) & 1) * 8;

    for (int jt = 0; jt < 6; jt++) {
        if (jt + 1 < 6) { stage(jt + 1); CP_WAIT(1); }
        else            { CP_WAIT(0); }
        __syncthreads();

        const uint32_t base = sb + (jt & 1) * AVSTAGE;
        const uint32_t sPh = base, sPl = base + PBUF, sV = base + 2 * PBUF;

#pragma unroll
        for (int ksp = 0; ksp < 192; ksp += 16) {
            const uint32_t sPbuf = (ksp < 128) ? sPh : sPl;   // [hi|hi|lo]
            uint32_t a[2][4], bf[2][2];
#pragma unroll
            for (int fi = 0; fi < 2; fi++)
                ldmatrix_x4(a[fi], sPbuf + (uint32_t)((wm * 32 + fi * 16 + aRow) * LDP
                                                      + (ksp & 63) + aCol) * 2);
#pragma unroll
            for (int fj = 0; fj < 2; fj++)
                ldmatrix_x2(bf[fj], sV + (uint32_t)((wn * 16 + fj * 8 + bRow) * LDV
                                                    + ksp + bCol) * 2);
#pragma unroll
            for (int fi = 0; fi < 2; fi++)
#pragma unroll
                for (int fj = 0; fj < 2; fj++)
                    mma_bf16(d[fi][fj], a[fi], bf[fj]);
        }
        __syncthreads();
    }

    // epilogue: write O as A-pattern split (hi|hi|lo) rows of g_ab
#pragma unroll
    for (int fi = 0; fi < 2; fi++) {
#pragma unroll
        for (int fj = 0; fj < 2; fj++) {
            int mm = i0 + wm * 32 + fi * 16 + (lane >> 2);
            int nn = h * 64 + wn * 16 + fj * 8 + (lane & 3) * 2;
            size_t row0 = (size_t)b * kS + mm;
            unsigned short* base0 = osplit + row0 * kK3 + nn;
            uint32_t hp, lp;
            split2_pack(d[fi][fj][0], d[fi][fj][1], hp, lp);
            *(uint32_t*)(base0)         = hp;
            *(uint32_t*)(base0 + 768)   = hp;
            *(uint32_t*)(base0 + 1536)  = lp;
            unsigned short* base1 = osplit + (row0 + 8) * kK3 + nn;
            split2_pack(d[fi][fj][2], d[fi][fj][3], hp, lp);
            *(uint32_t*)(base1)         = hp;
            *(uint32_t*)(base1 + 768)   = hp;
            *(uint32_t*)(base1 + 1536)  = lp;
        }
    }
}

// ---------------------------------------------------------------------------
// Launch
// ---------------------------------------------------------------------------
extern "C" void kernel_launch(void* const* d_in, const int* in_sizes, int n_in,
                              void* d_out, int out_size)
{
    const float* x    = (const float*)d_in[0];
    const int*   mask = (const int*)d_in[1];
    const int*   seg  = (const int*)d_in[2];
    const float* sep  = (const float*)d_in[3];
    const float* Wq   = (const float*)d_in[4];
    const float* bq   = (const float*)d_in[5];
    const float* Wk   = (const float*)d_in[6];
    const float* bk   = (const float*)d_in[7];
    const float* Wv   = (const float*)d_in[8];
    const float* bv   = (const float*)d_in[9];
    const float* rel  = (const float*)d_in[10];
    const float* Wpk  = (const float*)d_in[11];
    const float* bpk  = (const float*)d_in[12];
    const float* Wpq  = (const float*)d_in[13];
    const float* bpq  = (const float*)d_in[14];
    const float* same_b  = (const float*)d_in[15];
    const float* cross_b = (const float*)d_in[16];
    const float* sscale  = (const float*)d_in[17];
    const float* sdecay  = (const float*)d_in[18];
    const float* Wo   = (const float*)d_in[19];
    const float* bo   = (const float*)d_in[20];
    float* out = (float*)d_out;

    float *v_, *lg_;
    unsigned short *ab_, *wqkv_, *apos_, *wpos_, *qs_, *ks_, *pks_, *pqs_, *vt_, *ps_, *psl_;
    cudaGetSymbolAddress((void**)&v_,  g_v);
    cudaGetSymbolAddress((void**)&lg_, g_logits);
    cudaGetSymbolAddress((void**)&ab_,   g_ab);
    cudaGetSymbolAddress((void**)&wqkv_, g_wqkv);
    cudaGetSymbolAddress((void**)&apos_, g_apos);
    cudaGetSymbolAddress((void**)&wpos_, g_wpos);
    cudaGetSymbolAddress((void**)&qs_,  g_qs);
    cudaGetSymbolAddress((void**)&ks_,  g_ks);
    cudaGetSymbolAddress((void**)&pks_, g_pks);
    cudaGetSymbolAddress((void**)&pqs_, g_pqs);
    cudaGetSymbolAddress((void**)&vt_,  g_vt);
    cudaGetSymbolAddress((void**)&ps_,  g_ps);
    cudaGetSymbolAddress((void**)&psl_, g_psl);

    cudaFuncSetAttribute(tgemm_kernel,
                         cudaFuncAttributeMaxDynamicSharedMemorySize,
                         TGEMM_SMEM);
    cudaFuncSetAttribute(tgemm_dual_kernel,
                         cudaFuncAttributeMaxDynamicSharedMemorySize,
                         TGEMM_SMEM);
    cudaFuncSetAttribute(logits_mma_kernel,
                         cudaFuncAttributeMaxDynamicSharedMemorySize,
                         LOGMMA_SMEM);
    cudaFuncSetAttribute(av_mma_kernel,
                         cudaFuncAttributeMaxDynamicSharedMemorySize,
                         AV_SMEM);

    const int kq = kD / 4;  // 192

    // 1) operand splits (fp32 -> bf16 hi/lo, K-concat, duplicated-hi layout)
    split_a_kernel<<<(3072 * kq + 255) / 256, 256>>>(x, ab_, 3072, 3072, kD);
    split_w_kernel<<<(2304 * kq + 255) / 256, 256>>>(Wq, Wk, Wv, wqkv_, 3, kD);
    split_a_kernel<<<(768 * kq + 255) / 256, 256>>>(rel + (size_t)128 * kD, apos_, kR, 768, kD);
    split_w_kernel<<<(1536 * kq + 255) / 256, 256>>>(Wpk, Wpq, Wpq, wpos_, 2, kD);

    // 2) QKV + POS projections, merged into one launch (504 blocks)
    tgemm_dual_kernel<<<504, 256, TGEMM_SMEM>>>(
        (const __nv_bfloat16*)ab_, (const __nv_bfloat16*)wqkv_,
        bq, bk, bv, v_, qs_, ks_,
        (const __nv_bfloat16*)apos_, (const __nv_bfloat16*)wpos_,
        bpk, bpq, pks_, pqs_);

    // 2b) V transpose + split for tensor AV
    vtrans_kernel<<<dim3(6, 96), 256>>>(v_, vt_);

    // 3) fused banded-MMA logits + segment bias + mask (two-pass, 2 CTA/SM)
    dim3 glog(kS / 64, kS / 64, kB * kH);
    logits_mma_kernel<<<glog, 256, LOGMMA_SMEM>>>(
        qs_, ks_, pks_, pqs_, mask, seg, sep,
        same_b, cross_b, sscale, sdecay, lg_);

    // 4) softmax -> hi/lo bf16 probabilities (1 warp per row)
    softmax_bf16_kernel<<<kB * kH * kS / 8, 256>>>(lg_, ps_, psl_);

    // 5) split Wo (independent of softmax/AV stream order)
    split_w_kernel<<<(768 * kq + 255) / 256, 256>>>(Wo, Wo, Wo, wpos_, 1, kE);

    // 6) tensor AV: P @ V -> A-pattern split rows directly into ab_ (2 CTA/SM)
    av_mma_kernel<<<dim3(6, 96), 256, AV_SMEM>>>(ps_, psl_, vt_, ab_);

    // 7) Output projection (A operand = av output split, already in ab_)
    tgemm_kernel<<<dim3(6, 24), 256, TGEMM_SMEM>>>(
        (const __nv_bfloat16*)ab_, (const __nv_bfloat16*)wpos_, 3072, bo, out);
}